// round 10
// baseline (speedup 1.0000x reference)
#include <cuda_runtime.h>
#include <cuda_bf16.h>
#include <math.h>

#define B_ 16
#define S_ 512
#define FRAME_ 438
#define D_ 800
#define H_ 8
#define DH_ 100
#define FFN_ 1024
#define HID_ 1024
#define POSE_ 274
#define WIN_ 100
#define M_ (B_*S_)
#define G4_ (4*HID_)
#define QT_ 8
#define KSPAN_ (2*WIN_+QT_)
#define KROW_ 101
#define GATEB_ 128
#define OUTB_ 18
#define NB_ (GATEB_+OUTB_)
#define HBW_ 516
#define HBTOT_ (16*HBW_)
#define XBW_ 148
#define OGRP_ 35

__device__ float g_x[M_*D_];
__device__ float g_q[M_*D_];
__device__ float g_k[M_*D_];
__device__ float g_v[M_*D_];
__device__ float g_o[M_*D_];
__device__ float g_r1[M_*D_];
__device__ float g_x2[M_*D_];
__device__ float g_h1[M_*FFN_];
__device__ float g_t2[M_*D_];
__device__ float g_enc[M_*D_];
__device__ float g_xwx[(size_t)M_*G4_];
__device__ float g_encp[M_*POSE_];
__device__ __align__(16) unsigned g_hb[4*HBTOT_];
__device__ uint2 g_whb[(size_t)GATEB_*4*64*32];
__device__ uint2 g_wxb[(size_t)GATEB_*4*18*32];
__device__ uint2 g_owb[(size_t)OGRP_*64*32];
__device__ unsigned g_hcnt[16*64];
__device__ unsigned g_ocnt[6*64];

enum { EPI_NONE=0, EPI_POS=1, EPI_ADD=2, EPI_BIAS_RELU=3, EPI_BIAS_ADD=4, EPI_BIAS=5 };

__device__ __forceinline__ unsigned packbf(float a, float b) {
    __nv_bfloat162 t = __float22bfloat162_rn(make_float2(a, b));
    return *(unsigned*)&t;
}
__device__ __forceinline__ float bfres(float x, float& hi) {
    __nv_bfloat16 h = __float2bfloat16_rn(x);
    hi = __bfloat162float(h);
    return x - hi;
}

__device__ __forceinline__ void mma_bf16(float* d, const unsigned* a, const unsigned* b) {
    asm volatile("mma.sync.aligned.m16n8k16.row.col.f32.bf16.bf16.f32 "
        "{%0,%1,%2,%3}, {%4,%5,%6,%7}, {%8,%9}, {%0,%1,%2,%3};"
        : "+f"(d[0]), "+f"(d[1]), "+f"(d[2]), "+f"(d[3])
        : "r"(a[0]), "r"(a[1]), "r"(a[2]), "r"(a[3]), "r"(b[0]), "r"(b[1]));
}

// ---------------- split-bf16 (3-term) tensor-core GEMM ----------------
// block tile 128(M) x 64(N), kstep 32, 8 warps (4m x 2n), each warp 32x32.
// A = Ah + Al, W = Wh + Wl;  C ~= Ah@Wh + Ah@Wl + Al@Wh  (fp32 accum)
template<int EPI>
__global__ __launch_bounds__(256)
void gemmb_k(const float* __restrict__ A, const float* __restrict__ W,
             float* __restrict__ C, int Mm, int Nn, int Kk,
             const float* __restrict__ bias, const float* __restrict__ addend,
             const float* __restrict__ pos_table, const int* __restrict__ pos_idx)
{
    __shared__ unsigned Ah[128*17], Al[128*17];
    __shared__ unsigned Wh[16*72],  Wl[16*72];
    int tid = threadIdx.x, lane = tid & 31, w = tid >> 5;
    int wm = w >> 1, wn = w & 1;
    int rowBase = blockIdx.y * 128, colBase = blockIdx.x * 64;
    int tg = lane & 3, qd = lane >> 2;

    float d[2][4][4];
#pragma unroll
    for (int mt = 0; mt < 2; mt++)
#pragma unroll
        for (int nt = 0; nt < 4; nt++)
#pragma unroll
            for (int i = 0; i < 4; i++) d[mt][nt][i] = 0.f;

    for (int k0 = 0; k0 < Kk; k0 += 32) {
#pragma unroll
        for (int ii = 0; ii < 8; ii++) {
            int i = ii*256 + tid;
            int row = i >> 4, kw = i & 15, gk = k0 + kw*2;
            float2 v;
            if (gk + 1 < Kk) v = *(const float2*)(A + (size_t)(rowBase+row)*Kk + gk);
            else v = make_float2((gk < Kk) ? A[(size_t)(rowBase+row)*Kk + gk] : 0.f, 0.f);
            float h0, h1;
            float l0 = bfres(v.x, h0), l1 = bfres(v.y, h1);
            Ah[row*17 + kw] = packbf(h0, h1);
            Al[row*17 + kw] = packbf(l0, l1);
        }
#pragma unroll
        for (int ii = 0; ii < 4; ii++) {
            int i = ii*256 + tid;
            int n = i & 63, kw = i >> 6;
            int gk = k0 + kw*2, gn = colBase + n;
            float w0 = (gk   < Kk && gn < Nn) ? W[(size_t)gk*Nn + gn]     : 0.f;
            float w1 = (gk+1 < Kk && gn < Nn) ? W[(size_t)(gk+1)*Nn + gn] : 0.f;
            float h0, h1;
            float l0 = bfres(w0, h0), l1 = bfres(w1, h1);
            Wh[kw*72 + n] = packbf(h0, h1);
            Wl[kw*72 + n] = packbf(l0, l1);
        }
        __syncthreads();
#pragma unroll
        for (int kt = 0; kt < 2; kt++) {
            unsigned ah[2][4], al[2][4], bh[4][2], bl[4][2];
#pragma unroll
            for (int mt = 0; mt < 2; mt++) {
                int base = (wm*32 + mt*16 + qd)*17 + kt*8 + tg;
                ah[mt][0] = Ah[base];     ah[mt][1] = Ah[base + 8*17];
                ah[mt][2] = Ah[base + 4]; ah[mt][3] = Ah[base + 8*17 + 4];
                al[mt][0] = Al[base];     al[mt][1] = Al[base + 8*17];
                al[mt][2] = Al[base + 4]; al[mt][3] = Al[base + 8*17 + 4];
            }
#pragma unroll
            for (int nt = 0; nt < 4; nt++) {
                int nn = wn*32 + nt*8 + qd;
                int kb = kt*8 + tg;
                bh[nt][0] = Wh[kb*72 + nn]; bh[nt][1] = Wh[(kb+4)*72 + nn];
                bl[nt][0] = Wl[kb*72 + nn]; bl[nt][1] = Wl[(kb+4)*72 + nn];
            }
#pragma unroll
            for (int mt = 0; mt < 2; mt++)
#pragma unroll
                for (int nt = 0; nt < 4; nt++) {
                    mma_bf16(d[mt][nt], ah[mt], bh[nt]);
                    mma_bf16(d[mt][nt], ah[mt], bl[nt]);
                    mma_bf16(d[mt][nt], al[mt], bh[nt]);
                }
        }
        __syncthreads();
    }

#pragma unroll
    for (int mt = 0; mt < 2; mt++) {
#pragma unroll
        for (int nt = 0; nt < 4; nt++) {
#pragma unroll
            for (int half = 0; half < 2; half++) {
                int row = rowBase + wm*32 + mt*16 + qd + half*8;
                int col = colBase + wn*32 + nt*8 + tg*2;
                if (col < Nn) {
                    float v0 = d[mt][nt][half*2+0];
                    float v1 = d[mt][nt][half*2+1];
                    if (EPI == EPI_POS) {
                        size_t pb = (size_t)pos_idx[row]*Nn + col;
                        v0 += bias[col]   + pos_table[pb];
                        v1 += bias[col+1] + pos_table[pb+1];
                    } else if (EPI == EPI_ADD) {
                        size_t ab = (size_t)row*Nn + col;
                        v0 += addend[ab]; v1 += addend[ab+1];
                    } else if (EPI == EPI_BIAS_RELU) {
                        v0 += bias[col]; v1 += bias[col+1];
                        v0 = v0 > 0.f ? v0 : 0.f; v1 = v1 > 0.f ? v1 : 0.f;
                    } else if (EPI == EPI_BIAS_ADD) {
                        size_t ab = (size_t)row*Nn + col;
                        v0 += bias[col] + addend[ab]; v1 += bias[col+1] + addend[ab+1];
                    } else if (EPI == EPI_BIAS) {
                        v0 += bias[col]; v1 += bias[col+1];
                    }
                    *(float2*)(C + (size_t)row*Nn + col) = make_float2(v0, v1);
                }
            }
        }
    }
}

__global__ __launch_bounds__(256)
void ln_k(const float* __restrict__ in, float* __restrict__ out,
          const float* __restrict__ g, const float* __restrict__ b)
{
    __shared__ float buf[D_];
    __shared__ float red[256];
    int row = blockIdx.x, tid = threadIdx.x;
    float s = 0.f;
    for (int i = tid; i < D_; i += 256) { float v = in[(size_t)row*D_ + i]; buf[i] = v; s += v; }
    red[tid] = s; __syncthreads();
    for (int st = 128; st > 0; st >>= 1) { if (tid < st) red[tid] += red[tid+st]; __syncthreads(); }
    float mean = red[0] / (float)D_;
    __syncthreads();
    float ss = 0.f;
    for (int i = tid; i < D_; i += 256) { float dd = buf[i]-mean; ss += dd*dd; }
    red[tid] = ss; __syncthreads();
    for (int st = 128; st > 0; st >>= 1) { if (tid < st) red[tid] += red[tid+st]; __syncthreads(); }
    float inv = rsqrtf(red[0]/(float)D_ + 1e-6f);
    for (int i = tid; i < D_; i += 256)
        out[(size_t)row*D_ + i] = (buf[i]-mean)*inv*g[i] + b[i];
}

__global__ __launch_bounds__(128)
void attn_k(const float* __restrict__ Q, const float* __restrict__ K,
            const float* __restrict__ V, float* __restrict__ O)
{
    extern __shared__ float ks[];
    __shared__ float qs[QT_*DH_];
    __shared__ float sc[QT_][KSPAN_];
    __shared__ float invs[QT_];
    int tid = threadIdx.x;
    int q0 = blockIdx.x * QT_, h = blockIdx.y, b = blockIdx.z;
    int kl = max(0, q0 - WIN_);
    int kh = min(S_-1, q0 + QT_-1 + WIN_);
    int nk = kh - kl + 1;
    size_t base = ((size_t)b*S_)*D_ + (size_t)h*DH_;

    for (int idx = tid; idx < QT_*DH_; idx += 128) {
        int qi = idx / DH_, dd = idx % DH_;
        qs[idx] = Q[base + (size_t)(q0+qi)*D_ + dd];
    }
    for (int idx = tid; idx < nk*DH_; idx += 128) {
        int kk = idx / DH_, dd = idx % DH_;
        ks[kk*KROW_ + dd] = K[base + (size_t)(kl+kk)*D_ + dd];
    }
    __syncthreads();

    for (int pid = tid; pid < QT_*nk; pid += 128) {
        int kk = pid % nk, qi = pid / nk;
        int qq = q0 + qi, kp = kl + kk;
        float v;
        if (kp >= qq - WIN_ && kp <= qq + WIN_) {
            float dd = 0.f;
            for (int i = 0; i < DH_; i++) dd += qs[qi*DH_ + i]*ks[kk*KROW_ + i];
            v = dd * 0.1f;
        } else v = -1e30f;
        sc[qi][kk] = v;
    }
    __syncthreads();
    {
        int qi = tid >> 4, l = tid & 15;
        float m = -1e30f;
        for (int kk = l; kk < nk; kk += 16) m = fmaxf(m, sc[qi][kk]);
#pragma unroll
        for (int s2 = 8; s2 > 0; s2 >>= 1) m = fmaxf(m, __shfl_xor_sync(0xffffffffu, m, s2, 16));
        float ssum = 0.f;
        for (int kk = l; kk < nk; kk += 16) { float e = expf(sc[qi][kk]-m); sc[qi][kk] = e; ssum += e; }
#pragma unroll
        for (int s2 = 8; s2 > 0; s2 >>= 1) ssum += __shfl_xor_sync(0xffffffffu, ssum, s2, 16);
        if (l == 0) invs[qi] = 1.f / ssum;
    }
    __syncthreads();
    if (tid < DH_) {
        float acc[QT_];
#pragma unroll
        for (int qi = 0; qi < QT_; qi++) acc[qi] = 0.f;
        for (int kk = 0; kk < nk; kk++) {
            float vv = V[base + (size_t)(kl+kk)*D_ + tid];
#pragma unroll
            for (int qi = 0; qi < QT_; qi++) acc[qi] += sc[qi][kk]*vv;
        }
#pragma unroll
        for (int qi = 0; qi < QT_; qi++)
            O[base + (size_t)(q0+qi)*D_ + tid] = acc[qi]*invs[qi];
    }
}

// ---------------- decoder pack kernels ----------------
__global__ void pack_whb_k(const float* __restrict__ Wh, uint2* __restrict__ out)
{
    size_t idx = (size_t)blockIdx.x*256 + threadIdx.x;
    if (idx >= (size_t)GATEB_*4*64*32) return;
    int lane = idx & 31;
    int kt = (idx >> 5) & 63;
    int q  = (idx >> 11) & 3;
    int g  = idx >> 13;
    int j  = q*1024 + g*8 + (lane >> 2);
    int k0 = kt*16 + (lane & 3)*2;
    float w0 = Wh[(size_t)k0*G4_ + j],     w1 = Wh[(size_t)(k0+1)*G4_ + j];
    float w2 = Wh[(size_t)(k0+8)*G4_ + j], w3 = Wh[(size_t)(k0+9)*G4_ + j];
    out[idx] = make_uint2(packbf(w0,w1), packbf(w2,w3));
}

__global__ void pack_wxb_k(const float* __restrict__ Wx, uint2* __restrict__ out)
{
    size_t idx = (size_t)blockIdx.x*256 + threadIdx.x;
    if (idx >= (size_t)GATEB_*4*18*32) return;
    int lane = idx & 31;
    size_t r = idx >> 5;
    int kt = r % 18;
    int q  = (r / 18) & 3;
    int g  = r / 72;
    int j  = q*1024 + g*8 + (lane >> 2);
    int k0 = kt*16 + (lane & 3)*2;
    float w0 = (k0   < POSE_) ? Wx[(size_t)k0*G4_ + j]     : 0.f;
    float w1 = (k0+1 < POSE_) ? Wx[(size_t)(k0+1)*G4_ + j] : 0.f;
    float w2 = (k0+8 < POSE_) ? Wx[(size_t)(k0+8)*G4_ + j] : 0.f;
    float w3 = (k0+9 < POSE_) ? Wx[(size_t)(k0+9)*G4_ + j] : 0.f;
    out[idx] = make_uint2(packbf(w0,w1), packbf(w2,w3));
}

__global__ void pack_owb_k(const float* __restrict__ Wo, uint2* __restrict__ out)
{
    int idx = blockIdx.x*256 + threadIdx.x;
    if (idx >= OGRP_*64*32) return;
    int lane = idx & 31;
    int kt = (idx >> 5) & 63;
    int grp = idx >> 11;
    int n  = grp*8 + (lane >> 2);
    int k0 = kt*16 + (lane & 3)*2;
    float w0=0.f, w1=0.f, w2=0.f, w3=0.f;
    if (n < POSE_) {
        w0 = Wo[(size_t)k0*POSE_ + n];     w1 = Wo[(size_t)(k0+1)*POSE_ + n];
        w2 = Wo[(size_t)(k0+8)*POSE_ + n]; w3 = Wo[(size_t)(k0+9)*POSE_ + n];
    }
    out[idx] = make_uint2(packbf(w0,w1), packbf(w2,w3));
}

__global__ void init_dec_k(const float* __restrict__ vh, unsigned* __restrict__ hb)
{
    int i = blockIdx.x*256 + threadIdx.x;
    if (i < 16*64) g_hcnt[i] = 0;
    if (i < 6*64)  g_ocnt[i] = 0;
    if (i < HBTOT_) {
        int b = i / HBW_, kw = i % HBW_;
        int k0 = kw*2;
        float v0 = (k0   < HID_) ? vh[b*HID_ + k0]   : 0.f;
        float v1 = (k0+1 < HID_) ? vh[b*HID_ + k0+1] : 0.f;
        hb[3*HBTOT_ + i] = packbf(v0, v1);
    }
}

__device__ __forceinline__ float sigf(float x){ return 1.f/(1.f+expf(-x)); }

__device__ __forceinline__ unsigned ld_acq(const unsigned* p) {
    unsigned v;
    asm volatile("ld.acquire.gpu.global.u32 %0, [%1];" : "=r"(v) : "l"(p) : "memory");
    return v;
}
__device__ __forceinline__ void red_rel(unsigned* p) {
    asm volatile("red.release.gpu.global.add.u32 [%0], 1;" :: "l"(p) : "memory");
}

// grid = 146 x 128 threads. Blocks 0..127: gates (8 units each). 128..145: out-proj.
__global__ __launch_bounds__(128)
void dec_k(const uint2* __restrict__ WHB, const uint2* __restrict__ WXB,
           const uint2* __restrict__ OWB, const float* __restrict__ lb,
           const float* __restrict__ xwx, const float* __restrict__ encp,
           const float* __restrict__ vec_c, const float* __restrict__ dec0,
           unsigned* __restrict__ hb, float* __restrict__ outbuf,
           const int* __restrict__ ep)
{
    extern __shared__ unsigned smu[];
    unsigned* hbs = smu;
    unsigned* xbs = smu + HBTOT_;
    float*    red = (float*)(smu + HBTOT_ + 16*XBW_);
    float*    redo = (float*)(smu + HBTOT_);

    int tid = threadIdx.x, bx = blockIdx.x;
    int lane = tid & 31, w = tid >> 5;
    int b = lane >> 2, tg = lane & 3;
    bool isGate = bx < GATEB_;
    int p = (int)((double)(*ep) * 0.01);
    int per = p + 10;

    int u0 = bx*8 + tg*2;
    float c0=0.f, c1=0.f, c2=0.f, c3=0.f;
    if (isGate && w == 0) {
        c0 = vec_c[b*HID_ + u0];       c1 = vec_c[b*HID_ + u0 + 1];
        c2 = vec_c[(b+8)*HID_ + u0];   c3 = vec_c[(b+8)*HID_ + u0 + 1];
    }
    int ob = bx - GATEB_;
    int grp = ob*2 + (w >> 1);
    int kh = w & 1;
    bool ovalid = (grp < OGRP_);

#define HBS_COPY(hrp) { \
        const uint4* srcv = (const uint4*)(hrp); uint4* dstv = (uint4*)hbs; \
        for (int i = tid; i < HBTOT_/4; i += 128) dstv[i] = __ldcg(srcv + i); }

#define A_LOAD(buf, stride, ktv) { \
        int wA = b*(stride) + (ktv)*8 + tg; \
        a[0] = (buf)[wA]; a[1] = (buf)[wA + 8*(stride)]; \
        a[2] = (buf)[wA + 4]; a[3] = (buf)[wA + 8*(stride) + 4]; }

    if (isGate) {
        for (int t = 0; t < S_; t++) {
            bool sampled = (t % per) < p;
            const unsigned* hr = hb + ((t+3)&3)*(size_t)HBTOT_;
            unsigned*       hw = hb + (t&3)*(size_t)HBTOT_;

            unsigned needO3 = 0;
            if (sampled) needO3 = 3u*(unsigned)t;
            else if (t >= 4) needO3 = 3u*(unsigned)(t-3);
            if (tid < 16) {
                if (t > 0) { unsigned need = 8u*(unsigned)t;
                    while (ld_acq(&g_hcnt[tid*64]) < need) ; }
            } else if (tid >= 32 && tid < 38) {
                if (needO3) while (ld_acq(&g_ocnt[(tid-32)*64]) < needO3) ;
            }
            __syncthreads();

            float2 xw[8];
            if (w == 0 && !sampled) {
#pragma unroll
                for (int q = 0; q < 4; q++)
#pragma unroll
                    for (int rr = 0; rr < 2; rr++)
                        xw[q*2+rr] = __ldcg((const float2*)(xwx +
                            ((size_t)(b + rr*8)*S_ + t)*G4_ + q*1024 + u0));
            }
            HBS_COPY(hr);
            if (sampled) {
                const float* xsrc0 = (t == 0) ? dec0 : (outbuf + (size_t)(t-1)*POSE_);
                size_t bstride = (t == 0) ? (size_t)POSE_ : (size_t)S_*POSE_;
                for (int i = tid; i < 16*(XBW_-4); i += 128) {
                    int b2 = i / (XBW_-4), kw = i % (XBW_-4);
                    int k0 = kw*2;
                    const float* sp = xsrc0 + (size_t)b2*bstride;
                    float v0 = (k0   < POSE_) ? __ldcg(sp + k0)   : 0.f;
                    float v1 = (k0+1 < POSE_) ? __ldcg(sp + k0+1) : 0.f;
                    xbs[b2*XBW_ + kw] = packbf(v0, v1);
                }
            }
            __syncthreads();

            float d[4][4];
#pragma unroll
            for (int q = 0; q < 4; q++)
#pragma unroll
                for (int i = 0; i < 4; i++) d[q][i] = 0.f;
            unsigned a[4];
#pragma unroll 4
            for (int kt16 = 0; kt16 < 16; kt16++) {
                int kt = w*16 + kt16;
                A_LOAD(hbs, HBW_, kt);
#pragma unroll
                for (int q = 0; q < 4; q++) {
                    uint2 bb = WHB[(((size_t)bx*4 + q)*64 + kt)*32 + lane];
                    mma_bf16(d[q], a, &bb.x);
                }
            }
            if (sampled) {
                int e2 = min(18, w*5 + 5);
                for (int kt2 = w*5; kt2 < e2; kt2++) {
                    A_LOAD(xbs, XBW_, kt2);
#pragma unroll
                    for (int q = 0; q < 4; q++) {
                        uint2 bb = WXB[(((size_t)bx*4 + q)*18 + kt2)*32 + lane];
                        mma_bf16(d[q], a, &bb.x);
                    }
                }
            }
            {
                float* myr = red + (w*32 + lane)*16;
#pragma unroll
                for (int q = 0; q < 4; q++)
#pragma unroll
                    for (int i = 0; i < 4; i++) myr[q*4+i] = d[q][i];
            }
            __syncthreads();

            if (w == 0) {
                float s[16];
#pragma unroll
                for (int i = 0; i < 16; i++) s[i] = 0.f;
#pragma unroll
                for (int w2 = 0; w2 < 4; w2++) {
                    const float4* r4 = (const float4*)(red + (w2*32 + lane)*16);
#pragma unroll
                    for (int q = 0; q < 4; q++) {
                        float4 v = r4[q];
                        s[q*4+0] += v.x; s[q*4+1] += v.y; s[q*4+2] += v.z; s[q*4+3] += v.w;
                    }
                }
                float gate[4][4];
#pragma unroll
                for (int q = 0; q < 4; q++) {
                    float2 lbv = *(const float2*)(lb + q*1024 + u0);
                    gate[q][0] = s[q*4+0] + lbv.x;
                    gate[q][1] = s[q*4+1] + lbv.y;
                    gate[q][2] = s[q*4+2] + lbv.x;
                    gate[q][3] = s[q*4+3] + lbv.y;
                    if (!sampled) {
                        gate[q][0] += xw[q*2].x;   gate[q][1] += xw[q*2].y;
                        gate[q][2] += xw[q*2+1].x; gate[q][3] += xw[q*2+1].y;
                    }
                }
                float cc[4] = {c0, c1, c2, c3};
                float hh[4];
#pragma unroll
                for (int e = 0; e < 4; e++) {
                    float cv = sigf(gate[1][e])*cc[e] + sigf(gate[0][e])*tanhf(gate[2][e]);
                    hh[e] = sigf(gate[3][e])*tanhf(cv);
                    cc[e] = cv;
                }
                c0 = cc[0]; c1 = cc[1]; c2 = cc[2]; c3 = cc[3];
                hw[b*HBW_ + bx*4 + tg]     = packbf(hh[0], hh[1]);
                hw[(b+8)*HBW_ + bx*4 + tg] = packbf(hh[2], hh[3]);
            }
            __syncthreads();
            if (tid == 0) red_rel(&g_hcnt[(bx & 15)*64]);
        }
    } else {
        for (int t = 0; t < S_; t++) {
            if (tid < 16) {
                unsigned need = 8u*(unsigned)(t+1);
                while (ld_acq(&g_hcnt[tid*64]) < need) ;
            }
            __syncthreads();
            const unsigned* hrp = hb + (t&3)*(size_t)HBTOT_;
            HBS_COPY(hrp);
            __syncthreads();
            float d[4] = {0.f,0.f,0.f,0.f};
            unsigned a[4];
            if (ovalid) {
#pragma unroll 4
                for (int kt16 = 0; kt16 < 32; kt16++) {
                    int kt = kh*32 + kt16;
                    A_LOAD(hbs, HBW_, kt);
                    uint2 bb = OWB[((size_t)grp*64 + kt)*32 + lane];
                    mma_bf16(d, a, &bb.x);
                }
            }
            float* myr = redo + (w*32 + lane)*4;
            myr[0]=d[0]; myr[1]=d[1]; myr[2]=d[2]; myr[3]=d[3];
            __syncthreads();
            if ((w & 1) == 0 && ovalid) {
                float s0 = redo[(w*32+lane)*4+0] + redo[((w+1)*32+lane)*4+0];
                float s1 = redo[(w*32+lane)*4+1] + redo[((w+1)*32+lane)*4+1];
                float s2 = redo[(w*32+lane)*4+2] + redo[((w+1)*32+lane)*4+2];
                float s3 = redo[(w*32+lane)*4+3] + redo[((w+1)*32+lane)*4+3];
                int n0 = grp*8 + tg*2;
                if (n0 + 1 < POSE_) {
                    size_t o0 = ((size_t)b*S_ + t)*POSE_ + n0;
                    size_t o1 = ((size_t)(b+8)*S_ + t)*POSE_ + n0;
                    float2 e0 = *(const float2*)(encp + o0);
                    float2 e1 = *(const float2*)(encp + o1);
                    *(float2*)(outbuf + o0) = make_float2(s0 + e0.x, s1 + e0.y);
                    *(float2*)(outbuf + o1) = make_float2(s2 + e1.x, s3 + e1.y);
                }
            }
            __syncthreads();
            if (tid == 0) red_rel(&g_ocnt[(ob % 6)*64]);
        }
    }
#undef A_LOAD
#undef HBS_COPY
}

extern "C" void kernel_launch(void* const* d_in, const int* in_sizes, int n_in,
                              void* d_out, int out_size)
{
    (void)in_sizes; (void)n_in; (void)out_size;
    const float* src_seq = (const float*)d_in[0];
    const int*   src_pos = (const int*)  d_in[1];
    const float* tgt_seq = (const float*)d_in[2];
    const float* vec_h   = (const float*)d_in[3];
    const float* vec_c   = (const float*)d_in[4];
    const float* dec0    = (const float*)d_in[5];
    const float* emb_W   = (const float*)d_in[6];
    const float* emb_b   = (const float*)d_in[7];
    const float* pos_t   = (const float*)d_in[8];
    const float* Wq      = (const float*)d_in[9];
    const float* Wk      = (const float*)d_in[10];
    const float* Wv      = (const float*)d_in[11];
    const float* Wo      = (const float*)d_in[12];
    const float* ln1g    = (const float*)d_in[13];
    const float* ln1b    = (const float*)d_in[14];
    const float* fW1     = (const float*)d_in[15];
    const float* fb1     = (const float*)d_in[16];
    const float* fW2     = (const float*)d_in[17];
    const float* fb2     = (const float*)d_in[18];
    const float* ln2g    = (const float*)d_in[19];
    const float* ln2b    = (const float*)d_in[20];
    const float* lWx     = (const float*)d_in[21];
    const float* lWh     = (const float*)d_in[22];
    const float* lb      = (const float*)d_in[23];
    const float* outW    = (const float*)d_in[24];
    const float* outb    = (const float*)d_in[25];
    const int*   ep      = (const int*)  d_in[26];
    float* out = (float*)d_out;

    void *px,*pq,*pk,*pv,*po,*pr1,*px2,*ph1,*pt2,*penc,*pxwx,*pencp,*phb,*pwhb,*pwxb,*powb;
    cudaGetSymbolAddress(&px,  g_x);   cudaGetSymbolAddress(&pq,  g_q);
    cudaGetSymbolAddress(&pk,  g_k);   cudaGetSymbolAddress(&pv,  g_v);
    cudaGetSymbolAddress(&po,  g_o);   cudaGetSymbolAddress(&pr1, g_r1);
    cudaGetSymbolAddress(&px2, g_x2);  cudaGetSymbolAddress(&ph1, g_h1);
    cudaGetSymbolAddress(&pt2, g_t2);  cudaGetSymbolAddress(&penc,g_enc);
    cudaGetSymbolAddress(&pxwx,g_xwx); cudaGetSymbolAddress(&pencp,g_encp);
    cudaGetSymbolAddress(&phb, g_hb);  cudaGetSymbolAddress(&pwhb,g_whb);
    cudaGetSymbolAddress(&pwxb,g_wxb); cudaGetSymbolAddress(&powb,g_owb);
    float *X=(float*)px, *Qb=(float*)pq, *Kb=(float*)pk, *Vb=(float*)pv, *Ob=(float*)po;
    float *R1=(float*)pr1, *X2=(float*)px2, *H1=(float*)ph1, *T2=(float*)pt2, *ENC=(float*)penc;
    float *XWX=(float*)pxwx, *ENCP=(float*)pencp;
    unsigned *HB=(unsigned*)phb;
    uint2 *WHB=(uint2*)pwhb, *WXB=(uint2*)pwxb, *OWB=(uint2*)powb;

    cudaFuncSetAttribute(attn_k, cudaFuncAttributeMaxDynamicSharedMemorySize, KSPAN_*KROW_*4);
    cudaFuncSetAttribute(dec_k,  cudaFuncAttributeMaxDynamicSharedMemorySize, 50688);

    dim3 gD((D_+63)/64, M_/128), gF((FFN_+63)/64, M_/128);
    dim3 gG4((G4_+63)/64, M_/128), gP((POSE_+63)/64, M_/128);

    // encoder (split-bf16 tensor-core GEMMs, fp32-class accuracy)
    gemmb_k<EPI_POS><<<gD,256>>>(src_seq, emb_W, X, M_, D_, FRAME_, emb_b, nullptr, pos_t, src_pos);
    gemmb_k<EPI_NONE><<<gD,256>>>(X, Wq, Qb, M_, D_, D_, nullptr, nullptr, nullptr, nullptr);
    gemmb_k<EPI_NONE><<<gD,256>>>(X, Wk, Kb, M_, D_, D_, nullptr, nullptr, nullptr, nullptr);
    gemmb_k<EPI_NONE><<<gD,256>>>(X, Wv, Vb, M_, D_, D_, nullptr, nullptr, nullptr, nullptr);
    attn_k<<<dim3(S_/QT_, H_, B_),128,KSPAN_*KROW_*4>>>(Qb, Kb, Vb, Ob);
    gemmb_k<EPI_ADD><<<gD,256>>>(Ob, Wo, R1, M_, D_, D_, nullptr, X, nullptr, nullptr);
    ln_k<<<M_,256>>>(R1, X2, ln1g, ln1b);
    gemmb_k<EPI_BIAS_RELU><<<gF,256>>>(X2, fW1, H1, M_, FFN_, D_, fb1, nullptr, nullptr, nullptr);
    gemmb_k<EPI_BIAS_ADD><<<gD,256>>>(H1, fW2, T2, M_, D_, FFN_, fb2, X2, nullptr, nullptr);
    ln_k<<<M_,256>>>(T2, ENC, ln2g, ln2b);

    // decoder precompute
    gemmb_k<EPI_NONE><<<gG4,256>>>(tgt_seq, lWx, XWX, M_, G4_, POSE_, nullptr, nullptr, nullptr, nullptr);
    gemmb_k<EPI_BIAS><<<gP,256>>>(ENC, outW + (size_t)HID_*POSE_, ENCP, M_, POSE_, D_, outb, nullptr, nullptr, nullptr);
    pack_whb_k<<<(GATEB_*4*64*32+255)/256,256>>>(lWh, WHB);
    pack_wxb_k<<<(GATEB_*4*18*32+255)/256,256>>>(lWx, WXB);
    pack_owb_k<<<(OGRP_*64*32+255)/256,256>>>(outW, OWB);
    init_dec_k<<<(HBTOT_+255)/256,256>>>(vec_h, HB);

    dec_k<<<NB_,128,50688>>>(WHB, WXB, OWB, lb, XWX, ENCP, vec_c, dec0, HB, out, ep);
}

// round 11
// speedup vs baseline: 1.3177x; 1.3177x over previous
#include <cuda_runtime.h>
#include <cuda_bf16.h>
#include <math.h>

#define B_ 16
#define S_ 512
#define FRAME_ 438
#define D_ 800
#define H_ 8
#define DH_ 100
#define FFN_ 1024
#define HID_ 1024
#define POSE_ 274
#define WIN_ 100
#define M_ (B_*S_)
#define G4_ (4*HID_)
#define QT_ 8
#define KSPAN_ (2*WIN_+QT_)
#define KROW_ 101
#define GATEB_ 128
#define OUTB_ 18
#define NB_ (GATEB_+OUTB_)
#define HBW_ 516
#define HBTOT_ (16*HBW_)
#define XBW_ 148
#define OGRP_ 35

__device__ float g_x[M_*D_];
__device__ float g_q[M_*D_];
__device__ float g_k[M_*D_];
__device__ float g_v[M_*D_];
__device__ float g_o[M_*D_];
__device__ float g_r1[M_*D_];
__device__ float g_x2[M_*D_];
__device__ float g_h1[M_*FFN_];
__device__ float g_t2[M_*D_];
__device__ float g_enc[M_*D_];
__device__ float g_xwx[(size_t)M_*G4_];
__device__ float g_encp[M_*POSE_];
__device__ __align__(16) unsigned g_hb[4*HBTOT_];
__device__ uint2 g_whb[(size_t)GATEB_*4*64*32];
__device__ uint2 g_wxb[(size_t)GATEB_*4*18*32];
__device__ uint2 g_owb[(size_t)OGRP_*64*32];
__device__ uint2 g_ap[(size_t)M_*512];     // packed activations (hi,lo) pairs, max KP=512
__device__ uint2 g_wp[600000];             // packed weights, max KP*N = 561152
__device__ unsigned g_cnt;
__device__ unsigned g_ocnt;

enum { EPI_NONE=0, EPI_POS=1, EPI_ADD=2, EPI_BIAS_RELU=3, EPI_BIAS_ADD=4, EPI_BIAS=5 };

__device__ __forceinline__ unsigned packbf(float a, float b) {
    __nv_bfloat162 t = __float22bfloat162_rn(make_float2(a, b));
    return *(unsigned*)&t;
}
__device__ __forceinline__ float bfres(float x, float& hi) {
    __nv_bfloat16 h = __float2bfloat16_rn(x);
    hi = __bfloat162float(h);
    return x - hi;
}
__device__ __forceinline__ void mma_bf16(float* d, const unsigned* a, const unsigned* b) {
    asm volatile("mma.sync.aligned.m16n8k16.row.col.f32.bf16.bf16.f32 "
        "{%0,%1,%2,%3}, {%4,%5,%6,%7}, {%8,%9}, {%0,%1,%2,%3};"
        : "+f"(d[0]), "+f"(d[1]), "+f"(d[2]), "+f"(d[3])
        : "r"(a[0]), "r"(a[1]), "r"(a[2]), "r"(a[3]), "r"(b[0]), "r"(b[1]));
}

// ---------------- split-bf16 pre-pack kernels ----------------
// activations: A [rows][K] fp32 (K even) -> pairs (hi(2k,2k+1), lo(2k,2k+1))
__global__ void packa_k(const float* __restrict__ A, uint2* __restrict__ out, int npairs)
{
    int i = blockIdx.x*256 + threadIdx.x;
    if (i < npairs) {
        float2 v = ((const float2*)A)[i];
        float h0, h1;
        float l0 = bfres(v.x, h0), l1 = bfres(v.y, h1);
        out[i] = make_uint2(packbf(h0, h1), packbf(l0, l1));
    }
}
// weights: W [K][N] fp32 -> out[kp*N + n] = pair over K dim
__global__ void packw_k(const float* __restrict__ W, uint2* __restrict__ out, int KP, int Nn)
{
    int i = blockIdx.x*256 + threadIdx.x;
    if (i < KP*Nn) {
        int kp = i / Nn, n = i % Nn;
        float w0 = W[(size_t)(2*kp)*Nn + n];
        float w1 = W[(size_t)(2*kp+1)*Nn + n];
        float h0, h1;
        float l0 = bfres(w0, h0), l1 = bfres(w1, h1);
        out[i] = make_uint2(packbf(h0, h1), packbf(l0, l1));
    }
}

// ---------------- packed split-bf16 tensor-core GEMM ----------------
// tile 128(M) x 64(N), kstep 32 (16 pairs), 8 warps (4m x 2n).
// 3 terms: Ah@Wh + Ah@Wl + Al@Wh, fp32 accum. No conversions in-loop.
template<int EPI>
__global__ __launch_bounds__(256)
void gemmp_k(const uint2* __restrict__ Ap, int KP,
             const uint2* __restrict__ Wp,
             float* __restrict__ C, int Nn,
             const float* __restrict__ bias, const float* __restrict__ addend,
             const float* __restrict__ pos_table, const int* __restrict__ pos_idx)
{
    __shared__ uint2 Asm[128*17];
    __shared__ uint2 Wsm[16*65];
    int tid = threadIdx.x, lane = tid & 31, w = tid >> 5;
    int wm = w >> 1, wn = w & 1;
    int rowBase = blockIdx.y * 128, colBase = blockIdx.x * 64;
    int tg = lane & 3, qd = lane >> 2;

    float d[2][4][4];
#pragma unroll
    for (int mt = 0; mt < 2; mt++)
#pragma unroll
        for (int nt = 0; nt < 4; nt++)
#pragma unroll
            for (int i = 0; i < 4; i++) d[mt][nt][i] = 0.f;

    for (int k0p = 0; k0p < KP; k0p += 16) {
#pragma unroll
        for (int ii = 0; ii < 8; ii++) {
            int i = ii*256 + tid;
            int row = i >> 4, kw = i & 15, gkp = k0p + kw;
            Asm[row*17 + kw] = (gkp < KP) ? Ap[(size_t)(rowBase+row)*KP + gkp]
                                          : make_uint2(0u, 0u);
        }
#pragma unroll
        for (int ii = 0; ii < 4; ii++) {
            int i = ii*256 + tid;
            int n = i & 63, kw = i >> 6;
            int gkp = k0p + kw, gn = colBase + n;
            Wsm[kw*65 + n] = (gkp < KP && gn < Nn) ? Wp[(size_t)gkp*Nn + gn]
                                                   : make_uint2(0u, 0u);
        }
        __syncthreads();
#pragma unroll
        for (int kt = 0; kt < 2; kt++) {
            unsigned ah[2][4], al[2][4], bh[4][2], bl[4][2];
#pragma unroll
            for (int mt = 0; mt < 2; mt++) {
                int base = (wm*32 + mt*16 + qd)*17 + kt*8 + tg;
                uint2 q0 = Asm[base],     q1 = Asm[base + 8*17];
                uint2 q2 = Asm[base + 4], q3 = Asm[base + 8*17 + 4];
                ah[mt][0]=q0.x; ah[mt][1]=q1.x; ah[mt][2]=q2.x; ah[mt][3]=q3.x;
                al[mt][0]=q0.y; al[mt][1]=q1.y; al[mt][2]=q2.y; al[mt][3]=q3.y;
            }
#pragma unroll
            for (int nt = 0; nt < 4; nt++) {
                int nn = wn*32 + nt*8 + qd;
                int kb = kt*8 + tg;
                uint2 q0 = Wsm[kb*65 + nn], q1 = Wsm[(kb+4)*65 + nn];
                bh[nt][0]=q0.x; bh[nt][1]=q1.x;
                bl[nt][0]=q0.y; bl[nt][1]=q1.y;
            }
#pragma unroll
            for (int mt = 0; mt < 2; mt++)
#pragma unroll
                for (int nt = 0; nt < 4; nt++) {
                    mma_bf16(d[mt][nt], ah[mt], bh[nt]);
                    mma_bf16(d[mt][nt], ah[mt], bl[nt]);
                    mma_bf16(d[mt][nt], al[mt], bh[nt]);
                }
        }
        __syncthreads();
    }

#pragma unroll
    for (int mt = 0; mt < 2; mt++) {
#pragma unroll
        for (int nt = 0; nt < 4; nt++) {
#pragma unroll
            for (int half = 0; half < 2; half++) {
                int row = rowBase + wm*32 + mt*16 + qd + half*8;
                int col = colBase + wn*32 + nt*8 + tg*2;
                if (col < Nn) {
                    float v0 = d[mt][nt][half*2+0];
                    float v1 = d[mt][nt][half*2+1];
                    if (EPI == EPI_POS) {
                        size_t pb = (size_t)pos_idx[row]*Nn + col;
                        v0 += bias[col]   + pos_table[pb];
                        v1 += bias[col+1] + pos_table[pb+1];
                    } else if (EPI == EPI_ADD) {
                        size_t ab = (size_t)row*Nn + col;
                        v0 += addend[ab]; v1 += addend[ab+1];
                    } else if (EPI == EPI_BIAS_RELU) {
                        v0 += bias[col]; v1 += bias[col+1];
                        v0 = v0 > 0.f ? v0 : 0.f; v1 = v1 > 0.f ? v1 : 0.f;
                    } else if (EPI == EPI_BIAS_ADD) {
                        size_t ab = (size_t)row*Nn + col;
                        v0 += bias[col] + addend[ab]; v1 += bias[col+1] + addend[ab+1];
                    } else if (EPI == EPI_BIAS) {
                        v0 += bias[col]; v1 += bias[col+1];
                    }
                    *(float2*)(C + (size_t)row*Nn + col) = make_float2(v0, v1);
                }
            }
        }
    }
}

__global__ __launch_bounds__(256)
void ln_k(const float* __restrict__ in, float* __restrict__ out,
          const float* __restrict__ g, const float* __restrict__ b)
{
    __shared__ float buf[D_];
    __shared__ float red[256];
    int row = blockIdx.x, tid = threadIdx.x;
    float s = 0.f;
    for (int i = tid; i < D_; i += 256) { float v = in[(size_t)row*D_ + i]; buf[i] = v; s += v; }
    red[tid] = s; __syncthreads();
    for (int st = 128; st > 0; st >>= 1) { if (tid < st) red[tid] += red[tid+st]; __syncthreads(); }
    float mean = red[0] / (float)D_;
    __syncthreads();
    float ss = 0.f;
    for (int i = tid; i < D_; i += 256) { float dd = buf[i]-mean; ss += dd*dd; }
    red[tid] = ss; __syncthreads();
    for (int st = 128; st > 0; st >>= 1) { if (tid < st) red[tid] += red[tid+st]; __syncthreads(); }
    float inv = rsqrtf(red[0]/(float)D_ + 1e-6f);
    for (int i = tid; i < D_; i += 256)
        out[(size_t)row*D_ + i] = (buf[i]-mean)*inv*g[i] + b[i];
}

__global__ __launch_bounds__(128)
void attn_k(const float* __restrict__ Q, const float* __restrict__ K,
            const float* __restrict__ V, float* __restrict__ O)
{
    extern __shared__ float ks[];
    __shared__ float qs[QT_*DH_];
    __shared__ float sc[QT_][KSPAN_];
    __shared__ float invs[QT_];
    int tid = threadIdx.x;
    int q0 = blockIdx.x * QT_, h = blockIdx.y, b = blockIdx.z;
    int kl = max(0, q0 - WIN_);
    int kh = min(S_-1, q0 + QT_-1 + WIN_);
    int nk = kh - kl + 1;
    size_t base = ((size_t)b*S_)*D_ + (size_t)h*DH_;

    for (int idx = tid; idx < QT_*DH_; idx += 128) {
        int qi = idx / DH_, dd = idx % DH_;
        qs[idx] = Q[base + (size_t)(q0+qi)*D_ + dd];
    }
    for (int idx = tid; idx < nk*DH_; idx += 128) {
        int kk = idx / DH_, dd = idx % DH_;
        ks[kk*KROW_ + dd] = K[base + (size_t)(kl+kk)*D_ + dd];
    }
    __syncthreads();

    for (int pid = tid; pid < QT_*nk; pid += 128) {
        int kk = pid % nk, qi = pid / nk;
        int qq = q0 + qi, kp = kl + kk;
        float v;
        if (kp >= qq - WIN_ && kp <= qq + WIN_) {
            float dd = 0.f;
            for (int i = 0; i < DH_; i++) dd += qs[qi*DH_ + i]*ks[kk*KROW_ + i];
            v = dd * 0.1f;
        } else v = -1e30f;
        sc[qi][kk] = v;
    }
    __syncthreads();
    {
        int qi = tid >> 4, l = tid & 15;
        float m = -1e30f;
        for (int kk = l; kk < nk; kk += 16) m = fmaxf(m, sc[qi][kk]);
#pragma unroll
        for (int s2 = 8; s2 > 0; s2 >>= 1) m = fmaxf(m, __shfl_xor_sync(0xffffffffu, m, s2, 16));
        float ssum = 0.f;
        for (int kk = l; kk < nk; kk += 16) { float e = expf(sc[qi][kk]-m); sc[qi][kk] = e; ssum += e; }
#pragma unroll
        for (int s2 = 8; s2 > 0; s2 >>= 1) ssum += __shfl_xor_sync(0xffffffffu, ssum, s2, 16);
        if (l == 0) invs[qi] = 1.f / ssum;
    }
    __syncthreads();
    if (tid < DH_) {
        float acc[QT_];
#pragma unroll
        for (int qi = 0; qi < QT_; qi++) acc[qi] = 0.f;
        for (int kk = 0; kk < nk; kk++) {
            float vv = V[base + (size_t)(kl+kk)*D_ + tid];
#pragma unroll
            for (int qi = 0; qi < QT_; qi++) acc[qi] += sc[qi][kk]*vv;
        }
#pragma unroll
        for (int qi = 0; qi < QT_; qi++)
            O[base + (size_t)(q0+qi)*D_ + tid] = acc[qi]*invs[qi];
    }
}

// ---------------- decoder pack kernels ----------------
__global__ void pack_whb_k(const float* __restrict__ Wh, uint2* __restrict__ out)
{
    size_t idx = (size_t)blockIdx.x*256 + threadIdx.x;
    if (idx >= (size_t)GATEB_*4*64*32) return;
    int lane = idx & 31;
    int kt = (idx >> 5) & 63;
    int q  = (idx >> 11) & 3;
    int g  = idx >> 13;
    int j  = q*1024 + g*8 + (lane >> 2);
    int k0 = kt*16 + (lane & 3)*2;
    float w0 = Wh[(size_t)k0*G4_ + j],     w1 = Wh[(size_t)(k0+1)*G4_ + j];
    float w2 = Wh[(size_t)(k0+8)*G4_ + j], w3 = Wh[(size_t)(k0+9)*G4_ + j];
    out[idx] = make_uint2(packbf(w0,w1), packbf(w2,w3));
}

__global__ void pack_wxb_k(const float* __restrict__ Wx, uint2* __restrict__ out)
{
    size_t idx = (size_t)blockIdx.x*256 + threadIdx.x;
    if (idx >= (size_t)GATEB_*4*18*32) return;
    int lane = idx & 31;
    size_t r = idx >> 5;
    int kt = r % 18;
    int q  = (r / 18) & 3;
    int g  = r / 72;
    int j  = q*1024 + g*8 + (lane >> 2);
    int k0 = kt*16 + (lane & 3)*2;
    float w0 = (k0   < POSE_) ? Wx[(size_t)k0*G4_ + j]     : 0.f;
    float w1 = (k0+1 < POSE_) ? Wx[(size_t)(k0+1)*G4_ + j] : 0.f;
    float w2 = (k0+8 < POSE_) ? Wx[(size_t)(k0+8)*G4_ + j] : 0.f;
    float w3 = (k0+9 < POSE_) ? Wx[(size_t)(k0+9)*G4_ + j] : 0.f;
    out[idx] = make_uint2(packbf(w0,w1), packbf(w2,w3));
}

__global__ void pack_owb_k(const float* __restrict__ Wo, uint2* __restrict__ out)
{
    int idx = blockIdx.x*256 + threadIdx.x;
    if (idx >= OGRP_*64*32) return;
    int lane = idx & 31;
    int kt = (idx >> 5) & 63;
    int grp = idx >> 11;
    int n  = grp*8 + (lane >> 2);
    int k0 = kt*16 + (lane & 3)*2;
    float w0=0.f, w1=0.f, w2=0.f, w3=0.f;
    if (n < POSE_) {
        w0 = Wo[(size_t)k0*POSE_ + n];     w1 = Wo[(size_t)(k0+1)*POSE_ + n];
        w2 = Wo[(size_t)(k0+8)*POSE_ + n]; w3 = Wo[(size_t)(k0+9)*POSE_ + n];
    }
    out[idx] = make_uint2(packbf(w0,w1), packbf(w2,w3));
}

__global__ void init_dec_k(const float* __restrict__ vh, unsigned* __restrict__ hb)
{
    int i = blockIdx.x*256 + threadIdx.x;
    if (i == 0) { g_cnt = 0; g_ocnt = 0; }
    if (i < HBTOT_) {
        int b = i / HBW_, kw = i % HBW_;
        int k0 = kw*2;
        float v0 = (k0   < HID_) ? vh[b*HID_ + k0]   : 0.f;
        float v1 = (k0+1 < HID_) ? vh[b*HID_ + k0+1] : 0.f;
        hb[3*HBTOT_ + i] = packbf(v0, v1);
    }
}

__device__ __forceinline__ float sigf(float x){ return 1.f/(1.f+expf(-x)); }

__device__ __forceinline__ unsigned ld_acq(const unsigned* p) {
    unsigned v;
    asm volatile("ld.acquire.gpu.global.u32 %0, [%1];" : "=r"(v) : "l"(p) : "memory");
    return v;
}
__device__ __forceinline__ void red_rel(unsigned* p) {
    asm volatile("red.release.gpu.global.add.u32 [%0], 1;" :: "l"(p) : "memory");
}

// grid = 146 x 128 threads. Blocks 0..127: gates (8 units each). 128..145: out-proj.
__global__ __launch_bounds__(128)
void dec_k(const uint2* __restrict__ WHB, const uint2* __restrict__ WXB,
           const uint2* __restrict__ OWB, const float* __restrict__ lb,
           const float* __restrict__ xwx, const float* __restrict__ encp,
           const float* __restrict__ vec_c, const float* __restrict__ dec0,
           unsigned* __restrict__ hb, float* __restrict__ outbuf,
           const int* __restrict__ ep)
{
    extern __shared__ unsigned smu[];
    unsigned* hbs = smu;
    unsigned* xbs = smu + HBTOT_;
    float*    red = (float*)(smu + HBTOT_ + 16*XBW_);
    float*    redo = (float*)(smu + HBTOT_);

    int tid = threadIdx.x, bx = blockIdx.x;
    int lane = tid & 31, w = tid >> 5;
    int b = lane >> 2, tg = lane & 3;
    bool isGate = bx < GATEB_;
    int p = (int)((double)(*ep) * 0.01);   // double required: fp32 100*0.01 -> 0
    int per = p + 10;

    int u0 = bx*8 + tg*2;
    float c0=0.f, c1=0.f, c2=0.f, c3=0.f;
    if (isGate && w == 0) {
        c0 = vec_c[b*HID_ + u0];       c1 = vec_c[b*HID_ + u0 + 1];
        c2 = vec_c[(b+8)*HID_ + u0];   c3 = vec_c[(b+8)*HID_ + u0 + 1];
    }
    int ob = bx - GATEB_;
    int grp = ob*2 + (w >> 1);
    int kh = w & 1;
    bool ovalid = (grp < OGRP_);

#define HBS_COPY(hrp) { \
        const uint4* srcv = (const uint4*)(hrp); uint4* dstv = (uint4*)hbs; \
        for (int i = tid; i < HBTOT_/4; i += 128) dstv[i] = __ldcg(srcv + i); }

#define A_LOAD(buf, stride, ktv) { \
        int wA = b*(stride) + (ktv)*8 + tg; \
        a[0] = (buf)[wA]; a[1] = (buf)[wA + 8*(stride)]; \
        a[2] = (buf)[wA + 4]; a[3] = (buf)[wA + 8*(stride) + 4]; }

    if (isGate) {
        for (int t = 0; t < S_; t++) {
            bool sampled = (t % per) < p;
            const unsigned* hr = hb + ((t+3)&3)*(size_t)HBTOT_;
            unsigned*       hw = hb + (t&3)*(size_t)HBTOT_;

            unsigned needO = 0;
            if (sampled) needO = 18u*(unsigned)t;
            else if (t >= 4) needO = 18u*(unsigned)(t-3);
            if (tid == 0) {
                if (t > 0) { unsigned needH = 128u*(unsigned)t;
                    while (ld_acq(&g_cnt) < needH) ; }
                if (needO)  while (ld_acq(&g_ocnt) < needO) ;
            }
            __syncthreads();

            float2 xw[8];
            if (w == 0 && !sampled) {
#pragma unroll
                for (int q = 0; q < 4; q++)
#pragma unroll
                    for (int rr = 0; rr < 2; rr++)
                        xw[q*2+rr] = __ldcg((const float2*)(xwx +
                            ((size_t)(b + rr*8)*S_ + t)*G4_ + q*1024 + u0));
            }
            HBS_COPY(hr);
            if (sampled) {
                const float* xsrc0 = (t == 0) ? dec0 : (outbuf + (size_t)(t-1)*POSE_);
                size_t bstride = (t == 0) ? (size_t)POSE_ : (size_t)S_*POSE_;
                for (int i = tid; i < 16*(XBW_-4); i += 128) {
                    int b2 = i / (XBW_-4), kw = i % (XBW_-4);
                    int k0 = kw*2;
                    const float* sp = xsrc0 + (size_t)b2*bstride;
                    float v0 = (k0   < POSE_) ? __ldcg(sp + k0)   : 0.f;
                    float v1 = (k0+1 < POSE_) ? __ldcg(sp + k0+1) : 0.f;
                    xbs[b2*XBW_ + kw] = packbf(v0, v1);
                }
            }
            __syncthreads();

            float d[4][4];
#pragma unroll
            for (int q = 0; q < 4; q++)
#pragma unroll
                for (int i = 0; i < 4; i++) d[q][i] = 0.f;
            unsigned a[4];
#pragma unroll 4
            for (int kt16 = 0; kt16 < 16; kt16++) {
                int kt = w*16 + kt16;
                A_LOAD(hbs, HBW_, kt);
#pragma unroll
                for (int q = 0; q < 4; q++) {
                    uint2 bb = WHB[(((size_t)bx*4 + q)*64 + kt)*32 + lane];
                    mma_bf16(d[q], a, &bb.x);
                }
            }
            if (sampled) {
                int e2 = min(18, w*5 + 5);
                for (int kt2 = w*5; kt2 < e2; kt2++) {
                    A_LOAD(xbs, XBW_, kt2);
#pragma unroll
                    for (int q = 0; q < 4; q++) {
                        uint2 bb = WXB[(((size_t)bx*4 + q)*18 + kt2)*32 + lane];
                        mma_bf16(d[q], a, &bb.x);
                    }
                }
            }
            {
                float* myr = red + (w*32 + lane)*16;
#pragma unroll
                for (int q = 0; q < 4; q++)
#pragma unroll
                    for (int i = 0; i < 4; i++) myr[q*4+i] = d[q][i];
            }
            __syncthreads();

            if (w == 0) {
                float s[16];
#pragma unroll
                for (int i = 0; i < 16; i++) s[i] = 0.f;
#pragma unroll
                for (int w2 = 0; w2 < 4; w2++) {
                    const float4* r4 = (const float4*)(red + (w2*32 + lane)*16);
#pragma unroll
                    for (int q = 0; q < 4; q++) {
                        float4 v = r4[q];
                        s[q*4+0] += v.x; s[q*4+1] += v.y; s[q*4+2] += v.z; s[q*4+3] += v.w;
                    }
                }
                float gate[4][4];
#pragma unroll
                for (int q = 0; q < 4; q++) {
                    float2 lbv = *(const float2*)(lb + q*1024 + u0);
                    gate[q][0] = s[q*4+0] + lbv.x;
                    gate[q][1] = s[q*4+1] + lbv.y;
                    gate[q][2] = s[q*4+2] + lbv.x;
                    gate[q][3] = s[q*4+3] + lbv.y;
                    if (!sampled) {
                        gate[q][0] += xw[q*2].x;   gate[q][1] += xw[q*2].y;
                        gate[q][2] += xw[q*2+1].x; gate[q][3] += xw[q*2+1].y;
                    }
                }
                float cc[4] = {c0, c1, c2, c3};
                float hh[4];
#pragma unroll
                for (int e = 0; e < 4; e++) {
                    float cv = sigf(gate[1][e])*cc[e] + sigf(gate[0][e])*tanhf(gate[2][e]);
                    hh[e] = sigf(gate[3][e])*tanhf(cv);
                    cc[e] = cv;
                }
                c0 = cc[0]; c1 = cc[1]; c2 = cc[2]; c3 = cc[3];
                hw[b*HBW_ + bx*4 + tg]     = packbf(hh[0], hh[1]);
                hw[(b+8)*HBW_ + bx*4 + tg] = packbf(hh[2], hh[3]);
            }
            __syncthreads();
            if (tid == 0) red_rel(&g_cnt);
        }
    } else {
        for (int t = 0; t < S_; t++) {
            if (tid == 0) {
                unsigned needH = 128u*(unsigned)(t+1);
                while (ld_acq(&g_cnt) < needH) ;
            }
            __syncthreads();
            const unsigned* hrp = hb + (t&3)*(size_t)HBTOT_;
            HBS_COPY(hrp);
            __syncthreads();
            float d[4] = {0.f,0.f,0.f,0.f};
            unsigned a[4];
            if (ovalid) {
#pragma unroll 4
                for (int kt16 = 0; kt16 < 32; kt16++) {
                    int kt = kh*32 + kt16;
                    A_LOAD(hbs, HBW_, kt);
                    uint2 bb = OWB[((size_t)grp*64 + kt)*32 + lane];
                    mma_bf16(d, a, &bb.x);
                }
            }
            float* myr = redo + (w*32 + lane)*4;
            myr[0]=d[0]; myr[1]=d[1]; myr[2]=d[2]; myr[3]=d[3];
            __syncthreads();
            if ((w & 1) == 0 && ovalid) {
                float s0 = redo[(w*32+lane)*4+0] + redo[((w+1)*32+lane)*4+0];
                float s1 = redo[(w*32+lane)*4+1] + redo[((w+1)*32+lane)*4+1];
                float s2 = redo[(w*32+lane)*4+2] + redo[((w+1)*32+lane)*4+2];
                float s3 = redo[(w*32+lane)*4+3] + redo[((w+1)*32+lane)*4+3];
                int n0 = grp*8 + tg*2;
                if (n0 + 1 < POSE_) {
                    size_t o0 = ((size_t)b*S_ + t)*POSE_ + n0;
                    size_t o1 = ((size_t)(b+8)*S_ + t)*POSE_ + n0;
                    float2 e0 = *(const float2*)(encp + o0);
                    float2 e1 = *(const float2*)(encp + o1);
                    *(float2*)(outbuf + o0) = make_float2(s0 + e0.x, s1 + e0.y);
                    *(float2*)(outbuf + o1) = make_float2(s2 + e1.x, s3 + e1.y);
                }
            }
            __syncthreads();
            if (tid == 0) red_rel(&g_ocnt);
        }
    }
#undef A_LOAD
#undef HBS_COPY
}

extern "C" void kernel_launch(void* const* d_in, const int* in_sizes, int n_in,
                              void* d_out, int out_size)
{
    (void)in_sizes; (void)n_in; (void)out_size;
    const float* src_seq = (const float*)d_in[0];
    const int*   src_pos = (const int*)  d_in[1];
    const float* tgt_seq = (const float*)d_in[2];
    const float* vec_h   = (const float*)d_in[3];
    const float* vec_c   = (const float*)d_in[4];
    const float* dec0    = (const float*)d_in[5];
    const float* emb_W   = (const float*)d_in[6];
    const float* emb_b   = (const float*)d_in[7];
    const float* pos_t   = (const float*)d_in[8];
    const float* Wq      = (const float*)d_in[9];
    const float* Wk      = (const float*)d_in[10];
    const float* Wv      = (const float*)d_in[11];
    const float* Wo      = (const float*)d_in[12];
    const float* ln1g    = (const float*)d_in[13];
    const float* ln1b    = (const float*)d_in[14];
    const float* fW1     = (const float*)d_in[15];
    const float* fb1     = (const float*)d_in[16];
    const float* fW2     = (const float*)d_in[17];
    const float* fb2     = (const float*)d_in[18];
    const float* ln2g    = (const float*)d_in[19];
    const float* ln2b    = (const float*)d_in[20];
    const float* lWx     = (const float*)d_in[21];
    const float* lWh     = (const float*)d_in[22];
    const float* lb      = (const float*)d_in[23];
    const float* outW    = (const float*)d_in[24];
    const float* outb    = (const float*)d_in[25];
    const int*   ep      = (const int*)  d_in[26];
    float* out = (float*)d_out;

    void *px,*pq,*pk,*pv,*po,*pr1,*px2,*ph1,*pt2,*penc,*pxwx,*pencp,*phb,*pwhb,*pwxb,*powb,*pap,*pwp;
    cudaGetSymbolAddress(&px,  g_x);   cudaGetSymbolAddress(&pq,  g_q);
    cudaGetSymbolAddress(&pk,  g_k);   cudaGetSymbolAddress(&pv,  g_v);
    cudaGetSymbolAddress(&po,  g_o);   cudaGetSymbolAddress(&pr1, g_r1);
    cudaGetSymbolAddress(&px2, g_x2);  cudaGetSymbolAddress(&ph1, g_h1);
    cudaGetSymbolAddress(&pt2, g_t2);  cudaGetSymbolAddress(&penc,g_enc);
    cudaGetSymbolAddress(&pxwx,g_xwx); cudaGetSymbolAddress(&pencp,g_encp);
    cudaGetSymbolAddress(&phb, g_hb);  cudaGetSymbolAddress(&pwhb,g_whb);
    cudaGetSymbolAddress(&pwxb,g_wxb); cudaGetSymbolAddress(&powb,g_owb);
    cudaGetSymbolAddress(&pap, g_ap);  cudaGetSymbolAddress(&pwp, g_wp);
    float *X=(float*)px, *Qb=(float*)pq, *Kb=(float*)pk, *Vb=(float*)pv, *Ob=(float*)po;
    float *R1=(float*)pr1, *X2=(float*)px2, *H1=(float*)ph1, *T2=(float*)pt2, *ENC=(float*)penc;
    float *XWX=(float*)pxwx, *ENCP=(float*)pencp;
    unsigned *HB=(unsigned*)phb;
    uint2 *WHB=(uint2*)pwhb, *WXB=(uint2*)pwxb, *OWB=(uint2*)powb;
    uint2 *AP=(uint2*)pap, *WP=(uint2*)pwp;

    cudaFuncSetAttribute(attn_k, cudaFuncAttributeMaxDynamicSharedMemorySize, KSPAN_*KROW_*4);
    cudaFuncSetAttribute(dec_k,  cudaFuncAttributeMaxDynamicSharedMemorySize, 50688);

    dim3 gD((D_+63)/64, M_/128), gF((FFN_+63)/64, M_/128);
    dim3 gG4((G4_+63)/64, M_/128), gP((POSE_+63)/64, M_/128);

#define PACKA(src, KP) packa_k<<<((M_*(KP))+255)/256,256>>>((src), AP, M_*(KP))
#define PACKW(src, KP, N) packw_k<<<(((KP)*(N))+255)/256,256>>>((src), WP, (KP), (N))

    // encoder (pre-packed split-bf16 tensor-core GEMMs)
    PACKA(src_seq, 219); PACKW(emb_W, 219, D_);
    gemmp_k<EPI_POS><<<gD,256>>>(AP, 219, WP, X, D_, emb_b, nullptr, pos_t, src_pos);
    PACKA(X, 400);
    PACKW(Wq, 400, D_);
    gemmp_k<EPI_NONE><<<gD,256>>>(AP, 400, WP, Qb, D_, nullptr, nullptr, nullptr, nullptr);
    PACKW(Wk, 400, D_);
    gemmp_k<EPI_NONE><<<gD,256>>>(AP, 400, WP, Kb, D_, nullptr, nullptr, nullptr, nullptr);
    PACKW(Wv, 400, D_);
    gemmp_k<EPI_NONE><<<gD,256>>>(AP, 400, WP, Vb, D_, nullptr, nullptr, nullptr, nullptr);
    attn_k<<<dim3(S_/QT_, H_, B_),128,KSPAN_*KROW_*4>>>(Qb, Kb, Vb, Ob);
    PACKA(Ob, 400); PACKW(Wo, 400, D_);
    gemmp_k<EPI_ADD><<<gD,256>>>(AP, 400, WP, R1, D_, nullptr, X, nullptr, nullptr);
    ln_k<<<M_,256>>>(R1, X2, ln1g, ln1b);
    PACKA(X2, 400); PACKW(fW1, 400, FFN_);
    gemmp_k<EPI_BIAS_RELU><<<gF,256>>>(AP, 400, WP, H1, FFN_, fb1, nullptr, nullptr, nullptr);
    PACKA(H1, 512); PACKW(fW2, 512, D_);
    gemmp_k<EPI_BIAS_ADD><<<gD,256>>>(AP, 512, WP, T2, D_, fb2, X2, nullptr, nullptr);
    ln_k<<<M_,256>>>(T2, ENC, ln2g, ln2b);

    // decoder precompute
    PACKA(tgt_seq, 137); PACKW(lWx, 137, G4_);
    gemmp_k<EPI_NONE><<<gG4,256>>>(AP, 137, WP, XWX, G4_, nullptr, nullptr, nullptr, nullptr);
    PACKA(ENC, 400); PACKW(outW + (size_t)HID_*POSE_, 400, POSE_);
    gemmp_k<EPI_BIAS><<<gP,256>>>(AP, 400, WP, ENCP, POSE_, outb, nullptr, nullptr, nullptr);

    pack_whb_k<<<(GATEB_*4*64*32+255)/256,256>>>(lWh, WHB);
    pack_wxb_k<<<(GATEB_*4*18*32+255)/256,256>>>(lWx, WXB);
    pack_owb_k<<<(OGRP_*64*32+255)/256,256>>>(outW, OWB);
    init_dec_k<<<(HBTOT_+255)/256,256>>>(vec_h, HB);

    dec_k<<<NB_,128,50688>>>(WHB, WXB, OWB, lb, XWX, ENCP, vec_c, dec0, HB, out, ep);
#undef PACKA
#undef PACKW
}

// round 12
// speedup vs baseline: 1.4007x; 1.0630x over previous
#include <cuda_runtime.h>
#include <cuda_bf16.h>
#include <math.h>

#define B_ 16
#define S_ 512
#define FRAME_ 438
#define D_ 800
#define H_ 8
#define DH_ 100
#define FFN_ 1024
#define HID_ 1024
#define POSE_ 274
#define WIN_ 100
#define M_ (B_*S_)
#define G4_ (4*HID_)
#define QT_ 8
#define KSPAN_ (2*WIN_+QT_)
#define KROW_ 101
#define NGB_ 32
#define NOB_ 5
#define NBD_ (NGB_+NOB_)
#define HBW_ 516
#define HBTOT_ (16*HBW_)
#define XBW_ 148
#define OGRP_ 35
#define GATEB_ 128

__device__ float g_x[M_*D_];
__device__ float g_q[M_*D_];
__device__ float g_k[M_*D_];
__device__ float g_v[M_*D_];
__device__ float g_o[M_*D_];
__device__ float g_r1[M_*D_];
__device__ float g_x2[M_*D_];
__device__ float g_h1[M_*FFN_];
__device__ float g_t2[M_*D_];
__device__ float g_enc[M_*D_];
__device__ float g_xwx[(size_t)M_*G4_];
__device__ float g_encp[M_*POSE_];
__device__ __align__(16) unsigned g_hb[4*HBTOT_];
__device__ uint2 g_whb[(size_t)GATEB_*4*64*32];
__device__ uint2 g_wxb[(size_t)GATEB_*4*18*32];
__device__ uint2 g_owb[(size_t)OGRP_*64*32];
__device__ uint2 g_ap[(size_t)M_*512];
__device__ uint2 g_wp[600000];
__device__ unsigned g_cnt;
__device__ unsigned g_ocnt;

enum { EPI_NONE=0, EPI_POS=1, EPI_ADD=2, EPI_BIAS_RELU=3, EPI_BIAS_ADD=4, EPI_BIAS=5 };

__device__ __forceinline__ unsigned packbf(float a, float b) {
    __nv_bfloat162 t = __float22bfloat162_rn(make_float2(a, b));
    return *(unsigned*)&t;
}
__device__ __forceinline__ float bfres(float x, float& hi) {
    __nv_bfloat16 h = __float2bfloat16_rn(x);
    hi = __bfloat162float(h);
    return x - hi;
}
__device__ __forceinline__ void mma_bf16(float* d, const unsigned* a, const unsigned* b) {
    asm volatile("mma.sync.aligned.m16n8k16.row.col.f32.bf16.bf16.f32 "
        "{%0,%1,%2,%3}, {%4,%5,%6,%7}, {%8,%9}, {%0,%1,%2,%3};"
        : "+f"(d[0]), "+f"(d[1]), "+f"(d[2]), "+f"(d[3])
        : "r"(a[0]), "r"(a[1]), "r"(a[2]), "r"(a[3]), "r"(b[0]), "r"(b[1]));
}

// ---------------- split-bf16 pre-pack kernels ----------------
__global__ void packa_k(const float* __restrict__ A, uint2* __restrict__ out, int npairs)
{
    int i = blockIdx.x*256 + threadIdx.x;
    if (i < npairs) {
        float2 v = ((const float2*)A)[i];
        float h0, h1;
        float l0 = bfres(v.x, h0), l1 = bfres(v.y, h1);
        out[i] = make_uint2(packbf(h0, h1), packbf(l0, l1));
    }
}
__global__ void packw_k(const float* __restrict__ W, uint2* __restrict__ out, int KP, int Nn)
{
    int i = blockIdx.x*256 + threadIdx.x;
    if (i < KP*Nn) {
        int kp = i / Nn, n = i % Nn;
        float w0 = W[(size_t)(2*kp)*Nn + n];
        float w1 = W[(size_t)(2*kp+1)*Nn + n];
        float h0, h1;
        float l0 = bfres(w0, h0), l1 = bfres(w1, h1);
        out[i] = make_uint2(packbf(h0, h1), packbf(l0, l1));
    }
}

// ---------------- packed split-bf16 tensor-core GEMM ----------------
template<int EPI>
__global__ __launch_bounds__(256)
void gemmp_k(const uint2* __restrict__ Ap, int KP,
             const uint2* __restrict__ Wp,
             float* __restrict__ C, int Nn,
             const float* __restrict__ bias, const float* __restrict__ addend,
             const float* __restrict__ pos_table, const int* __restrict__ pos_idx)
{
    __shared__ uint2 Asm[128*17];
    __shared__ uint2 Wsm[16*65];
    int tid = threadIdx.x, lane = tid & 31, w = tid >> 5;
    int wm = w >> 1, wn = w & 1;
    int rowBase = blockIdx.y * 128, colBase = blockIdx.x * 64;
    int tg = lane & 3, qd = lane >> 2;

    float d[2][4][4];
#pragma unroll
    for (int mt = 0; mt < 2; mt++)
#pragma unroll
        for (int nt = 0; nt < 4; nt++)
#pragma unroll
            for (int i = 0; i < 4; i++) d[mt][nt][i] = 0.f;

    for (int k0p = 0; k0p < KP; k0p += 16) {
#pragma unroll
        for (int ii = 0; ii < 8; ii++) {
            int i = ii*256 + tid;
            int row = i >> 4, kw = i & 15, gkp = k0p + kw;
            Asm[row*17 + kw] = (gkp < KP) ? Ap[(size_t)(rowBase+row)*KP + gkp]
                                          : make_uint2(0u, 0u);
        }
#pragma unroll
        for (int ii = 0; ii < 4; ii++) {
            int i = ii*256 + tid;
            int n = i & 63, kw = i >> 6;
            int gkp = k0p + kw, gn = colBase + n;
            Wsm[kw*65 + n] = (gkp < KP && gn < Nn) ? Wp[(size_t)gkp*Nn + gn]
                                                   : make_uint2(0u, 0u);
        }
        __syncthreads();
#pragma unroll
        for (int kt = 0; kt < 2; kt++) {
            unsigned ah[2][4], al[2][4], bh[4][2], bl[4][2];
#pragma unroll
            for (int mt = 0; mt < 2; mt++) {
                int base = (wm*32 + mt*16 + qd)*17 + kt*8 + tg;
                uint2 q0 = Asm[base],     q1 = Asm[base + 8*17];
                uint2 q2 = Asm[base + 4], q3 = Asm[base + 8*17 + 4];
                ah[mt][0]=q0.x; ah[mt][1]=q1.x; ah[mt][2]=q2.x; ah[mt][3]=q3.x;
                al[mt][0]=q0.y; al[mt][1]=q1.y; al[mt][2]=q2.y; al[mt][3]=q3.y;
            }
#pragma unroll
            for (int nt = 0; nt < 4; nt++) {
                int nn = wn*32 + nt*8 + qd;
                int kb = kt*8 + tg;
                uint2 q0 = Wsm[kb*65 + nn], q1 = Wsm[(kb+4)*65 + nn];
                bh[nt][0]=q0.x; bh[nt][1]=q1.x;
                bl[nt][0]=q0.y; bl[nt][1]=q1.y;
            }
#pragma unroll
            for (int mt = 0; mt < 2; mt++)
#pragma unroll
                for (int nt = 0; nt < 4; nt++) {
                    mma_bf16(d[mt][nt], ah[mt], bh[nt]);
                    mma_bf16(d[mt][nt], ah[mt], bl[nt]);
                    mma_bf16(d[mt][nt], al[mt], bh[nt]);
                }
        }
        __syncthreads();
    }

#pragma unroll
    for (int mt = 0; mt < 2; mt++) {
#pragma unroll
        for (int nt = 0; nt < 4; nt++) {
#pragma unroll
            for (int half = 0; half < 2; half++) {
                int row = rowBase + wm*32 + mt*16 + qd + half*8;
                int col = colBase + wn*32 + nt*8 + tg*2;
                if (col < Nn) {
                    float v0 = d[mt][nt][half*2+0];
                    float v1 = d[mt][nt][half*2+1];
                    if (EPI == EPI_POS) {
                        size_t pb = (size_t)pos_idx[row]*Nn + col;
                        v0 += bias[col]   + pos_table[pb];
                        v1 += bias[col+1] + pos_table[pb+1];
                    } else if (EPI == EPI_ADD) {
                        size_t ab = (size_t)row*Nn + col;
                        v0 += addend[ab]; v1 += addend[ab+1];
                    } else if (EPI == EPI_BIAS_RELU) {
                        v0 += bias[col]; v1 += bias[col+1];
                        v0 = v0 > 0.f ? v0 : 0.f; v1 = v1 > 0.f ? v1 : 0.f;
                    } else if (EPI == EPI_BIAS_ADD) {
                        size_t ab = (size_t)row*Nn + col;
                        v0 += bias[col] + addend[ab]; v1 += bias[col+1] + addend[ab+1];
                    } else if (EPI == EPI_BIAS) {
                        v0 += bias[col]; v1 += bias[col+1];
                    }
                    *(float2*)(C + (size_t)row*Nn + col) = make_float2(v0, v1);
                }
            }
        }
    }
}

__global__ __launch_bounds__(256)
void ln_k(const float* __restrict__ in, float* __restrict__ out,
          const float* __restrict__ g, const float* __restrict__ b)
{
    __shared__ float buf[D_];
    __shared__ float red[256];
    int row = blockIdx.x, tid = threadIdx.x;
    float s = 0.f;
    for (int i = tid; i < D_; i += 256) { float v = in[(size_t)row*D_ + i]; buf[i] = v; s += v; }
    red[tid] = s; __syncthreads();
    for (int st = 128; st > 0; st >>= 1) { if (tid < st) red[tid] += red[tid+st]; __syncthreads(); }
    float mean = red[0] / (float)D_;
    __syncthreads();
    float ss = 0.f;
    for (int i = tid; i < D_; i += 256) { float dd = buf[i]-mean; ss += dd*dd; }
    red[tid] = ss; __syncthreads();
    for (int st = 128; st > 0; st >>= 1) { if (tid < st) red[tid] += red[tid+st]; __syncthreads(); }
    float inv = rsqrtf(red[0]/(float)D_ + 1e-6f);
    for (int i = tid; i < D_; i += 256)
        out[(size_t)row*D_ + i] = (buf[i]-mean)*inv*g[i] + b[i];
}

__global__ __launch_bounds__(128)
void attn_k(const float* __restrict__ Q, const float* __restrict__ K,
            const float* __restrict__ V, float* __restrict__ O)
{
    extern __shared__ float ks[];
    __shared__ float qs[QT_*DH_];
    __shared__ float sc[QT_][KSPAN_];
    __shared__ float invs[QT_];
    int tid = threadIdx.x;
    int q0 = blockIdx.x * QT_, h = blockIdx.y, b = blockIdx.z;
    int kl = max(0, q0 - WIN_);
    int kh = min(S_-1, q0 + QT_-1 + WIN_);
    int nk = kh - kl + 1;
    size_t base = ((size_t)b*S_)*D_ + (size_t)h*DH_;

    for (int idx = tid; idx < QT_*DH_; idx += 128) {
        int qi = idx / DH_, dd = idx % DH_;
        qs[idx] = Q[base + (size_t)(q0+qi)*D_ + dd];
    }
    for (int idx = tid; idx < nk*DH_; idx += 128) {
        int kk = idx / DH_, dd = idx % DH_;
        ks[kk*KROW_ + dd] = K[base + (size_t)(kl+kk)*D_ + dd];
    }
    __syncthreads();

    for (int pid = tid; pid < QT_*nk; pid += 128) {
        int kk = pid % nk, qi = pid / nk;
        int qq = q0 + qi, kp = kl + kk;
        float v;
        if (kp >= qq - WIN_ && kp <= qq + WIN_) {
            float dd = 0.f;
            for (int i = 0; i < DH_; i++) dd += qs[qi*DH_ + i]*ks[kk*KROW_ + i];
            v = dd * 0.1f;
        } else v = -1e30f;
        sc[qi][kk] = v;
    }
    __syncthreads();
    {
        int qi = tid >> 4, l = tid & 15;
        float m = -1e30f;
        for (int kk = l; kk < nk; kk += 16) m = fmaxf(m, sc[qi][kk]);
#pragma unroll
        for (int s2 = 8; s2 > 0; s2 >>= 1) m = fmaxf(m, __shfl_xor_sync(0xffffffffu, m, s2, 16));
        float ssum = 0.f;
        for (int kk = l; kk < nk; kk += 16) { float e = expf(sc[qi][kk]-m); sc[qi][kk] = e; ssum += e; }
#pragma unroll
        for (int s2 = 8; s2 > 0; s2 >>= 1) ssum += __shfl_xor_sync(0xffffffffu, ssum, s2, 16);
        if (l == 0) invs[qi] = 1.f / ssum;
    }
    __syncthreads();
    if (tid < DH_) {
        float acc[QT_];
#pragma unroll
        for (int qi = 0; qi < QT_; qi++) acc[qi] = 0.f;
        for (int kk = 0; kk < nk; kk++) {
            float vv = V[base + (size_t)(kl+kk)*D_ + tid];
#pragma unroll
            for (int qi = 0; qi < QT_; qi++) acc[qi] += sc[qi][kk]*vv;
        }
#pragma unroll
        for (int qi = 0; qi < QT_; qi++)
            O[base + (size_t)(q0+qi)*D_ + tid] = acc[qi]*invs[qi];
    }
}

// ---------------- decoder pack kernels (unchanged layouts) ----------------
__global__ void pack_whb_k(const float* __restrict__ Wh, uint2* __restrict__ out)
{
    size_t idx = (size_t)blockIdx.x*256 + threadIdx.x;
    if (idx >= (size_t)GATEB_*4*64*32) return;
    int lane = idx & 31;
    int kt = (idx >> 5) & 63;
    int q  = (idx >> 11) & 3;
    int g  = idx >> 13;
    int j  = q*1024 + g*8 + (lane >> 2);
    int k0 = kt*16 + (lane & 3)*2;
    float w0 = Wh[(size_t)k0*G4_ + j],     w1 = Wh[(size_t)(k0+1)*G4_ + j];
    float w2 = Wh[(size_t)(k0+8)*G4_ + j], w3 = Wh[(size_t)(k0+9)*G4_ + j];
    out[idx] = make_uint2(packbf(w0,w1), packbf(w2,w3));
}

__global__ void pack_wxb_k(const float* __restrict__ Wx, uint2* __restrict__ out)
{
    size_t idx = (size_t)blockIdx.x*256 + threadIdx.x;
    if (idx >= (size_t)GATEB_*4*18*32) return;
    int lane = idx & 31;
    size_t r = idx >> 5;
    int kt = r % 18;
    int q  = (r / 18) & 3;
    int g  = r / 72;
    int j  = q*1024 + g*8 + (lane >> 2);
    int k0 = kt*16 + (lane & 3)*2;
    float w0 = (k0   < POSE_) ? Wx[(size_t)k0*G4_ + j]     : 0.f;
    float w1 = (k0+1 < POSE_) ? Wx[(size_t)(k0+1)*G4_ + j] : 0.f;
    float w2 = (k0+8 < POSE_) ? Wx[(size_t)(k0+8)*G4_ + j] : 0.f;
    float w3 = (k0+9 < POSE_) ? Wx[(size_t)(k0+9)*G4_ + j] : 0.f;
    out[idx] = make_uint2(packbf(w0,w1), packbf(w2,w3));
}

__global__ void pack_owb_k(const float* __restrict__ Wo, uint2* __restrict__ out)
{
    int idx = blockIdx.x*256 + threadIdx.x;
    if (idx >= OGRP_*64*32) return;
    int lane = idx & 31;
    int kt = (idx >> 5) & 63;
    int grp = idx >> 11;
    int n  = grp*8 + (lane >> 2);
    int k0 = kt*16 + (lane & 3)*2;
    float w0=0.f, w1=0.f, w2=0.f, w3=0.f;
    if (n < POSE_) {
        w0 = Wo[(size_t)k0*POSE_ + n];     w1 = Wo[(size_t)(k0+1)*POSE_ + n];
        w2 = Wo[(size_t)(k0+8)*POSE_ + n]; w3 = Wo[(size_t)(k0+9)*POSE_ + n];
    }
    out[idx] = make_uint2(packbf(w0,w1), packbf(w2,w3));
}

__global__ void init_dec_k(const float* __restrict__ vh, unsigned* __restrict__ hb)
{
    int i = blockIdx.x*256 + threadIdx.x;
    if (i == 0) { g_cnt = 0; g_ocnt = 0; }
    if (i < HBTOT_) {
        int b = i / HBW_, kw = i % HBW_;
        int k0 = kw*2;
        float v0 = (k0   < HID_) ? vh[b*HID_ + k0]   : 0.f;
        float v1 = (k0+1 < HID_) ? vh[b*HID_ + k0+1] : 0.f;
        hb[3*HBTOT_ + i] = packbf(v0, v1);
    }
}

__device__ __forceinline__ float sigf(float x){ return 1.f/(1.f+expf(-x)); }

__device__ __forceinline__ unsigned ld_acq(const unsigned* p) {
    unsigned v;
    asm volatile("ld.acquire.gpu.global.u32 %0, [%1];" : "=r"(v) : "l"(p) : "memory");
    return v;
}
__device__ __forceinline__ void red_rel(unsigned* p) {
    asm volatile("red.release.gpu.global.add.u32 [%0], 1;" :: "l"(p) : "memory");
}

// grid = 37 x 512. Blocks 0..31: gates (32 units each). 32..36: out-proj (8 grp slots each).
// dyn smem: hbs 8256w | xbs 2368w | red 8192f | hso 512f = 77312 B
__global__ __launch_bounds__(512)
void dec_k(const uint2* __restrict__ WHB, const uint2* __restrict__ WXB,
           const uint2* __restrict__ OWB, const float* __restrict__ lb,
           const float* __restrict__ xwx, const float* __restrict__ encp,
           const float* __restrict__ vec_c, const float* __restrict__ dec0,
           unsigned* __restrict__ hb, float* __restrict__ outbuf,
           const int* __restrict__ ep)
{
    extern __shared__ unsigned smu[];
    unsigned* hbs = smu;
    unsigned* xbs = smu + HBTOT_;
    float*    red = (float*)(smu + HBTOT_ + 16*XBW_);
    float*    hso = red + 8192;

    int tid = threadIdx.x, bx = blockIdx.x;
    int lane = tid & 31, w = tid >> 5;
    int b = lane >> 2, tg = lane & 3;
    bool isGate = bx < NGB_;
    int p = (int)((double)(*ep) * 0.01);   // double required: fp32 100*0.01 -> 0
    int per = p + 10;

#define HBS_COPY(hrp) { \
        const uint4* srcv = (const uint4*)(hrp); uint4* dstv = (uint4*)hbs; \
        for (int i = tid; i < HBTOT_/4; i += 512) dstv[i] = __ldcg(srcv + i); }

#define A_LOAD(buf, stride, ktv) { \
        int wA = b*(stride) + (ktv)*8 + tg; \
        a[0] = (buf)[wA]; a[1] = (buf)[wA + 8*(stride)]; \
        a[2] = (buf)[wA + 4]; a[3] = (buf)[wA + 8*(stride) + 4]; }

    if (isGate) {
        int ug = w >> 2, ksx = w & 3;           // warp: unit-group 0..3, k-split 0..3
        int gidx = bx*4 + ug;                    // old 8-unit group id for WHB/WXB
        int u3 = tid >> 4, b3 = tid & 15;        // final stage: (unit-in-block, batch)
        int gu = bx*32 + u3;                     // global unit
        float c = vec_c[b3*HID_ + gu];
        int lane2 = (b3 & 7)*4 + ((u3 & 7) >> 1);
        int i2 = (b3 >> 3)*2 + (u3 & 1);
        int wbase = (u3 >> 3)*4;

        for (int t = 0; t < S_; t++) {
            bool sampled = (t % per) < p;
            const unsigned* hr = hb + ((t+3)&3)*(size_t)HBTOT_;
            unsigned*       hw = hb + (t&3)*(size_t)HBTOT_;

            float xwr[4];
            if (!sampled) {
#pragma unroll
                for (int q = 0; q < 4; q++)
                    xwr[q] = __ldcg(xwx + ((size_t)b3*S_ + t)*G4_ + q*1024 + gu);
            }

            unsigned needO = 0;
            if (sampled) needO = (unsigned)(NOB_*t);
            else if (t >= 4) needO = (unsigned)(NOB_*(t-3));
            if (tid == 0 && t > 0) {
                unsigned needH = (unsigned)(NGB_*t);
                while (ld_acq(&g_cnt) < needH) ;
            }
            if (tid == 32 && needO) {
                while (ld_acq(&g_ocnt) < needO) ;
            }
            __syncthreads();

            HBS_COPY(hr);
            if (sampled) {
                const float* xsrc0 = (t == 0) ? dec0 : (outbuf + (size_t)(t-1)*POSE_);
                size_t bstride = (t == 0) ? (size_t)POSE_ : (size_t)S_*POSE_;
                for (int i = tid; i < 16*(XBW_-4); i += 512) {
                    int b2 = i / (XBW_-4), kw = i % (XBW_-4);
                    int k0 = kw*2;
                    const float* sp = xsrc0 + (size_t)b2*bstride;
                    float v0 = (k0   < POSE_) ? __ldcg(sp + k0)   : 0.f;
                    float v1 = (k0+1 < POSE_) ? __ldcg(sp + k0+1) : 0.f;
                    xbs[b2*XBW_ + kw] = packbf(v0, v1);
                }
            }
            __syncthreads();

            float d[4][4];
#pragma unroll
            for (int q = 0; q < 4; q++)
#pragma unroll
                for (int i = 0; i < 4; i++) d[q][i] = 0.f;
            unsigned a[4];
#pragma unroll 4
            for (int kt16 = 0; kt16 < 16; kt16++) {
                int kt = ksx*16 + kt16;
                A_LOAD(hbs, HBW_, kt);
#pragma unroll
                for (int q = 0; q < 4; q++) {
                    uint2 bb = WHB[(((size_t)gidx*4 + q)*64 + kt)*32 + lane];
                    mma_bf16(d[q], a, &bb.x);
                }
            }
            if (sampled) {
                int e2 = min(18, ksx*5 + 5);
                for (int kt2 = ksx*5; kt2 < e2; kt2++) {
                    A_LOAD(xbs, XBW_, kt2);
#pragma unroll
                    for (int q = 0; q < 4; q++) {
                        uint2 bb = WXB[(((size_t)gidx*4 + q)*18 + kt2)*32 + lane];
                        mma_bf16(d[q], a, &bb.x);
                    }
                }
            }
            {
                float* myr = red + (w*32 + lane)*16;
#pragma unroll
                for (int q = 0; q < 4; q++)
#pragma unroll
                    for (int i = 0; i < 4; i++) myr[q*4+i] = d[q][i];
            }
            __syncthreads();

            // per-thread LSTM pointwise: (u3, b3)
            {
                float gate[4];
#pragma unroll
                for (int q = 0; q < 4; q++) {
                    float s = 0.f;
#pragma unroll
                    for (int ks2 = 0; ks2 < 4; ks2++)
                        s += red[((wbase + ks2)*32 + lane2)*16 + q*4 + i2];
                    s += lb[q*1024 + gu];
                    if (!sampled) s += xwr[q];
                    gate[q] = s;
                }
                float cv = sigf(gate[1])*c + sigf(gate[0])*tanhf(gate[2]);
                float h = sigf(gate[3])*tanhf(cv);
                c = cv;
                hso[u3*16 + b3] = h;
            }
            __syncthreads();
            if (tid < 256) {
                int kwu = tid >> 4, bb2 = tid & 15;
                hw[bb2*HBW_ + bx*16 + kwu] =
                    packbf(hso[(2*kwu)*16 + bb2], hso[(2*kwu+1)*16 + bb2]);
            }
            __syncthreads();
            if (tid == 0) red_rel(&g_cnt);
        }
    } else {
        int ob = bx - NGB_;
        int grpi = w >> 1, kh = w & 1;
        int grp = ob*8 + grpi;
        bool ovalid = (grp < OGRP_);
        for (int t = 0; t < S_; t++) {
            if (tid == 0) {
                unsigned needH = (unsigned)(NGB_*(t+1));
                while (ld_acq(&g_cnt) < needH) ;
            }
            __syncthreads();
            const unsigned* hrp = hb + (t&3)*(size_t)HBTOT_;
            HBS_COPY(hrp);
            __syncthreads();
            float d[4] = {0.f,0.f,0.f,0.f};
            unsigned a[4];
            if (ovalid) {
#pragma unroll 4
                for (int kt16 = 0; kt16 < 32; kt16++) {
                    int kt = kh*32 + kt16;
                    A_LOAD(hbs, HBW_, kt);
                    uint2 bb = OWB[((size_t)grp*64 + kt)*32 + lane];
                    mma_bf16(d, a, &bb.x);
                }
            }
            float* myr = red + (w*32 + lane)*4;
            myr[0]=d[0]; myr[1]=d[1]; myr[2]=d[2]; myr[3]=d[3];
            __syncthreads();
            if ((w & 1) == 0 && ovalid) {
                float s0 = red[(w*32+lane)*4+0] + red[((w+1)*32+lane)*4+0];
                float s1 = red[(w*32+lane)*4+1] + red[((w+1)*32+lane)*4+1];
                float s2 = red[(w*32+lane)*4+2] + red[((w+1)*32+lane)*4+2];
                float s3 = red[(w*32+lane)*4+3] + red[((w+1)*32+lane)*4+3];
                int n0 = grp*8 + tg*2;
                if (n0 + 1 < POSE_) {
                    size_t o0 = ((size_t)b*S_ + t)*POSE_ + n0;
                    size_t o1 = ((size_t)(b+8)*S_ + t)*POSE_ + n0;
                    float2 e0 = *(const float2*)(encp + o0);
                    float2 e1 = *(const float2*)(encp + o1);
                    *(float2*)(outbuf + o0) = make_float2(s0 + e0.x, s1 + e0.y);
                    *(float2*)(outbuf + o1) = make_float2(s2 + e1.x, s3 + e1.y);
                }
            }
            __syncthreads();
            if (tid == 0) red_rel(&g_ocnt);
        }
    }
#undef A_LOAD
#undef HBS_COPY
}

extern "C" void kernel_launch(void* const* d_in, const int* in_sizes, int n_in,
                              void* d_out, int out_size)
{
    (void)in_sizes; (void)n_in; (void)out_size;
    const float* src_seq = (const float*)d_in[0];
    const int*   src_pos = (const int*)  d_in[1];
    const float* tgt_seq = (const float*)d_in[2];
    const float* vec_h   = (const float*)d_in[3];
    const float* vec_c   = (const float*)d_in[4];
    const float* dec0    = (const float*)d_in[5];
    const float* emb_W   = (const float*)d_in[6];
    const float* emb_b   = (const float*)d_in[7];
    const float* pos_t   = (const float*)d_in[8];
    const float* Wq      = (const float*)d_in[9];
    const float* Wk      = (const float*)d_in[10];
    const float* Wv      = (const float*)d_in[11];
    const float* Wo      = (const float*)d_in[12];
    const float* ln1g    = (const float*)d_in[13];
    const float* ln1b    = (const float*)d_in[14];
    const float* fW1     = (const float*)d_in[15];
    const float* fb1     = (const float*)d_in[16];
    const float* fW2     = (const float*)d_in[17];
    const float* fb2     = (const float*)d_in[18];
    const float* ln2g    = (const float*)d_in[19];
    const float* ln2b    = (const float*)d_in[20];
    const float* lWx     = (const float*)d_in[21];
    const float* lWh     = (const float*)d_in[22];
    const float* lb      = (const float*)d_in[23];
    const float* outW    = (const float*)d_in[24];
    const float* outb    = (const float*)d_in[25];
    const int*   ep      = (const int*)  d_in[26];
    float* out = (float*)d_out;

    void *px,*pq,*pk,*pv,*po,*pr1,*px2,*ph1,*pt2,*penc,*pxwx,*pencp,*phb,*pwhb,*pwxb,*powb,*pap,*pwp;
    cudaGetSymbolAddress(&px,  g_x);   cudaGetSymbolAddress(&pq,  g_q);
    cudaGetSymbolAddress(&pk,  g_k);   cudaGetSymbolAddress(&pv,  g_v);
    cudaGetSymbolAddress(&po,  g_o);   cudaGetSymbolAddress(&pr1, g_r1);
    cudaGetSymbolAddress(&px2, g_x2);  cudaGetSymbolAddress(&ph1, g_h1);
    cudaGetSymbolAddress(&pt2, g_t2);  cudaGetSymbolAddress(&penc,g_enc);
    cudaGetSymbolAddress(&pxwx,g_xwx); cudaGetSymbolAddress(&pencp,g_encp);
    cudaGetSymbolAddress(&phb, g_hb);  cudaGetSymbolAddress(&pwhb,g_whb);
    cudaGetSymbolAddress(&pwxb,g_wxb); cudaGetSymbolAddress(&powb,g_owb);
    cudaGetSymbolAddress(&pap, g_ap);  cudaGetSymbolAddress(&pwp, g_wp);
    float *X=(float*)px, *Qb=(float*)pq, *Kb=(float*)pk, *Vb=(float*)pv, *Ob=(float*)po;
    float *R1=(float*)pr1, *X2=(float*)px2, *H1=(float*)ph1, *T2=(float*)pt2, *ENC=(float*)penc;
    float *XWX=(float*)pxwx, *ENCP=(float*)pencp;
    unsigned *HB=(unsigned*)phb;
    uint2 *WHB=(uint2*)pwhb, *WXB=(uint2*)pwxb, *OWB=(uint2*)powb;
    uint2 *AP=(uint2*)pap, *WP=(uint2*)pwp;

    cudaFuncSetAttribute(attn_k, cudaFuncAttributeMaxDynamicSharedMemorySize, KSPAN_*KROW_*4);
    cudaFuncSetAttribute(dec_k,  cudaFuncAttributeMaxDynamicSharedMemorySize, 77312);

    dim3 gD((D_+63)/64, M_/128), gF((FFN_+63)/64, M_/128);
    dim3 gG4((G4_+63)/64, M_/128), gP((POSE_+63)/64, M_/128);

#define PACKA(src, KP) packa_k<<<((M_*(KP))+255)/256,256>>>((src), AP, M_*(KP))
#define PACKW(src, KP, N) packw_k<<<(((KP)*(N))+255)/256,256>>>((src), WP, (KP), (N))

    // encoder (pre-packed split-bf16 tensor-core GEMMs)
    PACKA(src_seq, 219); PACKW(emb_W, 219, D_);
    gemmp_k<EPI_POS><<<gD,256>>>(AP, 219, WP, X, D_, emb_b, nullptr, pos_t, src_pos);
    PACKA(X, 400);
    PACKW(Wq, 400, D_);
    gemmp_k<EPI_NONE><<<gD,256>>>(AP, 400, WP, Qb, D_, nullptr, nullptr, nullptr, nullptr);
    PACKW(Wk, 400, D_);
    gemmp_k<EPI_NONE><<<gD,256>>>(AP, 400, WP, Kb, D_, nullptr, nullptr, nullptr, nullptr);
    PACKW(Wv, 400, D_);
    gemmp_k<EPI_NONE><<<gD,256>>>(AP, 400, WP, Vb, D_, nullptr, nullptr, nullptr, nullptr);
    attn_k<<<dim3(S_/QT_, H_, B_),128,KSPAN_*KROW_*4>>>(Qb, Kb, Vb, Ob);
    PACKA(Ob, 400); PACKW(Wo, 400, D_);
    gemmp_k<EPI_ADD><<<gD,256>>>(AP, 400, WP, R1, D_, nullptr, X, nullptr, nullptr);
    ln_k<<<M_,256>>>(R1, X2, ln1g, ln1b);
    PACKA(X2, 400); PACKW(fW1, 400, FFN_);
    gemmp_k<EPI_BIAS_RELU><<<gF,256>>>(AP, 400, WP, H1, FFN_, fb1, nullptr, nullptr, nullptr);
    PACKA(H1, 512); PACKW(fW2, 512, D_);
    gemmp_k<EPI_BIAS_ADD><<<gD,256>>>(AP, 512, WP, T2, D_, fb2, X2, nullptr, nullptr);
    ln_k<<<M_,256>>>(T2, ENC, ln2g, ln2b);

    // decoder precompute
    PACKA(tgt_seq, 137); PACKW(lWx, 137, G4_);
    gemmp_k<EPI_NONE><<<gG4,256>>>(AP, 137, WP, XWX, G4_, nullptr, nullptr, nullptr, nullptr);
    PACKA(ENC, 400); PACKW(outW + (size_t)HID_*POSE_, 400, POSE_);
    gemmp_k<EPI_BIAS><<<gP,256>>>(AP, 400, WP, ENCP, POSE_, outb, nullptr, nullptr, nullptr);

    pack_whb_k<<<(GATEB_*4*64*32+255)/256,256>>>(lWh, WHB);
    pack_wxb_k<<<(GATEB_*4*18*32+255)/256,256>>>(lWx, WXB);
    pack_owb_k<<<(OGRP_*64*32+255)/256,256>>>(outW, OWB);
    init_dec_k<<<(HBTOT_+255)/256,256>>>(vec_h, HB);

    dec_k<<<NBD_,512,77312>>>(WHB, WXB, OWB, lb, XWX, ENCP, vec_c, dec0, HB, out, ep);
#undef PACKA
#undef PACKW
}

// round 13
// speedup vs baseline: 1.4379x; 1.0265x over previous
#include <cuda_runtime.h>
#include <cuda_bf16.h>
#include <math.h>

#define B_ 16
#define S_ 512
#define FRAME_ 438
#define D_ 800
#define H_ 8
#define DH_ 100
#define FFN_ 1024
#define HID_ 1024
#define POSE_ 274
#define WIN_ 100
#define M_ (B_*S_)
#define G4_ (4*HID_)
#define QT_ 8
#define KSPAN_ (2*WIN_+QT_)
#define KROW_ 101
#define NGB_ 32
#define NOB_ 5
#define NBD_ (NGB_+NOB_)
#define HBW_ 516
#define HBTOT_ (16*HBW_)
#define XBW_ 148
#define OGRP_ 35
#define GATEB_ 128
#define GSTAGE_ (128*17 + 16*65)   // uint2 per gemm pipeline stage

__device__ float g_x[M_*D_];
__device__ float g_q[M_*D_];
__device__ float g_k[M_*D_];
__device__ float g_v[M_*D_];
__device__ float g_o[M_*D_];
__device__ float g_r1[M_*D_];
__device__ float g_x2[M_*D_];
__device__ float g_h1[M_*FFN_];
__device__ float g_t2[M_*D_];
__device__ float g_enc[M_*D_];
__device__ float g_xwx[(size_t)M_*G4_];
__device__ float g_encp[M_*POSE_];
__device__ __align__(16) unsigned g_hb[4*HBTOT_];
__device__ __align__(16) uint2 g_whb[(size_t)GATEB_*4*64*32];
__device__ __align__(16) uint2 g_wxb[(size_t)GATEB_*4*18*32];
__device__ __align__(16) uint2 g_owb[(size_t)OGRP_*64*32];
__device__ uint2 g_ap[(size_t)M_*512];
__device__ uint2 g_wp[600000];
__device__ unsigned g_cnt;
__device__ unsigned g_ocnt;

enum { EPI_NONE=0, EPI_POS=1, EPI_ADD=2, EPI_BIAS_RELU=3, EPI_BIAS_ADD=4, EPI_BIAS=5 };

__device__ __forceinline__ unsigned packbf(float a, float b) {
    __nv_bfloat162 t = __float22bfloat162_rn(make_float2(a, b));
    return *(unsigned*)&t;
}
__device__ __forceinline__ float bfres(float x, float& hi) {
    __nv_bfloat16 h = __float2bfloat16_rn(x);
    hi = __bfloat162float(h);
    return x - hi;
}
__device__ __forceinline__ void mma_bf16(float* d, const unsigned* a, const unsigned* b) {
    asm volatile("mma.sync.aligned.m16n8k16.row.col.f32.bf16.bf16.f32 "
        "{%0,%1,%2,%3}, {%4,%5,%6,%7}, {%8,%9}, {%0,%1,%2,%3};"
        : "+f"(d[0]), "+f"(d[1]), "+f"(d[2]), "+f"(d[3])
        : "r"(a[0]), "r"(a[1]), "r"(a[2]), "r"(a[3]), "r"(b[0]), "r"(b[1]));
}

// ---------------- split-bf16 pre-pack kernels ----------------
__global__ void packa_k(const float* __restrict__ A, uint2* __restrict__ out, int npairs)
{
    int i = blockIdx.x*256 + threadIdx.x;
    if (i < npairs) {
        float2 v = ((const float2*)A)[i];
        float h0, h1;
        float l0 = bfres(v.x, h0), l1 = bfres(v.y, h1);
        out[i] = make_uint2(packbf(h0, h1), packbf(l0, l1));
    }
}
__global__ void packw_k(const float* __restrict__ W, uint2* __restrict__ out, int KP, int Nn)
{
    int i = blockIdx.x*256 + threadIdx.x;
    if (i < KP*Nn) {
        int kp = i / Nn, n = i % Nn;
        float w0 = W[(size_t)(2*kp)*Nn + n];
        float w1 = W[(size_t)(2*kp+1)*Nn + n];
        float h0, h1;
        float l0 = bfres(w0, h0), l1 = bfres(w1, h1);
        out[i] = make_uint2(packbf(h0, h1), packbf(l0, l1));
    }
}

// ---------------- packed split-bf16 GEMM, 2-stage cp.async pipeline ----------------
template<int EPI>
__global__ __launch_bounds__(256)
void gemmp_k(const uint2* __restrict__ Ap, int KP,
             const uint2* __restrict__ Wp,
             float* __restrict__ C, int Nn,
             const float* __restrict__ bias, const float* __restrict__ addend,
             const float* __restrict__ pos_table, const int* __restrict__ pos_idx)
{
    extern __shared__ uint2 sm2[];
    int tid = threadIdx.x, lane = tid & 31, w = tid >> 5;
    int wm = w >> 1, wn = w & 1;
    int rowBase = blockIdx.y * 128, colBase = blockIdx.x * 64;
    int tg = lane & 3, qd = lane >> 2;
    int ntiles = (KP + 15) >> 4;

    float d[2][4][4];
#pragma unroll
    for (int mt = 0; mt < 2; mt++)
#pragma unroll
        for (int nt = 0; nt < 4; nt++)
#pragma unroll
            for (int i = 0; i < 4; i++) d[mt][nt][i] = 0.f;

    auto issue = [&](int ti, int s) {
        uint2* As = sm2 + s*GSTAGE_;
        uint2* Ws = As + 128*17;
        int k0p = ti*16;
#pragma unroll
        for (int ii = 0; ii < 8; ii++) {
            int i = ii*256 + tid;
            int row = i >> 4, kw = i & 15, gkp = k0p + kw;
            uint2* dst = &As[row*17 + kw];
            if (gkp < KP) {
                unsigned da = (unsigned)__cvta_generic_to_shared(dst);
                asm volatile("cp.async.ca.shared.global [%0], [%1], 8;"
                             :: "r"(da), "l"(&Ap[(size_t)(rowBase+row)*KP + gkp]));
            } else *dst = make_uint2(0u, 0u);
        }
#pragma unroll
        for (int ii = 0; ii < 4; ii++) {
            int i = ii*256 + tid;
            int n = i & 63, kw = i >> 6;
            int gkp = k0p + kw, gn = colBase + n;
            uint2* dst = &Ws[kw*65 + n];
            if (gkp < KP && gn < Nn) {
                unsigned da = (unsigned)__cvta_generic_to_shared(dst);
                asm volatile("cp.async.ca.shared.global [%0], [%1], 8;"
                             :: "r"(da), "l"(&Wp[(size_t)gkp*Nn + gn]));
            } else *dst = make_uint2(0u, 0u);
        }
        asm volatile("cp.async.commit_group;");
    };

    issue(0, 0);
    for (int ti = 0; ti < ntiles; ti++) {
        if (ti + 1 < ntiles) {
            issue(ti+1, (ti+1) & 1);
            asm volatile("cp.async.wait_group 1;");
        } else {
            asm volatile("cp.async.wait_group 0;");
        }
        __syncthreads();
        uint2* Asm = sm2 + (ti & 1)*GSTAGE_;
        uint2* Wsm = Asm + 128*17;
#pragma unroll
        for (int kt = 0; kt < 2; kt++) {
            unsigned ah[2][4], al[2][4], bh[4][2], bl[4][2];
#pragma unroll
            for (int mt = 0; mt < 2; mt++) {
                int base = (wm*32 + mt*16 + qd)*17 + kt*8 + tg;
                uint2 q0 = Asm[base],     q1 = Asm[base + 8*17];
                uint2 q2 = Asm[base + 4], q3 = Asm[base + 8*17 + 4];
                ah[mt][0]=q0.x; ah[mt][1]=q1.x; ah[mt][2]=q2.x; ah[mt][3]=q3.x;
                al[mt][0]=q0.y; al[mt][1]=q1.y; al[mt][2]=q2.y; al[mt][3]=q3.y;
            }
#pragma unroll
            for (int nt = 0; nt < 4; nt++) {
                int nn = wn*32 + nt*8 + qd;
                int kb = kt*8 + tg;
                uint2 q0 = Wsm[kb*65 + nn], q1 = Wsm[(kb+4)*65 + nn];
                bh[nt][0]=q0.x; bh[nt][1]=q1.x;
                bl[nt][0]=q0.y; bl[nt][1]=q1.y;
            }
#pragma unroll
            for (int mt = 0; mt < 2; mt++)
#pragma unroll
                for (int nt = 0; nt < 4; nt++) {
                    mma_bf16(d[mt][nt], ah[mt], bh[nt]);
                    mma_bf16(d[mt][nt], ah[mt], bl[nt]);
                    mma_bf16(d[mt][nt], al[mt], bh[nt]);
                }
        }
        __syncthreads();
    }

#pragma unroll
    for (int mt = 0; mt < 2; mt++) {
#pragma unroll
        for (int nt = 0; nt < 4; nt++) {
#pragma unroll
            for (int half = 0; half < 2; half++) {
                int row = rowBase + wm*32 + mt*16 + qd + half*8;
                int col = colBase + wn*32 + nt*8 + tg*2;
                if (col < Nn) {
                    float v0 = d[mt][nt][half*2+0];
                    float v1 = d[mt][nt][half*2+1];
                    if (EPI == EPI_POS) {
                        size_t pb = (size_t)pos_idx[row]*Nn + col;
                        v0 += bias[col]   + pos_table[pb];
                        v1 += bias[col+1] + pos_table[pb+1];
                    } else if (EPI == EPI_ADD) {
                        size_t ab = (size_t)row*Nn + col;
                        v0 += addend[ab]; v1 += addend[ab+1];
                    } else if (EPI == EPI_BIAS_RELU) {
                        v0 += bias[col]; v1 += bias[col+1];
                        v0 = v0 > 0.f ? v0 : 0.f; v1 = v1 > 0.f ? v1 : 0.f;
                    } else if (EPI == EPI_BIAS_ADD) {
                        size_t ab = (size_t)row*Nn + col;
                        v0 += bias[col] + addend[ab]; v1 += bias[col+1] + addend[ab+1];
                    } else if (EPI == EPI_BIAS) {
                        v0 += bias[col]; v1 += bias[col+1];
                    }
                    *(float2*)(C + (size_t)row*Nn + col) = make_float2(v0, v1);
                }
            }
        }
    }
}

__global__ __launch_bounds__(256)
void ln_k(const float* __restrict__ in, float* __restrict__ out,
          const float* __restrict__ g, const float* __restrict__ b)
{
    __shared__ float buf[D_];
    __shared__ float red[256];
    int row = blockIdx.x, tid = threadIdx.x;
    float s = 0.f;
    for (int i = tid; i < D_; i += 256) { float v = in[(size_t)row*D_ + i]; buf[i] = v; s += v; }
    red[tid] = s; __syncthreads();
    for (int st = 128; st > 0; st >>= 1) { if (tid < st) red[tid] += red[tid+st]; __syncthreads(); }
    float mean = red[0] / (float)D_;
    __syncthreads();
    float ss = 0.f;
    for (int i = tid; i < D_; i += 256) { float dd = buf[i]-mean; ss += dd*dd; }
    red[tid] = ss; __syncthreads();
    for (int st = 128; st > 0; st >>= 1) { if (tid < st) red[tid] += red[tid+st]; __syncthreads(); }
    float inv = rsqrtf(red[0]/(float)D_ + 1e-6f);
    for (int i = tid; i < D_; i += 256)
        out[(size_t)row*D_ + i] = (buf[i]-mean)*inv*g[i] + b[i];
}

__global__ __launch_bounds__(128)
void attn_k(const float* __restrict__ Q, const float* __restrict__ K,
            const float* __restrict__ V, float* __restrict__ O)
{
    extern __shared__ float ks[];
    __shared__ float qs[QT_*DH_];
    __shared__ float sc[QT_][KSPAN_];
    __shared__ float invs[QT_];
    int tid = threadIdx.x;
    int q0 = blockIdx.x * QT_, h = blockIdx.y, b = blockIdx.z;
    int kl = max(0, q0 - WIN_);
    int kh = min(S_-1, q0 + QT_-1 + WIN_);
    int nk = kh - kl + 1;
    size_t base = ((size_t)b*S_)*D_ + (size_t)h*DH_;

    for (int idx = tid; idx < QT_*DH_; idx += 128) {
        int qi = idx / DH_, dd = idx % DH_;
        qs[idx] = Q[base + (size_t)(q0+qi)*D_ + dd];
    }
    for (int idx = tid; idx < nk*DH_; idx += 128) {
        int kk = idx / DH_, dd = idx % DH_;
        ks[kk*KROW_ + dd] = K[base + (size_t)(kl+kk)*D_ + dd];
    }
    __syncthreads();

    for (int pid = tid; pid < QT_*nk; pid += 128) {
        int kk = pid % nk, qi = pid / nk;
        int qq = q0 + qi, kp = kl + kk;
        float v;
        if (kp >= qq - WIN_ && kp <= qq + WIN_) {
            float dd = 0.f;
            for (int i = 0; i < DH_; i++) dd += qs[qi*DH_ + i]*ks[kk*KROW_ + i];
            v = dd * 0.1f;
        } else v = -1e30f;
        sc[qi][kk] = v;
    }
    __syncthreads();
    {
        int qi = tid >> 4, l = tid & 15;
        float m = -1e30f;
        for (int kk = l; kk < nk; kk += 16) m = fmaxf(m, sc[qi][kk]);
#pragma unroll
        for (int s2 = 8; s2 > 0; s2 >>= 1) m = fmaxf(m, __shfl_xor_sync(0xffffffffu, m, s2, 16));
        float ssum = 0.f;
        for (int kk = l; kk < nk; kk += 16) { float e = expf(sc[qi][kk]-m); sc[qi][kk] = e; ssum += e; }
#pragma unroll
        for (int s2 = 8; s2 > 0; s2 >>= 1) ssum += __shfl_xor_sync(0xffffffffu, ssum, s2, 16);
        if (l == 0) invs[qi] = 1.f / ssum;
    }
    __syncthreads();
    if (tid < DH_) {
        float acc[QT_];
#pragma unroll
        for (int qi = 0; qi < QT_; qi++) acc[qi] = 0.f;
        for (int kk = 0; kk < nk; kk++) {
            float vv = V[base + (size_t)(kl+kk)*D_ + tid];
#pragma unroll
            for (int qi = 0; qi < QT_; qi++) acc[qi] += sc[qi][kk]*vv;
        }
#pragma unroll
        for (int qi = 0; qi < QT_; qi++)
            O[base + (size_t)(q0+qi)*D_ + tid] = acc[qi]*invs[qi];
    }
}

// ---------------- decoder pack kernels: paired-kt (uint4-friendly) layout ----------------
__global__ void pack_whb_k(const float* __restrict__ Wh, uint2* __restrict__ out)
{
    size_t idx = (size_t)blockIdx.x*256 + threadIdx.x;
    if (idx >= (size_t)GATEB_*4*64*32) return;
    int lane = idx & 31;
    int kt = (idx >> 5) & 63;
    int q  = (idx >> 11) & 3;
    int g  = idx >> 13;
    int j  = q*1024 + g*8 + (lane >> 2);
    int k0 = kt*16 + (lane & 3)*2;
    float w0 = Wh[(size_t)k0*G4_ + j],     w1 = Wh[(size_t)(k0+1)*G4_ + j];
    float w2 = Wh[(size_t)(k0+8)*G4_ + j], w3 = Wh[(size_t)(k0+9)*G4_ + j];
    size_t o = ((((size_t)g*4 + q)*32 + (kt>>1))*32 + lane)*2 + (kt & 1);
    out[o] = make_uint2(packbf(w0,w1), packbf(w2,w3));
}

__global__ void pack_wxb_k(const float* __restrict__ Wx, uint2* __restrict__ out)
{
    size_t idx = (size_t)blockIdx.x*256 + threadIdx.x;
    if (idx >= (size_t)GATEB_*4*18*32) return;
    int lane = idx & 31;
    size_t r = idx >> 5;
    int kt = r % 18;
    int q  = (r / 18) & 3;
    int g  = r / 72;
    int j  = q*1024 + g*8 + (lane >> 2);
    int k0 = kt*16 + (lane & 3)*2;
    float w0 = (k0   < POSE_) ? Wx[(size_t)k0*G4_ + j]     : 0.f;
    float w1 = (k0+1 < POSE_) ? Wx[(size_t)(k0+1)*G4_ + j] : 0.f;
    float w2 = (k0+8 < POSE_) ? Wx[(size_t)(k0+8)*G4_ + j] : 0.f;
    float w3 = (k0+9 < POSE_) ? Wx[(size_t)(k0+9)*G4_ + j] : 0.f;
    size_t o = ((((size_t)g*4 + q)*9 + (kt>>1))*32 + lane)*2 + (kt & 1);
    out[o] = make_uint2(packbf(w0,w1), packbf(w2,w3));
}

__global__ void pack_owb_k(const float* __restrict__ Wo, uint2* __restrict__ out)
{
    int idx = blockIdx.x*256 + threadIdx.x;
    if (idx >= OGRP_*64*32) return;
    int lane = idx & 31;
    int kt = (idx >> 5) & 63;
    int grp = idx >> 11;
    int n  = grp*8 + (lane >> 2);
    int k0 = kt*16 + (lane & 3)*2;
    float w0=0.f, w1=0.f, w2=0.f, w3=0.f;
    if (n < POSE_) {
        w0 = Wo[(size_t)k0*POSE_ + n];     w1 = Wo[(size_t)(k0+1)*POSE_ + n];
        w2 = Wo[(size_t)(k0+8)*POSE_ + n]; w3 = Wo[(size_t)(k0+9)*POSE_ + n];
    }
    size_t o = (((size_t)grp*32 + (kt>>1))*32 + lane)*2 + (kt & 1);
    out[o] = make_uint2(packbf(w0,w1), packbf(w2,w3));
}

__global__ void init_dec_k(const float* __restrict__ vh, unsigned* __restrict__ hb)
{
    int i = blockIdx.x*256 + threadIdx.x;
    if (i == 0) { g_cnt = 0; g_ocnt = 0; }
    if (i < HBTOT_) {
        int b = i / HBW_, kw = i % HBW_;
        int k0 = kw*2;
        float v0 = (k0   < HID_) ? vh[b*HID_ + k0]   : 0.f;
        float v1 = (k0+1 < HID_) ? vh[b*HID_ + k0+1] : 0.f;
        hb[3*HBTOT_ + i] = packbf(v0, v1);
    }
}

__device__ __forceinline__ float sigf(float x){ return 1.f/(1.f+expf(-x)); }

__device__ __forceinline__ unsigned ld_acq(const unsigned* p) {
    unsigned v;
    asm volatile("ld.acquire.gpu.global.u32 %0, [%1];" : "=r"(v) : "l"(p) : "memory");
    return v;
}
__device__ __forceinline__ void red_rel(unsigned* p) {
    asm volatile("red.release.gpu.global.add.u32 [%0], 1;" :: "l"(p) : "memory");
}

// grid = 37 x 512. Blocks 0..31: gates (32 units each). 32..36: out-proj.
__global__ __launch_bounds__(512)
void dec_k(const uint2* __restrict__ WHB, const uint2* __restrict__ WXB,
           const uint2* __restrict__ OWB, const float* __restrict__ lb,
           const float* __restrict__ xwx, const float* __restrict__ encp,
           const float* __restrict__ vec_c, const float* __restrict__ dec0,
           unsigned* __restrict__ hb, float* __restrict__ outbuf,
           const int* __restrict__ ep)
{
    extern __shared__ unsigned smu[];
    unsigned* hbs = smu;
    unsigned* xbs = smu + HBTOT_;
    float*    red = (float*)(smu + HBTOT_ + 16*XBW_);
    float*    hso = red + 8192;

    int tid = threadIdx.x, bx = blockIdx.x;
    int lane = tid & 31, w = tid >> 5;
    int b = lane >> 2, tg = lane & 3;
    bool isGate = bx < NGB_;
    int p = (int)((double)(*ep) * 0.01);   // double required: fp32 100*0.01 -> 0
    int per = p + 10;
    const uint4* WHB4 = (const uint4*)WHB;
    const uint4* WXB4 = (const uint4*)WXB;
    const uint4* OWB4 = (const uint4*)OWB;

#define HBS_COPY(hrp) { \
        const uint4* srcv = (const uint4*)(hrp); uint4* dstv = (uint4*)hbs; \
        for (int i = tid; i < HBTOT_/4; i += 512) dstv[i] = __ldcg(srcv + i); }

#define A_LOAD2(buf, stride, ktv) { \
        int wA = b*(stride) + (ktv)*8 + tg; \
        a0[0] = (buf)[wA];     a0[1] = (buf)[wA + 8*(stride)]; \
        a0[2] = (buf)[wA + 4]; a0[3] = (buf)[wA + 8*(stride) + 4]; \
        wA += 8; \
        a1[0] = (buf)[wA];     a1[1] = (buf)[wA + 8*(stride)]; \
        a1[2] = (buf)[wA + 4]; a1[3] = (buf)[wA + 8*(stride) + 4]; }

    if (isGate) {
        int ug = w >> 2, ksx = w & 3;
        int gidx = bx*4 + ug;
        int u3 = tid >> 4, b3 = tid & 15;
        int gu = bx*32 + u3;
        float c = vec_c[b3*HID_ + gu];
        int lane2 = (b3 & 7)*4 + ((u3 & 7) >> 1);
        int i2 = (b3 >> 3)*2 + (u3 & 1);
        int wbase = (u3 >> 3)*4;

        for (int t = 0; t < S_; t++) {
            bool sampled = (t % per) < p;
            const unsigned* hr = hb + ((t+3)&3)*(size_t)HBTOT_;
            unsigned*       hw = hb + (t&3)*(size_t)HBTOT_;

            float xwr[4];
            if (!sampled) {
#pragma unroll
                for (int q = 0; q < 4; q++)
                    xwr[q] = __ldcg(xwx + ((size_t)b3*S_ + t)*G4_ + q*1024 + gu);
            }

            unsigned needO = 0;
            if (sampled) needO = (unsigned)(NOB_*t);
            else if (t >= 4) needO = (unsigned)(NOB_*(t-3));
            if (tid == 0 && t > 0) {
                unsigned needH = (unsigned)(NGB_*t);
                while (ld_acq(&g_cnt) < needH) ;
            }
            if (tid == 32 && needO) {
                while (ld_acq(&g_ocnt) < needO) ;
            }
            __syncthreads();

            HBS_COPY(hr);
            if (sampled) {
                const float* xsrc0 = (t == 0) ? dec0 : (outbuf + (size_t)(t-1)*POSE_);
                size_t bstride = (t == 0) ? (size_t)POSE_ : (size_t)S_*POSE_;
                for (int i = tid; i < 16*(XBW_-4); i += 512) {
                    int b2 = i / (XBW_-4), kw = i % (XBW_-4);
                    int k0 = kw*2;
                    const float* sp = xsrc0 + (size_t)b2*bstride;
                    float v0 = (k0   < POSE_) ? __ldcg(sp + k0)   : 0.f;
                    float v1 = (k0+1 < POSE_) ? __ldcg(sp + k0+1) : 0.f;
                    xbs[b2*XBW_ + kw] = packbf(v0, v1);
                }
            }
            __syncthreads();

            float d[4][4];
#pragma unroll
            for (int q = 0; q < 4; q++)
#pragma unroll
                for (int i = 0; i < 4; i++) d[q][i] = 0.f;
            unsigned a0[4], a1[4];
#pragma unroll 2
            for (int kt8 = 0; kt8 < 8; kt8++) {
                int kt2 = ksx*8 + kt8;
                A_LOAD2(hbs, HBW_, kt2*2);
#pragma unroll
                for (int q = 0; q < 4; q++) {
                    uint4 bb = WHB4[(((size_t)gidx*4 + q)*32 + kt2)*32 + lane];
                    unsigned be[2] = {bb.x, bb.y}, bo[2] = {bb.z, bb.w};
                    mma_bf16(d[q], a0, be);
                    mma_bf16(d[q], a1, bo);
                }
            }
            if (sampled) {
                int e2 = min(9, ksx*3 + 3);
                for (int kt2 = ksx*3; kt2 < e2; kt2++) {
                    A_LOAD2(xbs, XBW_, kt2*2);
#pragma unroll
                    for (int q = 0; q < 4; q++) {
                        uint4 bb = WXB4[(((size_t)gidx*4 + q)*9 + kt2)*32 + lane];
                        unsigned be[2] = {bb.x, bb.y}, bo[2] = {bb.z, bb.w};
                        mma_bf16(d[q], a0, be);
                        mma_bf16(d[q], a1, bo);
                    }
                }
            }
            {
                float* myr = red + (w*32 + lane)*16;
#pragma unroll
                for (int q = 0; q < 4; q++)
#pragma unroll
                    for (int i = 0; i < 4; i++) myr[q*4+i] = d[q][i];
            }
            __syncthreads();

            {
                float gate[4];
#pragma unroll
                for (int q = 0; q < 4; q++) {
                    float s = 0.f;
#pragma unroll
                    for (int ks2 = 0; ks2 < 4; ks2++)
                        s += red[((wbase + ks2)*32 + lane2)*16 + q*4 + i2];
                    s += lb[q*1024 + gu];
                    if (!sampled) s += xwr[q];
                    gate[q] = s;
                }
                float cv = sigf(gate[1])*c + sigf(gate[0])*tanhf(gate[2]);
                float h = sigf(gate[3])*tanhf(cv);
                c = cv;
                hso[u3*16 + b3] = h;
            }
            __syncthreads();
            if (tid < 256) {
                int kwu = tid >> 4, bb2 = tid & 15;
                hw[bb2*HBW_ + bx*16 + kwu] =
                    packbf(hso[(2*kwu)*16 + bb2], hso[(2*kwu+1)*16 + bb2]);
            }
            __syncthreads();
            if (tid == 0) red_rel(&g_cnt);
        }
    } else {
        int ob = bx - NGB_;
        int grpi = w >> 1, kh = w & 1;
        int grp = ob*8 + grpi;
        bool ovalid = (grp < OGRP_);
        for (int t = 0; t < S_; t++) {
            if (tid == 0) {
                unsigned needH = (unsigned)(NGB_*(t+1));
                while (ld_acq(&g_cnt) < needH) ;
            }
            __syncthreads();
            const unsigned* hrp = hb + (t&3)*(size_t)HBTOT_;
            HBS_COPY(hrp);
            __syncthreads();
            float d[4] = {0.f,0.f,0.f,0.f};
            unsigned a0[4], a1[4];
            if (ovalid) {
#pragma unroll 2
                for (int kt16 = 0; kt16 < 16; kt16++) {
                    int kt2 = kh*16 + kt16;
                    A_LOAD2(hbs, HBW_, kt2*2);
                    uint4 bb = OWB4[((size_t)grp*32 + kt2)*32 + lane];
                    unsigned be[2] = {bb.x, bb.y}, bo[2] = {bb.z, bb.w};
                    mma_bf16(d, a0, be);
                    mma_bf16(d, a1, bo);
                }
            }
            float* myr = red + (w*32 + lane)*4;
            myr[0]=d[0]; myr[1]=d[1]; myr[2]=d[2]; myr[3]=d[3];
            __syncthreads();
            if ((w & 1) == 0 && ovalid) {
                float s0 = red[(w*32+lane)*4+0] + red[((w+1)*32+lane)*4+0];
                float s1 = red[(w*32+lane)*4+1] + red[((w+1)*32+lane)*4+1];
                float s2 = red[(w*32+lane)*4+2] + red[((w+1)*32+lane)*4+2];
                float s3 = red[(w*32+lane)*4+3] + red[((w+1)*32+lane)*4+3];
                int n0 = grp*8 + tg*2;
                if (n0 + 1 < POSE_) {
                    size_t o0 = ((size_t)b*S_ + t)*POSE_ + n0;
                    size_t o1 = ((size_t)(b+8)*S_ + t)*POSE_ + n0;
                    float2 e0 = *(const float2*)(encp + o0);
                    float2 e1 = *(const float2*)(encp + o1);
                    *(float2*)(outbuf + o0) = make_float2(s0 + e0.x, s1 + e0.y);
                    *(float2*)(outbuf + o1) = make_float2(s2 + e1.x, s3 + e1.y);
                }
            }
            __syncthreads();
            if (tid == 0) red_rel(&g_ocnt);
        }
    }
#undef A_LOAD2
#undef HBS_COPY
}

extern "C" void kernel_launch(void* const* d_in, const int* in_sizes, int n_in,
                              void* d_out, int out_size)
{
    (void)in_sizes; (void)n_in; (void)out_size;
    const float* src_seq = (const float*)d_in[0];
    const int*   src_pos = (const int*)  d_in[1];
    const float* tgt_seq = (const float*)d_in[2];
    const float* vec_h   = (const float*)d_in[3];
    const float* vec_c   = (const float*)d_in[4];
    const float* dec0    = (const float*)d_in[5];
    const float* emb_W   = (const float*)d_in[6];
    const float* emb_b   = (const float*)d_in[7];
    const float* pos_t   = (const float*)d_in[8];
    const float* Wq      = (const float*)d_in[9];
    const float* Wk      = (const float*)d_in[10];
    const float* Wv      = (const float*)d_in[11];
    const float* Wo      = (const float*)d_in[12];
    const float* ln1g    = (const float*)d_in[13];
    const float* ln1b    = (const float*)d_in[14];
    const float* fW1     = (const float*)d_in[15];
    const float* fb1     = (const float*)d_in[16];
    const float* fW2     = (const float*)d_in[17];
    const float* fb2     = (const float*)d_in[18];
    const float* ln2g    = (const float*)d_in[19];
    const float* ln2b    = (const float*)d_in[20];
    const float* lWx     = (const float*)d_in[21];
    const float* lWh     = (const float*)d_in[22];
    const float* lb      = (const float*)d_in[23];
    const float* outW    = (const float*)d_in[24];
    const float* outb    = (const float*)d_in[25];
    const int*   ep      = (const int*)  d_in[26];
    float* out = (float*)d_out;

    void *px,*pq,*pk,*pv,*po,*pr1,*px2,*ph1,*pt2,*penc,*pxwx,*pencp,*phb,*pwhb,*pwxb,*powb,*pap,*pwp;
    cudaGetSymbolAddress(&px,  g_x);   cudaGetSymbolAddress(&pq,  g_q);
    cudaGetSymbolAddress(&pk,  g_k);   cudaGetSymbolAddress(&pv,  g_v);
    cudaGetSymbolAddress(&po,  g_o);   cudaGetSymbolAddress(&pr1, g_r1);
    cudaGetSymbolAddress(&px2, g_x2);  cudaGetSymbolAddress(&ph1, g_h1);
    cudaGetSymbolAddress(&pt2, g_t2);  cudaGetSymbolAddress(&penc,g_enc);
    cudaGetSymbolAddress(&pxwx,g_xwx); cudaGetSymbolAddress(&pencp,g_encp);
    cudaGetSymbolAddress(&phb, g_hb);  cudaGetSymbolAddress(&pwhb,g_whb);
    cudaGetSymbolAddress(&pwxb,g_wxb); cudaGetSymbolAddress(&powb,g_owb);
    cudaGetSymbolAddress(&pap, g_ap);  cudaGetSymbolAddress(&pwp, g_wp);
    float *X=(float*)px, *Qb=(float*)pq, *Kb=(float*)pk, *Vb=(float*)pv, *Ob=(float*)po;
    float *R1=(float*)pr1, *X2=(float*)px2, *H1=(float*)ph1, *T2=(float*)pt2, *ENC=(float*)penc;
    float *XWX=(float*)pxwx, *ENCP=(float*)pencp;
    unsigned *HB=(unsigned*)phb;
    uint2 *WHB=(uint2*)pwhb, *WXB=(uint2*)pwxb, *OWB=(uint2*)powb;
    uint2 *AP=(uint2*)pap, *WP=(uint2*)pwp;

    const int GSM = 2*GSTAGE_*8;   // 51456 B dynamic smem for gemmp
    cudaFuncSetAttribute(attn_k, cudaFuncAttributeMaxDynamicSharedMemorySize, KSPAN_*KROW_*4);
    cudaFuncSetAttribute(dec_k,  cudaFuncAttributeMaxDynamicSharedMemorySize, 77312);
    cudaFuncSetAttribute(gemmp_k<EPI_NONE>,      cudaFuncAttributeMaxDynamicSharedMemorySize, GSM);
    cudaFuncSetAttribute(gemmp_k<EPI_POS>,       cudaFuncAttributeMaxDynamicSharedMemorySize, GSM);
    cudaFuncSetAttribute(gemmp_k<EPI_ADD>,       cudaFuncAttributeMaxDynamicSharedMemorySize, GSM);
    cudaFuncSetAttribute(gemmp_k<EPI_BIAS_RELU>, cudaFuncAttributeMaxDynamicSharedMemorySize, GSM);
    cudaFuncSetAttribute(gemmp_k<EPI_BIAS_ADD>,  cudaFuncAttributeMaxDynamicSharedMemorySize, GSM);
    cudaFuncSetAttribute(gemmp_k<EPI_BIAS>,      cudaFuncAttributeMaxDynamicSharedMemorySize, GSM);

    dim3 gD((D_+63)/64, M_/128), gF((FFN_+63)/64, M_/128);
    dim3 gG4((G4_+63)/64, M_/128), gP((POSE_+63)/64, M_/128);

#define PACKA(src, KP) packa_k<<<((M_*(KP))+255)/256,256>>>((src), AP, M_*(KP))
#define PACKW(src, KP, N) packw_k<<<(((KP)*(N))+255)/256,256>>>((src), WP, (KP), (N))

    PACKA(src_seq, 219); PACKW(emb_W, 219, D_);
    gemmp_k<EPI_POS><<<gD,256,GSM>>>(AP, 219, WP, X, D_, emb_b, nullptr, pos_t, src_pos);
    PACKA(X, 400);
    PACKW(Wq, 400, D_);
    gemmp_k<EPI_NONE><<<gD,256,GSM>>>(AP, 400, WP, Qb, D_, nullptr, nullptr, nullptr, nullptr);
    PACKW(Wk, 400, D_);
    gemmp_k<EPI_NONE><<<gD,256,GSM>>>(AP, 400, WP, Kb, D_, nullptr, nullptr, nullptr, nullptr);
    PACKW(Wv, 400, D_);
    gemmp_k<EPI_NONE><<<gD,256,GSM>>>(AP, 400, WP, Vb, D_, nullptr, nullptr, nullptr, nullptr);
    attn_k<<<dim3(S_/QT_, H_, B_),128,KSPAN_*KROW_*4>>>(Qb, Kb, Vb, Ob);
    PACKA(Ob, 400); PACKW(Wo, 400, D_);
    gemmp_k<EPI_ADD><<<gD,256,GSM>>>(AP, 400, WP, R1, D_, nullptr, X, nullptr, nullptr);
    ln_k<<<M_,256>>>(R1, X2, ln1g, ln1b);
    PACKA(X2, 400); PACKW(fW1, 400, FFN_);
    gemmp_k<EPI_BIAS_RELU><<<gF,256,GSM>>>(AP, 400, WP, H1, FFN_, fb1, nullptr, nullptr, nullptr);
    PACKA(H1, 512); PACKW(fW2, 512, D_);
    gemmp_k<EPI_BIAS_ADD><<<gD,256,GSM>>>(AP, 512, WP, T2, D_, fb2, X2, nullptr, nullptr);
    ln_k<<<M_,256>>>(T2, ENC, ln2g, ln2b);

    PACKA(tgt_seq, 137); PACKW(lWx, 137, G4_);
    gemmp_k<EPI_NONE><<<gG4,256,GSM>>>(AP, 137, WP, XWX, G4_, nullptr, nullptr, nullptr, nullptr);
    PACKA(ENC, 400); PACKW(outW + (size_t)HID_*POSE_, 400, POSE_);
    gemmp_k<EPI_BIAS><<<gP,256,GSM>>>(AP, 400, WP, ENCP, POSE_, outb, nullptr, nullptr, nullptr);

    pack_whb_k<<<(GATEB_*4*64*32+255)/256,256>>>(lWh, WHB);
    pack_wxb_k<<<(GATEB_*4*18*32+255)/256,256>>>(lWx, WXB);
    pack_owb_k<<<(OGRP_*64*32+255)/256,256>>>(outW, OWB);
    init_dec_k<<<(HBTOT_+255)/256,256>>>(vec_h, HB);

    dec_k<<<NBD_,512,77312>>>(WHB, WXB, OWB, lb, XWX, ENCP, vec_c, dec0, HB, out, ep);
#undef PACKA
#undef PACKW
}

// round 14
// speedup vs baseline: 1.5323x; 1.0657x over previous
#include <cuda_runtime.h>
#include <cuda_bf16.h>
#include <math.h>

#define B_ 16
#define S_ 512
#define FRAME_ 438
#define D_ 800
#define H_ 8
#define DH_ 100
#define FFN_ 1024
#define HID_ 1024
#define POSE_ 274
#define WIN_ 100
#define M_ (B_*S_)
#define G4_ (4*HID_)
#define QT_ 8
#define KSPAN_ (2*WIN_+QT_)
#define KROW_ 101
#define GATEB_ 128
#define OUTB_ 18
#define NBDEC_ (GATEB_+OUTB_)
#define HBW_ 516
#define HBTOT_ (16*HBW_)
#define XBW_ 148
#define OGRP_ 35
#define GSTAGE_ (128*17 + 16*65)

__device__ float g_x[M_*D_];
__device__ float g_q[M_*D_];
__device__ float g_k[M_*D_];
__device__ float g_v[M_*D_];
__device__ float g_o[M_*D_];
__device__ float g_r1[M_*D_];
__device__ float g_x2[M_*D_];
__device__ float g_h1[M_*FFN_];
__device__ float g_t2[M_*D_];
__device__ float g_enc[M_*D_];
__device__ float g_xwx[(size_t)M_*G4_];
__device__ float g_encp[M_*POSE_];
__device__ __align__(16) unsigned g_hb[4*HBTOT_];
__device__ __align__(16) uint2 g_whb[(size_t)GATEB_*4*64*32];
__device__ __align__(16) uint2 g_wxb[(size_t)GATEB_*4*18*32];
__device__ __align__(16) uint2 g_owb[(size_t)OGRP_*64*32];
__device__ uint2 g_ap[(size_t)M_*512];
__device__ uint2 g_wp[600000];
__device__ unsigned g_hflag[GATEB_*8];   // one flag per gate block, 32B apart
__device__ unsigned g_oflag[OUTB_*8];    // one flag per out block

enum { EPI_NONE=0, EPI_POS=1, EPI_ADD=2, EPI_BIAS_RELU=3, EPI_BIAS_ADD=4, EPI_BIAS=5 };

__device__ __forceinline__ unsigned packbf(float a, float b) {
    __nv_bfloat162 t = __float22bfloat162_rn(make_float2(a, b));
    return *(unsigned*)&t;
}
__device__ __forceinline__ float bfres(float x, float& hi) {
    __nv_bfloat16 h = __float2bfloat16_rn(x);
    hi = __bfloat162float(h);
    return x - hi;
}
__device__ __forceinline__ void mma_bf16(float* d, const unsigned* a, const unsigned* b) {
    asm volatile("mma.sync.aligned.m16n8k16.row.col.f32.bf16.bf16.f32 "
        "{%0,%1,%2,%3}, {%4,%5,%6,%7}, {%8,%9}, {%0,%1,%2,%3};"
        : "+f"(d[0]), "+f"(d[1]), "+f"(d[2]), "+f"(d[3])
        : "r"(a[0]), "r"(a[1]), "r"(a[2]), "r"(a[3]), "r"(b[0]), "r"(b[1]));
}

// ---------------- split-bf16 pre-pack kernels ----------------
__global__ void packa_k(const float* __restrict__ A, uint2* __restrict__ out, int npairs)
{
    int i = blockIdx.x*256 + threadIdx.x;
    if (i < npairs) {
        float2 v = ((const float2*)A)[i];
        float h0, h1;
        float l0 = bfres(v.x, h0), l1 = bfres(v.y, h1);
        out[i] = make_uint2(packbf(h0, h1), packbf(l0, l1));
    }
}
__global__ void packw_k(const float* __restrict__ W, uint2* __restrict__ out, int KP, int Nn)
{
    int i = blockIdx.x*256 + threadIdx.x;
    if (i < KP*Nn) {
        int kp = i / Nn, n = i % Nn;
        float w0 = W[(size_t)(2*kp)*Nn + n];
        float w1 = W[(size_t)(2*kp+1)*Nn + n];
        float h0, h1;
        float l0 = bfres(w0, h0), l1 = bfres(w1, h1);
        out[i] = make_uint2(packbf(h0, h1), packbf(l0, l1));
    }
}

// ---------------- packed split-bf16 GEMM, 2-stage cp.async pipeline ----------------
template<int EPI>
__global__ __launch_bounds__(256)
void gemmp_k(const uint2* __restrict__ Ap, int KP,
             const uint2* __restrict__ Wp,
             float* __restrict__ C, int Nn,
             const float* __restrict__ bias, const float* __restrict__ addend,
             const float* __restrict__ pos_table, const int* __restrict__ pos_idx)
{
    extern __shared__ uint2 sm2[];
    int tid = threadIdx.x, lane = tid & 31, w = tid >> 5;
    int wm = w >> 1, wn = w & 1;
    int rowBase = blockIdx.y * 128, colBase = blockIdx.x * 64;
    int tg = lane & 3, qd = lane >> 2;
    int ntiles = (KP + 15) >> 4;

    float d[2][4][4];
#pragma unroll
    for (int mt = 0; mt < 2; mt++)
#pragma unroll
        for (int nt = 0; nt < 4; nt++)
#pragma unroll
            for (int i = 0; i < 4; i++) d[mt][nt][i] = 0.f;

    auto issue = [&](int ti, int s) {
        uint2* As = sm2 + s*GSTAGE_;
        uint2* Ws = As + 128*17;
        int k0p = ti*16;
#pragma unroll
        for (int ii = 0; ii < 8; ii++) {
            int i = ii*256 + tid;
            int row = i >> 4, kw = i & 15, gkp = k0p + kw;
            uint2* dst = &As[row*17 + kw];
            if (gkp < KP) {
                unsigned da = (unsigned)__cvta_generic_to_shared(dst);
                asm volatile("cp.async.ca.shared.global [%0], [%1], 8;"
                             :: "r"(da), "l"(&Ap[(size_t)(rowBase+row)*KP + gkp]));
            } else *dst = make_uint2(0u, 0u);
        }
#pragma unroll
        for (int ii = 0; ii < 4; ii++) {
            int i = ii*256 + tid;
            int n = i & 63, kw = i >> 6;
            int gkp = k0p + kw, gn = colBase + n;
            uint2* dst = &Ws[kw*65 + n];
            if (gkp < KP && gn < Nn) {
                unsigned da = (unsigned)__cvta_generic_to_shared(dst);
                asm volatile("cp.async.ca.shared.global [%0], [%1], 8;"
                             :: "r"(da), "l"(&Wp[(size_t)gkp*Nn + gn]));
            } else *dst = make_uint2(0u, 0u);
        }
        asm volatile("cp.async.commit_group;");
    };

    issue(0, 0);
    for (int ti = 0; ti < ntiles; ti++) {
        if (ti + 1 < ntiles) {
            issue(ti+1, (ti+1) & 1);
            asm volatile("cp.async.wait_group 1;");
        } else {
            asm volatile("cp.async.wait_group 0;");
        }
        __syncthreads();
        uint2* Asm = sm2 + (ti & 1)*GSTAGE_;
        uint2* Wsm = Asm + 128*17;
#pragma unroll
        for (int kt = 0; kt < 2; kt++) {
            unsigned ah[2][4], al[2][4], bh[4][2], bl[4][2];
#pragma unroll
            for (int mt = 0; mt < 2; mt++) {
                int base = (wm*32 + mt*16 + qd)*17 + kt*8 + tg;
                uint2 q0 = Asm[base],     q1 = Asm[base + 8*17];
                uint2 q2 = Asm[base + 4], q3 = Asm[base + 8*17 + 4];
                ah[mt][0]=q0.x; ah[mt][1]=q1.x; ah[mt][2]=q2.x; ah[mt][3]=q3.x;
                al[mt][0]=q0.y; al[mt][1]=q1.y; al[mt][2]=q2.y; al[mt][3]=q3.y;
            }
#pragma unroll
            for (int nt = 0; nt < 4; nt++) {
                int nn = wn*32 + nt*8 + qd;
                int kb = kt*8 + tg;
                uint2 q0 = Wsm[kb*65 + nn], q1 = Wsm[(kb+4)*65 + nn];
                bh[nt][0]=q0.x; bh[nt][1]=q1.x;
                bl[nt][0]=q0.y; bl[nt][1]=q1.y;
            }
#pragma unroll
            for (int mt = 0; mt < 2; mt++)
#pragma unroll
                for (int nt = 0; nt < 4; nt++) {
                    mma_bf16(d[mt][nt], ah[mt], bh[nt]);
                    mma_bf16(d[mt][nt], ah[mt], bl[nt]);
                    mma_bf16(d[mt][nt], al[mt], bh[nt]);
                }
        }
        __syncthreads();
    }

#pragma unroll
    for (int mt = 0; mt < 2; mt++) {
#pragma unroll
        for (int nt = 0; nt < 4; nt++) {
#pragma unroll
            for (int half = 0; half < 2; half++) {
                int row = rowBase + wm*32 + mt*16 + qd + half*8;
                int col = colBase + wn*32 + nt*8 + tg*2;
                if (col < Nn) {
                    float v0 = d[mt][nt][half*2+0];
                    float v1 = d[mt][nt][half*2+1];
                    if (EPI == EPI_POS) {
                        size_t pb = (size_t)pos_idx[row]*Nn + col;
                        v0 += bias[col]   + pos_table[pb];
                        v1 += bias[col+1] + pos_table[pb+1];
                    } else if (EPI == EPI_ADD) {
                        size_t ab = (size_t)row*Nn + col;
                        v0 += addend[ab]; v1 += addend[ab+1];
                    } else if (EPI == EPI_BIAS_RELU) {
                        v0 += bias[col]; v1 += bias[col+1];
                        v0 = v0 > 0.f ? v0 : 0.f; v1 = v1 > 0.f ? v1 : 0.f;
                    } else if (EPI == EPI_BIAS_ADD) {
                        size_t ab = (size_t)row*Nn + col;
                        v0 += bias[col] + addend[ab]; v1 += bias[col+1] + addend[ab+1];
                    } else if (EPI == EPI_BIAS) {
                        v0 += bias[col]; v1 += bias[col+1];
                    }
                    *(float2*)(C + (size_t)row*Nn + col) = make_float2(v0, v1);
                }
            }
        }
    }
}

__global__ __launch_bounds__(256)
void ln_k(const float* __restrict__ in, float* __restrict__ out,
          const float* __restrict__ g, const float* __restrict__ b)
{
    __shared__ float buf[D_];
    __shared__ float red[256];
    int row = blockIdx.x, tid = threadIdx.x;
    float s = 0.f;
    for (int i = tid; i < D_; i += 256) { float v = in[(size_t)row*D_ + i]; buf[i] = v; s += v; }
    red[tid] = s; __syncthreads();
    for (int st = 128; st > 0; st >>= 1) { if (tid < st) red[tid] += red[tid+st]; __syncthreads(); }
    float mean = red[0] / (float)D_;
    __syncthreads();
    float ss = 0.f;
    for (int i = tid; i < D_; i += 256) { float dd = buf[i]-mean; ss += dd*dd; }
    red[tid] = ss; __syncthreads();
    for (int st = 128; st > 0; st >>= 1) { if (tid < st) red[tid] += red[tid+st]; __syncthreads(); }
    float inv = rsqrtf(red[0]/(float)D_ + 1e-6f);
    for (int i = tid; i < D_; i += 256)
        out[(size_t)row*D_ + i] = (buf[i]-mean)*inv*g[i] + b[i];
}

__global__ __launch_bounds__(128)
void attn_k(const float* __restrict__ Q, const float* __restrict__ K,
            const float* __restrict__ V, float* __restrict__ O)
{
    extern __shared__ float ks[];
    __shared__ float qs[QT_*DH_];
    __shared__ float sc[QT_][KSPAN_];
    __shared__ float invs[QT_];
    int tid = threadIdx.x;
    int q0 = blockIdx.x * QT_, h = blockIdx.y, b = blockIdx.z;
    int kl = max(0, q0 - WIN_);
    int kh = min(S_-1, q0 + QT_-1 + WIN_);
    int nk = kh - kl + 1;
    size_t base = ((size_t)b*S_)*D_ + (size_t)h*DH_;

    for (int idx = tid; idx < QT_*DH_; idx += 128) {
        int qi = idx / DH_, dd = idx % DH_;
        qs[idx] = Q[base + (size_t)(q0+qi)*D_ + dd];
    }
    for (int idx = tid; idx < nk*DH_; idx += 128) {
        int kk = idx / DH_, dd = idx % DH_;
        ks[kk*KROW_ + dd] = K[base + (size_t)(kl+kk)*D_ + dd];
    }
    __syncthreads();

    for (int pid = tid; pid < QT_*nk; pid += 128) {
        int kk = pid % nk, qi = pid / nk;
        int qq = q0 + qi, kp = kl + kk;
        float v;
        if (kp >= qq - WIN_ && kp <= qq + WIN_) {
            float dd = 0.f;
            for (int i = 0; i < DH_; i++) dd += qs[qi*DH_ + i]*ks[kk*KROW_ + i];
            v = dd * 0.1f;
        } else v = -1e30f;
        sc[qi][kk] = v;
    }
    __syncthreads();
    {
        int qi = tid >> 4, l = tid & 15;
        float m = -1e30f;
        for (int kk = l; kk < nk; kk += 16) m = fmaxf(m, sc[qi][kk]);
#pragma unroll
        for (int s2 = 8; s2 > 0; s2 >>= 1) m = fmaxf(m, __shfl_xor_sync(0xffffffffu, m, s2, 16));
        float ssum = 0.f;
        for (int kk = l; kk < nk; kk += 16) { float e = expf(sc[qi][kk]-m); sc[qi][kk] = e; ssum += e; }
#pragma unroll
        for (int s2 = 8; s2 > 0; s2 >>= 1) ssum += __shfl_xor_sync(0xffffffffu, ssum, s2, 16);
        if (l == 0) invs[qi] = 1.f / ssum;
    }
    __syncthreads();
    if (tid < DH_) {
        float acc[QT_];
#pragma unroll
        for (int qi = 0; qi < QT_; qi++) acc[qi] = 0.f;
        for (int kk = 0; kk < nk; kk++) {
            float vv = V[base + (size_t)(kl+kk)*D_ + tid];
#pragma unroll
            for (int qi = 0; qi < QT_; qi++) acc[qi] += sc[qi][kk]*vv;
        }
#pragma unroll
        for (int qi = 0; qi < QT_; qi++)
            O[base + (size_t)(q0+qi)*D_ + tid] = acc[qi]*invs[qi];
    }
}

// ---------------- decoder pack kernels: paired-kt uint4 layout ----------------
__global__ void pack_whb_k(const float* __restrict__ Wh, uint2* __restrict__ out)
{
    size_t idx = (size_t)blockIdx.x*256 + threadIdx.x;
    if (idx >= (size_t)GATEB_*4*64*32) return;
    int lane = idx & 31;
    int kt = (idx >> 5) & 63;
    int q  = (idx >> 11) & 3;
    int g  = idx >> 13;
    int j  = q*1024 + g*8 + (lane >> 2);
    int k0 = kt*16 + (lane & 3)*2;
    float w0 = Wh[(size_t)k0*G4_ + j],     w1 = Wh[(size_t)(k0+1)*G4_ + j];
    float w2 = Wh[(size_t)(k0+8)*G4_ + j], w3 = Wh[(size_t)(k0+9)*G4_ + j];
    size_t o = ((((size_t)g*4 + q)*32 + (kt>>1))*32 + lane)*2 + (kt & 1);
    out[o] = make_uint2(packbf(w0,w1), packbf(w2,w3));
}

__global__ void pack_wxb_k(const float* __restrict__ Wx, uint2* __restrict__ out)
{
    size_t idx = (size_t)blockIdx.x*256 + threadIdx.x;
    if (idx >= (size_t)GATEB_*4*18*32) return;
    int lane = idx & 31;
    size_t r = idx >> 5;
    int kt = r % 18;
    int q  = (r / 18) & 3;
    int g  = r / 72;
    int j  = q*1024 + g*8 + (lane >> 2);
    int k0 = kt*16 + (lane & 3)*2;
    float w0 = (k0   < POSE_) ? Wx[(size_t)k0*G4_ + j]     : 0.f;
    float w1 = (k0+1 < POSE_) ? Wx[(size_t)(k0+1)*G4_ + j] : 0.f;
    float w2 = (k0+8 < POSE_) ? Wx[(size_t)(k0+8)*G4_ + j] : 0.f;
    float w3 = (k0+9 < POSE_) ? Wx[(size_t)(k0+9)*G4_ + j] : 0.f;
    size_t o = ((((size_t)g*4 + q)*9 + (kt>>1))*32 + lane)*2 + (kt & 1);
    out[o] = make_uint2(packbf(w0,w1), packbf(w2,w3));
}

__global__ void pack_owb_k(const float* __restrict__ Wo, uint2* __restrict__ out)
{
    int idx = blockIdx.x*256 + threadIdx.x;
    if (idx >= OGRP_*64*32) return;
    int lane = idx & 31;
    int kt = (idx >> 5) & 63;
    int grp = idx >> 11;
    int n  = grp*8 + (lane >> 2);
    int k0 = kt*16 + (lane & 3)*2;
    float w0=0.f, w1=0.f, w2=0.f, w3=0.f;
    if (n < POSE_) {
        w0 = Wo[(size_t)k0*POSE_ + n];     w1 = Wo[(size_t)(k0+1)*POSE_ + n];
        w2 = Wo[(size_t)(k0+8)*POSE_ + n]; w3 = Wo[(size_t)(k0+9)*POSE_ + n];
    }
    size_t o = (((size_t)grp*32 + (kt>>1))*32 + lane)*2 + (kt & 1);
    out[o] = make_uint2(packbf(w0,w1), packbf(w2,w3));
}

__global__ void init_dec_k(const float* __restrict__ vh, unsigned* __restrict__ hb)
{
    int i = blockIdx.x*256 + threadIdx.x;
    if (i < GATEB_*8) g_hflag[i] = 0;
    if (i < OUTB_*8)  g_oflag[i] = 0;
    if (i < HBTOT_) {
        int b = i / HBW_, kw = i % HBW_;
        int k0 = kw*2;
        float v0 = (k0   < HID_) ? vh[b*HID_ + k0]   : 0.f;
        float v1 = (k0+1 < HID_) ? vh[b*HID_ + k0+1] : 0.f;
        hb[3*HBTOT_ + i] = packbf(v0, v1);
    }
}

__device__ __forceinline__ float sigf(float x){ return 1.f/(1.f+expf(-x)); }

__device__ __forceinline__ unsigned ld_acq(const unsigned* p) {
    unsigned v;
    asm volatile("ld.acquire.gpu.global.u32 %0, [%1];" : "=r"(v) : "l"(p) : "memory");
    return v;
}
__device__ __forceinline__ void st_rel(unsigned* p, unsigned v) {
    asm volatile("st.release.gpu.global.u32 [%0], %1;" :: "l"(p), "r"(v) : "memory");
}

// grid = 146 x 128 threads. Blocks 0..127: gates (8 units each, 1 warp/SMSP).
// Blocks 128..145: out-proj. Sync: per-block release flags, no atomics.
// dyn smem: hbs 8256w | xbs 2368w | red 2048f = 50688 B
__global__ __launch_bounds__(128)
void dec_k(const uint2* __restrict__ WHB, const uint2* __restrict__ WXB,
           const uint2* __restrict__ OWB, const float* __restrict__ lb,
           const float* __restrict__ xwx, const float* __restrict__ encp,
           const float* __restrict__ vec_c, const float* __restrict__ dec0,
           unsigned* __restrict__ hb, float* __restrict__ outbuf,
           const int* __restrict__ ep)
{
    extern __shared__ unsigned smu[];
    unsigned* hbs = smu;
    unsigned* xbs = smu + HBTOT_;
    float*    red = (float*)(smu + HBTOT_ + 16*XBW_);
    float*    redo = (float*)(smu + HBTOT_);

    int tid = threadIdx.x, bx = blockIdx.x;
    int lane = tid & 31, w = tid >> 5;
    int b = lane >> 2, tg = lane & 3;
    bool isGate = bx < GATEB_;
    int p = (int)((double)(*ep) * 0.01);   // double required: fp32 100*0.01 -> 0
    int per = p + 10;
    const uint4* WHB4 = (const uint4*)WHB;
    const uint4* WXB4 = (const uint4*)WXB;
    const uint4* OWB4 = (const uint4*)OWB;

#define HBS_COPY(hrp) { \
        const uint4* srcv = (const uint4*)(hrp); uint4* dstv = (uint4*)hbs; \
        for (int i = tid; i < HBTOT_/4; i += 128) dstv[i] = __ldcg(srcv + i); }

#define A_LOAD2(buf, stride, ktv) { \
        int wA = b*(stride) + (ktv)*8 + tg; \
        a0[0] = (buf)[wA];     a0[1] = (buf)[wA + 8*(stride)]; \
        a0[2] = (buf)[wA + 4]; a0[3] = (buf)[wA + 8*(stride) + 4]; \
        wA += 8; \
        a1[0] = (buf)[wA];     a1[1] = (buf)[wA + 8*(stride)]; \
        a1[2] = (buf)[wA + 4]; a1[3] = (buf)[wA + 8*(stride) + 4]; }

#define WAIT_H(needv) { \
        unsigned _need = (unsigned)(needv); \
        for (;;) { \
            unsigned mn = 0xffffffffu; \
            _Pragma("unroll") \
            for (int ii = 0; ii < 4; ii++) \
                mn = min(mn, ld_acq(&g_hflag[(lane + ii*32)*8])); \
            mn = __reduce_min_sync(0xffffffffu, mn); \
            if (mn >= _need) break; \
        } }

    if (isGate) {
        int u0 = bx*8 + tg*2;
        float c0=0.f, c1=0.f, c2=0.f, c3=0.f;
        if (w == 0) {
            c0 = vec_c[b*HID_ + u0];       c1 = vec_c[b*HID_ + u0 + 1];
            c2 = vec_c[(b+8)*HID_ + u0];   c3 = vec_c[(b+8)*HID_ + u0 + 1];
        }
        for (int t = 0; t < S_; t++) {
            bool sampled = (t % per) < p;
            const unsigned* hr = hb + ((t+3)&3)*(size_t)HBTOT_;
            unsigned*       hw = hb + (t&3)*(size_t)HBTOT_;

            float2 xw[8];
            if (w == 0 && !sampled) {
#pragma unroll
                for (int q = 0; q < 4; q++)
#pragma unroll
                    for (int rr = 0; rr < 2; rr++)
                        xw[q*2+rr] = __ldcg((const float2*)(xwx +
                            ((size_t)(b + rr*8)*S_ + t)*G4_ + q*1024 + u0));
            }

            if (w == 1 && t > 0) WAIT_H(t);
            if (w == 2) {
                unsigned needO = sampled ? (unsigned)t : (t >= 4 ? (unsigned)(t-3) : 0u);
                if (needO) {
                    for (;;) {
                        unsigned v = (lane < OUTB_) ? ld_acq(&g_oflag[lane*8]) : 0xffffffffu;
                        unsigned mn = __reduce_min_sync(0xffffffffu, v);
                        if (mn >= needO) break;
                    }
                }
            }
            __syncthreads();

            HBS_COPY(hr);
            if (sampled) {
                const float* xsrc0 = (t == 0) ? dec0 : (outbuf + (size_t)(t-1)*POSE_);
                size_t bstride = (t == 0) ? (size_t)POSE_ : (size_t)S_*POSE_;
                for (int i = tid; i < 16*(XBW_-4); i += 128) {
                    int b2 = i / (XBW_-4), kw = i % (XBW_-4);
                    int k0 = kw*2;
                    const float* sp = xsrc0 + (size_t)b2*bstride;
                    float v0 = (k0   < POSE_) ? __ldcg(sp + k0)   : 0.f;
                    float v1 = (k0+1 < POSE_) ? __ldcg(sp + k0+1) : 0.f;
                    xbs[b2*XBW_ + kw] = packbf(v0, v1);
                }
            }
            __syncthreads();

            float d[4][4];
#pragma unroll
            for (int q = 0; q < 4; q++)
#pragma unroll
                for (int i = 0; i < 4; i++) d[q][i] = 0.f;
            unsigned a0[4], a1[4];
#pragma unroll 2
            for (int kt8 = 0; kt8 < 8; kt8++) {
                int kt2 = w*8 + kt8;
                A_LOAD2(hbs, HBW_, kt2*2);
#pragma unroll
                for (int q = 0; q < 4; q++) {
                    uint4 bb = WHB4[(((size_t)bx*4 + q)*32 + kt2)*32 + lane];
                    unsigned be[2] = {bb.x, bb.y}, bo[2] = {bb.z, bb.w};
                    mma_bf16(d[q], a0, be);
                    mma_bf16(d[q], a1, bo);
                }
            }
            if (sampled) {
                int e2 = min(9, w*3 + 3);
                for (int kt2 = w*3; kt2 < e2; kt2++) {
                    A_LOAD2(xbs, XBW_, kt2*2);
#pragma unroll
                    for (int q = 0; q < 4; q++) {
                        uint4 bb = WXB4[(((size_t)bx*4 + q)*9 + kt2)*32 + lane];
                        unsigned be[2] = {bb.x, bb.y}, bo[2] = {bb.z, bb.w};
                        mma_bf16(d[q], a0, be);
                        mma_bf16(d[q], a1, bo);
                    }
                }
            }
            {
                float* myr = red + (w*32 + lane)*16;
#pragma unroll
                for (int q = 0; q < 4; q++)
#pragma unroll
                    for (int i = 0; i < 4; i++) myr[q*4+i] = d[q][i];
            }
            __syncthreads();

            if (w == 0) {
                float s[16];
#pragma unroll
                for (int i = 0; i < 16; i++) s[i] = 0.f;
#pragma unroll
                for (int w2 = 0; w2 < 4; w2++) {
                    const float4* r4 = (const float4*)(red + (w2*32 + lane)*16);
#pragma unroll
                    for (int q = 0; q < 4; q++) {
                        float4 v = r4[q];
                        s[q*4+0] += v.x; s[q*4+1] += v.y; s[q*4+2] += v.z; s[q*4+3] += v.w;
                    }
                }
                float gate[4][4];
#pragma unroll
                for (int q = 0; q < 4; q++) {
                    float2 lbv = *(const float2*)(lb + q*1024 + u0);
                    gate[q][0] = s[q*4+0] + lbv.x;
                    gate[q][1] = s[q*4+1] + lbv.y;
                    gate[q][2] = s[q*4+2] + lbv.x;
                    gate[q][3] = s[q*4+3] + lbv.y;
                    if (!sampled) {
                        gate[q][0] += xw[q*2].x;   gate[q][1] += xw[q*2].y;
                        gate[q][2] += xw[q*2+1].x; gate[q][3] += xw[q*2+1].y;
                    }
                }
                float cc[4] = {c0, c1, c2, c3};
                float hh[4];
#pragma unroll
                for (int e = 0; e < 4; e++) {
                    float cv = sigf(gate[1][e])*cc[e] + sigf(gate[0][e])*tanhf(gate[2][e]);
                    hh[e] = sigf(gate[3][e])*tanhf(cv);
                    cc[e] = cv;
                }
                c0 = cc[0]; c1 = cc[1]; c2 = cc[2]; c3 = cc[3];
                hw[b*HBW_ + bx*4 + tg]     = packbf(hh[0], hh[1]);
                hw[(b+8)*HBW_ + bx*4 + tg] = packbf(hh[2], hh[3]);
            }
            __syncthreads();
            if (tid == 0) st_rel(&g_hflag[bx*8], (unsigned)(t+1));
        }
    } else {
        int ob = bx - GATEB_;
        int grp = ob*2 + (w >> 1);
        int kh = w & 1;
        bool ovalid = (grp < OGRP_);
        for (int t = 0; t < S_; t++) {
            if (w == 0) WAIT_H(t+1);
            __syncthreads();
            const unsigned* hrp = hb + (t&3)*(size_t)HBTOT_;
            HBS_COPY(hrp);
            __syncthreads();
            float d[4] = {0.f,0.f,0.f,0.f};
            unsigned a0[4], a1[4];
            if (ovalid) {
#pragma unroll 2
                for (int kt16 = 0; kt16 < 16; kt16++) {
                    int kt2 = kh*16 + kt16;
                    A_LOAD2(hbs, HBW_, kt2*2);
                    uint4 bb = OWB4[((size_t)grp*32 + kt2)*32 + lane];
                    unsigned be[2] = {bb.x, bb.y}, bo[2] = {bb.z, bb.w};
                    mma_bf16(d, a0, be);
                    mma_bf16(d, a1, bo);
                }
            }
            float* myr = redo + (w*32 + lane)*4;
            myr[0]=d[0]; myr[1]=d[1]; myr[2]=d[2]; myr[3]=d[3];
            __syncthreads();
            if ((w & 1) == 0 && ovalid) {
                float s0 = redo[(w*32+lane)*4+0] + redo[((w+1)*32+lane)*4+0];
                float s1 = redo[(w*32+lane)*4+1] + redo[((w+1)*32+lane)*4+1];
                float s2 = redo[(w*32+lane)*4+2] + redo[((w+1)*32+lane)*4+2];
                float s3 = redo[(w*32+lane)*4+3] + redo[((w+1)*32+lane)*4+3];
                int n0 = grp*8 + tg*2;
                if (n0 + 1 < POSE_) {
                    size_t o0 = ((size_t)b*S_ + t)*POSE_ + n0;
                    size_t o1 = ((size_t)(b+8)*S_ + t)*POSE_ + n0;
                    float2 e0 = *(const float2*)(encp + o0);
                    float2 e1 = *(const float2*)(encp + o1);
                    *(float2*)(outbuf + o0) = make_float2(s0 + e0.x, s1 + e0.y);
                    *(float2*)(outbuf + o1) = make_float2(s2 + e1.x, s3 + e1.y);
                }
            }
            __syncthreads();
            if (tid == 0) st_rel(&g_oflag[ob*8], (unsigned)(t+1));
        }
    }
#undef WAIT_H
#undef A_LOAD2
#undef HBS_COPY
}

extern "C" void kernel_launch(void* const* d_in, const int* in_sizes, int n_in,
                              void* d_out, int out_size)
{
    (void)in_sizes; (void)n_in; (void)out_size;
    const float* src_seq = (const float*)d_in[0];
    const int*   src_pos = (const int*)  d_in[1];
    const float* tgt_seq = (const float*)d_in[2];
    const float* vec_h   = (const float*)d_in[3];
    const float* vec_c   = (const float*)d_in[4];
    const float* dec0    = (const float*)d_in[5];
    const float* emb_W   = (const float*)d_in[6];
    const float* emb_b   = (const float*)d_in[7];
    const float* pos_t   = (const float*)d_in[8];
    const float* Wq      = (const float*)d_in[9];
    const float* Wk      = (const float*)d_in[10];
    const float* Wv      = (const float*)d_in[11];
    const float* Wo      = (const float*)d_in[12];
    const float* ln1g    = (const float*)d_in[13];
    const float* ln1b    = (const float*)d_in[14];
    const float* fW1     = (const float*)d_in[15];
    const float* fb1     = (const float*)d_in[16];
    const float* fW2     = (const float*)d_in[17];
    const float* fb2     = (const float*)d_in[18];
    const float* ln2g    = (const float*)d_in[19];
    const float* ln2b    = (const float*)d_in[20];
    const float* lWx     = (const float*)d_in[21];
    const float* lWh     = (const float*)d_in[22];
    const float* lb      = (const float*)d_in[23];
    const float* outW    = (const float*)d_in[24];
    const float* outb    = (const float*)d_in[25];
    const int*   ep      = (const int*)  d_in[26];
    float* out = (float*)d_out;

    void *px,*pq,*pk,*pv,*po,*pr1,*px2,*ph1,*pt2,*penc,*pxwx,*pencp,*phb,*pwhb,*pwxb,*powb,*pap,*pwp;
    cudaGetSymbolAddress(&px,  g_x);   cudaGetSymbolAddress(&pq,  g_q);
    cudaGetSymbolAddress(&pk,  g_k);   cudaGetSymbolAddress(&pv,  g_v);
    cudaGetSymbolAddress(&po,  g_o);   cudaGetSymbolAddress(&pr1, g_r1);
    cudaGetSymbolAddress(&px2, g_x2);  cudaGetSymbolAddress(&ph1, g_h1);
    cudaGetSymbolAddress(&pt2, g_t2);  cudaGetSymbolAddress(&penc,g_enc);
    cudaGetSymbolAddress(&pxwx,g_xwx); cudaGetSymbolAddress(&pencp,g_encp);
    cudaGetSymbolAddress(&phb, g_hb);  cudaGetSymbolAddress(&pwhb,g_whb);
    cudaGetSymbolAddress(&pwxb,g_wxb); cudaGetSymbolAddress(&powb,g_owb);
    cudaGetSymbolAddress(&pap, g_ap);  cudaGetSymbolAddress(&pwp, g_wp);
    float *X=(float*)px, *Qb=(float*)pq, *Kb=(float*)pk, *Vb=(float*)pv, *Ob=(float*)po;
    float *R1=(float*)pr1, *X2=(float*)px2, *H1=(float*)ph1, *T2=(float*)pt2, *ENC=(float*)penc;
    float *XWX=(float*)pxwx, *ENCP=(float*)pencp;
    unsigned *HB=(unsigned*)phb;
    uint2 *WHB=(uint2*)pwhb, *WXB=(uint2*)pwxb, *OWB=(uint2*)powb;
    uint2 *AP=(uint2*)pap, *WP=(uint2*)pwp;

    const int GSM = 2*GSTAGE_*8;
    cudaFuncSetAttribute(attn_k, cudaFuncAttributeMaxDynamicSharedMemorySize, KSPAN_*KROW_*4);
    cudaFuncSetAttribute(dec_k,  cudaFuncAttributeMaxDynamicSharedMemorySize, 50688);
    cudaFuncSetAttribute(gemmp_k<EPI_NONE>,      cudaFuncAttributeMaxDynamicSharedMemorySize, GSM);
    cudaFuncSetAttribute(gemmp_k<EPI_POS>,       cudaFuncAttributeMaxDynamicSharedMemorySize, GSM);
    cudaFuncSetAttribute(gemmp_k<EPI_ADD>,       cudaFuncAttributeMaxDynamicSharedMemorySize, GSM);
    cudaFuncSetAttribute(gemmp_k<EPI_BIAS_RELU>, cudaFuncAttributeMaxDynamicSharedMemorySize, GSM);
    cudaFuncSetAttribute(gemmp_k<EPI_BIAS_ADD>,  cudaFuncAttributeMaxDynamicSharedMemorySize, GSM);
    cudaFuncSetAttribute(gemmp_k<EPI_BIAS>,      cudaFuncAttributeMaxDynamicSharedMemorySize, GSM);

    dim3 gD((D_+63)/64, M_/128), gF((FFN_+63)/64, M_/128);
    dim3 gG4((G4_+63)/64, M_/128), gP((POSE_+63)/64, M_/128);

#define PACKA(src, KP) packa_k<<<((M_*(KP))+255)/256,256>>>((src), AP, M_*(KP))
#define PACKW(src, KP, N) packw_k<<<(((KP)*(N))+255)/256,256>>>((src), WP, (KP), (N))

    PACKA(src_seq, 219); PACKW(emb_W, 219, D_);
    gemmp_k<EPI_POS><<<gD,256,GSM>>>(AP, 219, WP, X, D_, emb_b, nullptr, pos_t, src_pos);
    PACKA(X, 400);
    PACKW(Wq, 400, D_);
    gemmp_k<EPI_NONE><<<gD,256,GSM>>>(AP, 400, WP, Qb, D_, nullptr, nullptr, nullptr, nullptr);
    PACKW(Wk, 400, D_);
    gemmp_k<EPI_NONE><<<gD,256,GSM>>>(AP, 400, WP, Kb, D_, nullptr, nullptr, nullptr, nullptr);
    PACKW(Wv, 400, D_);
    gemmp_k<EPI_NONE><<<gD,256,GSM>>>(AP, 400, WP, Vb, D_, nullptr, nullptr, nullptr, nullptr);
    attn_k<<<dim3(S_/QT_, H_, B_),128,KSPAN_*KROW_*4>>>(Qb, Kb, Vb, Ob);
    PACKA(Ob, 400); PACKW(Wo, 400, D_);
    gemmp_k<EPI_ADD><<<gD,256,GSM>>>(AP, 400, WP, R1, D_, nullptr, X, nullptr, nullptr);
    ln_k<<<M_,256>>>(R1, X2, ln1g, ln1b);
    PACKA(X2, 400); PACKW(fW1, 400, FFN_);
    gemmp_k<EPI_BIAS_RELU><<<gF,256,GSM>>>(AP, 400, WP, H1, FFN_, fb1, nullptr, nullptr, nullptr);
    PACKA(H1, 512); PACKW(fW2, 512, D_);
    gemmp_k<EPI_BIAS_ADD><<<gD,256,GSM>>>(AP, 512, WP, T2, D_, fb2, X2, nullptr, nullptr);
    ln_k<<<M_,256>>>(T2, ENC, ln2g, ln2b);

    PACKA(tgt_seq, 137); PACKW(lWx, 137, G4_);
    gemmp_k<EPI_NONE><<<gG4,256,GSM>>>(AP, 137, WP, XWX, G4_, nullptr, nullptr, nullptr, nullptr);
    PACKA(ENC, 400); PACKW(outW + (size_t)HID_*POSE_, 400, POSE_);
    gemmp_k<EPI_BIAS><<<gP,256,GSM>>>(AP, 400, WP, ENCP, POSE_, outb, nullptr, nullptr, nullptr);

    pack_whb_k<<<(GATEB_*4*64*32+255)/256,256>>>(lWh, WHB);
    pack_wxb_k<<<(GATEB_*4*18*32+255)/256,256>>>(lWx, WXB);
    pack_owb_k<<<(OGRP_*64*32+255)/256,256>>>(outW, OWB);
    init_dec_k<<<(HBTOT_+255)/256,256>>>(vec_h, HB);

    dec_k<<<NBDEC_,128,50688>>>(WHB, WXB, OWB, lb, XWX, ENCP, vec_c, dec0, HB, out, ep);
#undef PACKA
#undef PACKW
}

// round 15
// speedup vs baseline: 1.6714x; 1.0908x over previous
#include <cuda_runtime.h>
#include <cuda_bf16.h>
#include <math.h>

#define B_ 16
#define S_ 512
#define FRAME_ 438
#define D_ 800
#define H_ 8
#define DH_ 100
#define FFN_ 1024
#define HID_ 1024
#define POSE_ 274
#define WIN_ 100
#define M_ (B_*S_)
#define G4_ (4*HID_)
#define QT_ 8
#define KSPAN_ (2*WIN_+QT_)
#define KROW_ 101
#define GATEB_ 128
#define OUTB_ 18
#define NBDEC_ (GATEB_+OUTB_)
#define HBW_ 516
#define HBTOT_ (16*HBW_)
#define XBW_ 148
#define OGRP_ 35
#define GSTAGE_ (128*17 + 16*65)
#define WSM_OFF_ 12672           // words: hbs 8256 + xbs 2368 + red 2048
#define DEC_SMEM_ 134656         // bytes: 50688 + 4096*16 + 1152*16

__device__ float g_x[M_*D_];
__device__ float g_q[M_*D_];
__device__ float g_k[M_*D_];
__device__ float g_v[M_*D_];
__device__ float g_o[M_*D_];
__device__ float g_r1[M_*D_];
__device__ float g_x2[M_*D_];
__device__ float g_h1[M_*FFN_];
__device__ float g_t2[M_*D_];
__device__ float g_enc[M_*D_];
__device__ float g_xwx[(size_t)M_*G4_];
__device__ float g_encp[M_*POSE_];
__device__ __align__(16) unsigned g_hb[4*HBTOT_];
__device__ __align__(16) uint2 g_whb[(size_t)GATEB_*4*64*32];
__device__ __align__(16) uint2 g_wxb[(size_t)GATEB_*4*18*32];
__device__ __align__(16) uint2 g_owb[(size_t)OGRP_*64*32];
__device__ uint2 g_ap[(size_t)M_*512];
__device__ uint2 g_wp[600000];
__device__ unsigned g_hflag[GATEB_*8];
__device__ unsigned g_oflag[OUTB_*8];

enum { EPI_NONE=0, EPI_POS=1, EPI_ADD=2, EPI_BIAS_RELU=3, EPI_BIAS_ADD=4, EPI_BIAS=5 };

__device__ __forceinline__ unsigned packbf(float a, float b) {
    __nv_bfloat162 t = __float22bfloat162_rn(make_float2(a, b));
    return *(unsigned*)&t;
}
__device__ __forceinline__ float bfres(float x, float& hi) {
    __nv_bfloat16 h = __float2bfloat16_rn(x);
    hi = __bfloat162float(h);
    return x - hi;
}
__device__ __forceinline__ void mma_bf16(float* d, const unsigned* a, const unsigned* b) {
    asm volatile("mma.sync.aligned.m16n8k16.row.col.f32.bf16.bf16.f32 "
        "{%0,%1,%2,%3}, {%4,%5,%6,%7}, {%8,%9}, {%0,%1,%2,%3};"
        : "+f"(d[0]), "+f"(d[1]), "+f"(d[2]), "+f"(d[3])
        : "r"(a[0]), "r"(a[1]), "r"(a[2]), "r"(a[3]), "r"(b[0]), "r"(b[1]));
}

// ---------------- split-bf16 pre-pack kernels ----------------
__global__ void packa_k(const float* __restrict__ A, uint2* __restrict__ out, int npairs)
{
    int i = blockIdx.x*256 + threadIdx.x;
    if (i < npairs) {
        float2 v = ((const float2*)A)[i];
        float h0, h1;
        float l0 = bfres(v.x, h0), l1 = bfres(v.y, h1);
        out[i] = make_uint2(packbf(h0, h1), packbf(l0, l1));
    }
}
__global__ void packw_k(const float* __restrict__ W, uint2* __restrict__ out, int KP, int Nn)
{
    int i = blockIdx.x*256 + threadIdx.x;
    if (i < KP*Nn) {
        int kp = i / Nn, n = i % Nn;
        float w0 = W[(size_t)(2*kp)*Nn + n];
        float w1 = W[(size_t)(2*kp+1)*Nn + n];
        float h0, h1;
        float l0 = bfres(w0, h0), l1 = bfres(w1, h1);
        out[i] = make_uint2(packbf(h0, h1), packbf(l0, l1));
    }
}

// ---------------- packed split-bf16 GEMM, 2-stage cp.async pipeline ----------------
template<int EPI>
__global__ __launch_bounds__(256)
void gemmp_k(const uint2* __restrict__ Ap, int KP,
             const uint2* __restrict__ Wp,
             float* __restrict__ C, int Nn,
             const float* __restrict__ bias, const float* __restrict__ addend,
             const float* __restrict__ pos_table, const int* __restrict__ pos_idx)
{
    extern __shared__ uint2 sm2[];
    int tid = threadIdx.x, lane = tid & 31, w = tid >> 5;
    int wm = w >> 1, wn = w & 1;
    int rowBase = blockIdx.y * 128, colBase = blockIdx.x * 64;
    int tg = lane & 3, qd = lane >> 2;
    int ntiles = (KP + 15) >> 4;

    float d[2][4][4];
#pragma unroll
    for (int mt = 0; mt < 2; mt++)
#pragma unroll
        for (int nt = 0; nt < 4; nt++)
#pragma unroll
            for (int i = 0; i < 4; i++) d[mt][nt][i] = 0.f;

    auto issue = [&](int ti, int s) {
        uint2* As = sm2 + s*GSTAGE_;
        uint2* Ws = As + 128*17;
        int k0p = ti*16;
#pragma unroll
        for (int ii = 0; ii < 8; ii++) {
            int i = ii*256 + tid;
            int row = i >> 4, kw = i & 15, gkp = k0p + kw;
            uint2* dst = &As[row*17 + kw];
            if (gkp < KP) {
                unsigned da = (unsigned)__cvta_generic_to_shared(dst);
                asm volatile("cp.async.ca.shared.global [%0], [%1], 8;"
                             :: "r"(da), "l"(&Ap[(size_t)(rowBase+row)*KP + gkp]));
            } else *dst = make_uint2(0u, 0u);
        }
#pragma unroll
        for (int ii = 0; ii < 4; ii++) {
            int i = ii*256 + tid;
            int n = i & 63, kw = i >> 6;
            int gkp = k0p + kw, gn = colBase + n;
            uint2* dst = &Ws[kw*65 + n];
            if (gkp < KP && gn < Nn) {
                unsigned da = (unsigned)__cvta_generic_to_shared(dst);
                asm volatile("cp.async.ca.shared.global [%0], [%1], 8;"
                             :: "r"(da), "l"(&Wp[(size_t)gkp*Nn + gn]));
            } else *dst = make_uint2(0u, 0u);
        }
        asm volatile("cp.async.commit_group;");
    };

    issue(0, 0);
    for (int ti = 0; ti < ntiles; ti++) {
        if (ti + 1 < ntiles) {
            issue(ti+1, (ti+1) & 1);
            asm volatile("cp.async.wait_group 1;");
        } else {
            asm volatile("cp.async.wait_group 0;");
        }
        __syncthreads();
        uint2* Asm = sm2 + (ti & 1)*GSTAGE_;
        uint2* Wsm = Asm + 128*17;
#pragma unroll
        for (int kt = 0; kt < 2; kt++) {
            unsigned ah[2][4], al[2][4], bh[4][2], bl[4][2];
#pragma unroll
            for (int mt = 0; mt < 2; mt++) {
                int base = (wm*32 + mt*16 + qd)*17 + kt*8 + tg;
                uint2 q0 = Asm[base],     q1 = Asm[base + 8*17];
                uint2 q2 = Asm[base + 4], q3 = Asm[base + 8*17 + 4];
                ah[mt][0]=q0.x; ah[mt][1]=q1.x; ah[mt][2]=q2.x; ah[mt][3]=q3.x;
                al[mt][0]=q0.y; al[mt][1]=q1.y; al[mt][2]=q2.y; al[mt][3]=q3.y;
            }
#pragma unroll
            for (int nt = 0; nt < 4; nt++) {
                int nn = wn*32 + nt*8 + qd;
                int kb = kt*8 + tg;
                uint2 q0 = Wsm[kb*65 + nn], q1 = Wsm[(kb+4)*65 + nn];
                bh[nt][0]=q0.x; bh[nt][1]=q1.x;
                bl[nt][0]=q0.y; bl[nt][1]=q1.y;
            }
#pragma unroll
            for (int mt = 0; mt < 2; mt++)
#pragma unroll
                for (int nt = 0; nt < 4; nt++) {
                    mma_bf16(d[mt][nt], ah[mt], bh[nt]);
                    mma_bf16(d[mt][nt], ah[mt], bl[nt]);
                    mma_bf16(d[mt][nt], al[mt], bh[nt]);
                }
        }
        __syncthreads();
    }

#pragma unroll
    for (int mt = 0; mt < 2; mt++) {
#pragma unroll
        for (int nt = 0; nt < 4; nt++) {
#pragma unroll
            for (int half = 0; half < 2; half++) {
                int row = rowBase + wm*32 + mt*16 + qd + half*8;
                int col = colBase + wn*32 + nt*8 + tg*2;
                if (col < Nn) {
                    float v0 = d[mt][nt][half*2+0];
                    float v1 = d[mt][nt][half*2+1];
                    if (EPI == EPI_POS) {
                        size_t pb = (size_t)pos_idx[row]*Nn + col;
                        v0 += bias[col]   + pos_table[pb];
                        v1 += bias[col+1] + pos_table[pb+1];
                    } else if (EPI == EPI_ADD) {
                        size_t ab = (size_t)row*Nn + col;
                        v0 += addend[ab]; v1 += addend[ab+1];
                    } else if (EPI == EPI_BIAS_RELU) {
                        v0 += bias[col]; v1 += bias[col+1];
                        v0 = v0 > 0.f ? v0 : 0.f; v1 = v1 > 0.f ? v1 : 0.f;
                    } else if (EPI == EPI_BIAS_ADD) {
                        size_t ab = (size_t)row*Nn + col;
                        v0 += bias[col] + addend[ab]; v1 += bias[col+1] + addend[ab+1];
                    } else if (EPI == EPI_BIAS) {
                        v0 += bias[col]; v1 += bias[col+1];
                    }
                    *(float2*)(C + (size_t)row*Nn + col) = make_float2(v0, v1);
                }
            }
        }
    }
}

__global__ __launch_bounds__(256)
void ln_k(const float* __restrict__ in, float* __restrict__ out,
          const float* __restrict__ g, const float* __restrict__ b)
{
    __shared__ float buf[D_];
    __shared__ float red[256];
    int row = blockIdx.x, tid = threadIdx.x;
    float s = 0.f;
    for (int i = tid; i < D_; i += 256) { float v = in[(size_t)row*D_ + i]; buf[i] = v; s += v; }
    red[tid] = s; __syncthreads();
    for (int st = 128; st > 0; st >>= 1) { if (tid < st) red[tid] += red[tid+st]; __syncthreads(); }
    float mean = red[0] / (float)D_;
    __syncthreads();
    float ss = 0.f;
    for (int i = tid; i < D_; i += 256) { float dd = buf[i]-mean; ss += dd*dd; }
    red[tid] = ss; __syncthreads();
    for (int st = 128; st > 0; st >>= 1) { if (tid < st) red[tid] += red[tid+st]; __syncthreads(); }
    float inv = rsqrtf(red[0]/(float)D_ + 1e-6f);
    for (int i = tid; i < D_; i += 256)
        out[(size_t)row*D_ + i] = (buf[i]-mean)*inv*g[i] + b[i];
}

__global__ __launch_bounds__(128)
void attn_k(const float* __restrict__ Q, const float* __restrict__ K,
            const float* __restrict__ V, float* __restrict__ O)
{
    extern __shared__ float ks[];
    __shared__ float qs[QT_*DH_];
    __shared__ float sc[QT_][KSPAN_];
    __shared__ float invs[QT_];
    int tid = threadIdx.x;
    int q0 = blockIdx.x * QT_, h = blockIdx.y, b = blockIdx.z;
    int kl = max(0, q0 - WIN_);
    int kh = min(S_-1, q0 + QT_-1 + WIN_);
    int nk = kh - kl + 1;
    size_t base = ((size_t)b*S_)*D_ + (size_t)h*DH_;

    for (int idx = tid; idx < QT_*DH_; idx += 128) {
        int qi = idx / DH_, dd = idx % DH_;
        qs[idx] = Q[base + (size_t)(q0+qi)*D_ + dd];
    }
    for (int idx = tid; idx < nk*DH_; idx += 128) {
        int kk = idx / DH_, dd = idx % DH_;
        ks[kk*KROW_ + dd] = K[base + (size_t)(kl+kk)*D_ + dd];
    }
    __syncthreads();

    for (int pid = tid; pid < QT_*nk; pid += 128) {
        int kk = pid % nk, qi = pid / nk;
        int qq = q0 + qi, kp = kl + kk;
        float v;
        if (kp >= qq - WIN_ && kp <= qq + WIN_) {
            float dd = 0.f;
            for (int i = 0; i < DH_; i++) dd += qs[qi*DH_ + i]*ks[kk*KROW_ + i];
            v = dd * 0.1f;
        } else v = -1e30f;
        sc[qi][kk] = v;
    }
    __syncthreads();
    {
        int qi = tid >> 4, l = tid & 15;
        float m = -1e30f;
        for (int kk = l; kk < nk; kk += 16) m = fmaxf(m, sc[qi][kk]);
#pragma unroll
        for (int s2 = 8; s2 > 0; s2 >>= 1) m = fmaxf(m, __shfl_xor_sync(0xffffffffu, m, s2, 16));
        float ssum = 0.f;
        for (int kk = l; kk < nk; kk += 16) { float e = expf(sc[qi][kk]-m); sc[qi][kk] = e; ssum += e; }
#pragma unroll
        for (int s2 = 8; s2 > 0; s2 >>= 1) ssum += __shfl_xor_sync(0xffffffffu, ssum, s2, 16);
        if (l == 0) invs[qi] = 1.f / ssum;
    }
    __syncthreads();
    if (tid < DH_) {
        float acc[QT_];
#pragma unroll
        for (int qi = 0; qi < QT_; qi++) acc[qi] = 0.f;
        for (int kk = 0; kk < nk; kk++) {
            float vv = V[base + (size_t)(kl+kk)*D_ + tid];
#pragma unroll
            for (int qi = 0; qi < QT_; qi++) acc[qi] += sc[qi][kk]*vv;
        }
#pragma unroll
        for (int qi = 0; qi < QT_; qi++)
            O[base + (size_t)(q0+qi)*D_ + tid] = acc[qi]*invs[qi];
    }
}

// ---------------- decoder pack kernels: paired-kt uint4 layout ----------------
__global__ void pack_whb_k(const float* __restrict__ Wh, uint2* __restrict__ out)
{
    size_t idx = (size_t)blockIdx.x*256 + threadIdx.x;
    if (idx >= (size_t)GATEB_*4*64*32) return;
    int lane = idx & 31;
    int kt = (idx >> 5) & 63;
    int q  = (idx >> 11) & 3;
    int g  = idx >> 13;
    int j  = q*1024 + g*8 + (lane >> 2);
    int k0 = kt*16 + (lane & 3)*2;
    float w0 = Wh[(size_t)k0*G4_ + j],     w1 = Wh[(size_t)(k0+1)*G4_ + j];
    float w2 = Wh[(size_t)(k0+8)*G4_ + j], w3 = Wh[(size_t)(k0+9)*G4_ + j];
    size_t o = ((((size_t)g*4 + q)*32 + (kt>>1))*32 + lane)*2 + (kt & 1);
    out[o] = make_uint2(packbf(w0,w1), packbf(w2,w3));
}

__global__ void pack_wxb_k(const float* __restrict__ Wx, uint2* __restrict__ out)
{
    size_t idx = (size_t)blockIdx.x*256 + threadIdx.x;
    if (idx >= (size_t)GATEB_*4*18*32) return;
    int lane = idx & 31;
    size_t r = idx >> 5;
    int kt = r % 18;
    int q  = (r / 18) & 3;
    int g  = r / 72;
    int j  = q*1024 + g*8 + (lane >> 2);
    int k0 = kt*16 + (lane & 3)*2;
    float w0 = (k0   < POSE_) ? Wx[(size_t)k0*G4_ + j]     : 0.f;
    float w1 = (k0+1 < POSE_) ? Wx[(size_t)(k0+1)*G4_ + j] : 0.f;
    float w2 = (k0+8 < POSE_) ? Wx[(size_t)(k0+8)*G4_ + j] : 0.f;
    float w3 = (k0+9 < POSE_) ? Wx[(size_t)(k0+9)*G4_ + j] : 0.f;
    size_t o = ((((size_t)g*4 + q)*9 + (kt>>1))*32 + lane)*2 + (kt & 1);
    out[o] = make_uint2(packbf(w0,w1), packbf(w2,w3));
}

__global__ void pack_owb_k(const float* __restrict__ Wo, uint2* __restrict__ out)
{
    int idx = blockIdx.x*256 + threadIdx.x;
    if (idx >= OGRP_*64*32) return;
    int lane = idx & 31;
    int kt = (idx >> 5) & 63;
    int grp = idx >> 11;
    int n  = grp*8 + (lane >> 2);
    int k0 = kt*16 + (lane & 3)*2;
    float w0=0.f, w1=0.f, w2=0.f, w3=0.f;
    if (n < POSE_) {
        w0 = Wo[(size_t)k0*POSE_ + n];     w1 = Wo[(size_t)(k0+1)*POSE_ + n];
        w2 = Wo[(size_t)(k0+8)*POSE_ + n]; w3 = Wo[(size_t)(k0+9)*POSE_ + n];
    }
    size_t o = (((size_t)grp*32 + (kt>>1))*32 + lane)*2 + (kt & 1);
    out[o] = make_uint2(packbf(w0,w1), packbf(w2,w3));
}

__global__ void init_dec_k(const float* __restrict__ vh, unsigned* __restrict__ hb)
{
    int i = blockIdx.x*256 + threadIdx.x;
    if (i < GATEB_*8) g_hflag[i] = 0;
    if (i < OUTB_*8)  g_oflag[i] = 0;
    if (i < HBTOT_) {
        int b = i / HBW_, kw = i % HBW_;
        int k0 = kw*2;
        float v0 = (k0   < HID_) ? vh[b*HID_ + k0]   : 0.f;
        float v1 = (k0+1 < HID_) ? vh[b*HID_ + k0+1] : 0.f;
        hb[3*HBTOT_ + i] = packbf(v0, v1);
    }
}

__device__ __forceinline__ float sigf(float x){ return 1.f/(1.f+expf(-x)); }

__device__ __forceinline__ unsigned ld_acq(const unsigned* p) {
    unsigned v;
    asm volatile("ld.acquire.gpu.global.u32 %0, [%1];" : "=r"(v) : "l"(p) : "memory");
    return v;
}
__device__ __forceinline__ void st_rel(unsigned* p, unsigned v) {
    asm volatile("st.release.gpu.global.u32 [%0], %1;" :: "l"(p), "r"(v) : "memory");
}

// grid = 146 x 128. Gates 0..127 (8 units each); out 128..145.
// All per-block weights cached in SMEM before the t-loop (no per-step L2 weight traffic).
// dyn smem: hbs 8256w | xbs 2368w | red 2048w | wsm 20992w = 134656 B
__global__ __launch_bounds__(128)
void dec_k(const uint2* __restrict__ WHB, const uint2* __restrict__ WXB,
           const uint2* __restrict__ OWB, const float* __restrict__ lb,
           const float* __restrict__ xwx, const float* __restrict__ encp,
           const float* __restrict__ vec_c, const float* __restrict__ dec0,
           unsigned* __restrict__ hb, float* __restrict__ outbuf,
           const int* __restrict__ ep)
{
    extern __shared__ unsigned smu[];
    unsigned* hbs = smu;
    unsigned* xbs = smu + HBTOT_;
    float*    red = (float*)(smu + HBTOT_ + 16*XBW_);
    float*    redo = (float*)(smu + HBTOT_);
    uint4*    wsm4 = (uint4*)(smu + WSM_OFF_);

    int tid = threadIdx.x, bx = blockIdx.x;
    int lane = tid & 31, w = tid >> 5;
    int b = lane >> 2, tg = lane & 3;
    bool isGate = bx < GATEB_;
    int p = (int)((double)(*ep) * 0.01);   // double required: fp32 100*0.01 -> 0
    int per = p + 10;
    const uint4* WHB4 = (const uint4*)WHB;
    const uint4* WXB4 = (const uint4*)WXB;
    const uint4* OWB4 = (const uint4*)OWB;

#define HBS_COPY(hrp) { \
        const uint4* srcv = (const uint4*)(hrp); uint4* dstv = (uint4*)hbs; \
        for (int i = tid; i < HBTOT_/4; i += 128) dstv[i] = __ldcg(srcv + i); }

#define A_LOAD2(buf, stride, ktv) { \
        int wA = b*(stride) + (ktv)*8 + tg; \
        a0[0] = (buf)[wA];     a0[1] = (buf)[wA + 8*(stride)]; \
        a0[2] = (buf)[wA + 4]; a0[3] = (buf)[wA + 8*(stride) + 4]; \
        wA += 8; \
        a1[0] = (buf)[wA];     a1[1] = (buf)[wA + 8*(stride)]; \
        a1[2] = (buf)[wA + 4]; a1[3] = (buf)[wA + 8*(stride) + 4]; }

#define WAIT_H(needv) { \
        unsigned _need = (unsigned)(needv); \
        for (;;) { \
            unsigned mn = 0xffffffffu; \
            _Pragma("unroll") \
            for (int ii = 0; ii < 4; ii++) \
                mn = min(mn, ld_acq(&g_hflag[(lane + ii*32)*8])); \
            mn = __reduce_min_sync(0xffffffffu, mn); \
            if (mn >= _need) break; \
        } }

    if (isGate) {
        // preload WHB slice (4096 uint4 = 64KB) + WXB slice (1152 uint4 = 18KB)
        {
            const uint4* src = WHB4 + (size_t)bx*4096;
            for (int i = tid; i < 4096; i += 128) wsm4[i] = src[i];
            const uint4* srcx = WXB4 + (size_t)bx*1152;
            for (int i = tid; i < 1152; i += 128) wsm4[4096 + i] = srcx[i];
        }
        int u0 = bx*8 + tg*2;
        float c0=0.f, c1=0.f, c2=0.f, c3=0.f;
        if (w == 0) {
            c0 = vec_c[b*HID_ + u0];       c1 = vec_c[b*HID_ + u0 + 1];
            c2 = vec_c[(b+8)*HID_ + u0];   c3 = vec_c[(b+8)*HID_ + u0 + 1];
        }
        __syncthreads();
        for (int t = 0; t < S_; t++) {
            bool sampled = (t % per) < p;
            const unsigned* hr = hb + ((t+3)&3)*(size_t)HBTOT_;
            unsigned*       hw = hb + (t&3)*(size_t)HBTOT_;

            float2 xw[8];
            if (w == 0 && !sampled) {
#pragma unroll
                for (int q = 0; q < 4; q++)
#pragma unroll
                    for (int rr = 0; rr < 2; rr++)
                        xw[q*2+rr] = __ldcg((const float2*)(xwx +
                            ((size_t)(b + rr*8)*S_ + t)*G4_ + q*1024 + u0));
            }

            if (w == 1 && t > 0) WAIT_H(t);
            if (w == 2) {
                unsigned needO = sampled ? (unsigned)t : (t >= 4 ? (unsigned)(t-3) : 0u);
                if (needO) {
                    for (;;) {
                        unsigned v = (lane < OUTB_) ? ld_acq(&g_oflag[lane*8]) : 0xffffffffu;
                        unsigned mn = __reduce_min_sync(0xffffffffu, v);
                        if (mn >= needO) break;
                    }
                }
            }
            __syncthreads();

            HBS_COPY(hr);
            if (sampled) {
                const float* xsrc0 = (t == 0) ? dec0 : (outbuf + (size_t)(t-1)*POSE_);
                size_t bstride = (t == 0) ? (size_t)POSE_ : (size_t)S_*POSE_;
                for (int i = tid; i < 16*(XBW_-4); i += 128) {
                    int b2 = i / (XBW_-4), kw = i % (XBW_-4);
                    int k0 = kw*2;
                    const float* sp = xsrc0 + (size_t)b2*bstride;
                    float v0 = (k0   < POSE_) ? __ldcg(sp + k0)   : 0.f;
                    float v1 = (k0+1 < POSE_) ? __ldcg(sp + k0+1) : 0.f;
                    xbs[b2*XBW_ + kw] = packbf(v0, v1);
                }
            }
            __syncthreads();

            float d[4][4];
#pragma unroll
            for (int q = 0; q < 4; q++)
#pragma unroll
                for (int i = 0; i < 4; i++) d[q][i] = 0.f;
            unsigned a0[4], a1[4];
#pragma unroll 2
            for (int kt8 = 0; kt8 < 8; kt8++) {
                int kt2 = w*8 + kt8;
                A_LOAD2(hbs, HBW_, kt2*2);
#pragma unroll
                for (int q = 0; q < 4; q++) {
                    uint4 bb = wsm4[(q*32 + kt2)*32 + lane];
                    unsigned be[2] = {bb.x, bb.y}, bo[2] = {bb.z, bb.w};
                    mma_bf16(d[q], a0, be);
                    mma_bf16(d[q], a1, bo);
                }
            }
            if (sampled) {
                int e2 = min(9, w*3 + 3);
                for (int kt2 = w*3; kt2 < e2; kt2++) {
                    A_LOAD2(xbs, XBW_, kt2*2);
#pragma unroll
                    for (int q = 0; q < 4; q++) {
                        uint4 bb = wsm4[4096 + (q*9 + kt2)*32 + lane];
                        unsigned be[2] = {bb.x, bb.y}, bo[2] = {bb.z, bb.w};
                        mma_bf16(d[q], a0, be);
                        mma_bf16(d[q], a1, bo);
                    }
                }
            }
            {
                float* myr = red + (w*32 + lane)*16;
#pragma unroll
                for (int q = 0; q < 4; q++)
#pragma unroll
                    for (int i = 0; i < 4; i++) myr[q*4+i] = d[q][i];
            }
            __syncthreads();

            if (w == 0) {
                float s[16];
#pragma unroll
                for (int i = 0; i < 16; i++) s[i] = 0.f;
#pragma unroll
                for (int w2 = 0; w2 < 4; w2++) {
                    const float4* r4 = (const float4*)(red + (w2*32 + lane)*16);
#pragma unroll
                    for (int q = 0; q < 4; q++) {
                        float4 v = r4[q];
                        s[q*4+0] += v.x; s[q*4+1] += v.y; s[q*4+2] += v.z; s[q*4+3] += v.w;
                    }
                }
                float gate[4][4];
#pragma unroll
                for (int q = 0; q < 4; q++) {
                    float2 lbv = *(const float2*)(lb + q*1024 + u0);
                    gate[q][0] = s[q*4+0] + lbv.x;
                    gate[q][1] = s[q*4+1] + lbv.y;
                    gate[q][2] = s[q*4+2] + lbv.x;
                    gate[q][3] = s[q*4+3] + lbv.y;
                    if (!sampled) {
                        gate[q][0] += xw[q*2].x;   gate[q][1] += xw[q*2].y;
                        gate[q][2] += xw[q*2+1].x; gate[q][3] += xw[q*2+1].y;
                    }
                }
                float cc[4] = {c0, c1, c2, c3};
                float hh[4];
#pragma unroll
                for (int e = 0; e < 4; e++) {
                    float cv = sigf(gate[1][e])*cc[e] + sigf(gate[0][e])*tanhf(gate[2][e]);
                    hh[e] = sigf(gate[3][e])*tanhf(cv);
                    cc[e] = cv;
                }
                c0 = cc[0]; c1 = cc[1]; c2 = cc[2]; c3 = cc[3];
                hw[b*HBW_ + bx*4 + tg]     = packbf(hh[0], hh[1]);
                hw[(b+8)*HBW_ + bx*4 + tg] = packbf(hh[2], hh[3]);
            }
            __syncthreads();
            if (tid == 0) st_rel(&g_hflag[bx*8], (unsigned)(t+1));
        }
    } else {
        int ob = bx - GATEB_;
        int grp = ob*2 + (w >> 1);
        int kh = w & 1;
        bool ovalid = (grp < OGRP_);
        // preload OWB slice: 2 grps x 32 kt2 x 32 lanes uint4 = 32KB
        {
            size_t base0 = (size_t)(ob*2)*1024;   // 32*32 uint4 per grp
            for (int i = tid; i < 2048; i += 128) {
                size_t gi = base0 + i;
                wsm4[i] = (gi < (size_t)OGRP_*1024) ? OWB4[gi] : make_uint4(0u,0u,0u,0u);
            }
        }
        __syncthreads();
        for (int t = 0; t < S_; t++) {
            if (w == 0) WAIT_H(t+1);
            __syncthreads();
            const unsigned* hrp = hb + (t&3)*(size_t)HBTOT_;
            HBS_COPY(hrp);
            __syncthreads();
            float d[4] = {0.f,0.f,0.f,0.f};
            unsigned a0[4], a1[4];
            if (ovalid) {
#pragma unroll 2
                for (int kt16 = 0; kt16 < 16; kt16++) {
                    int kt2 = kh*16 + kt16;
                    A_LOAD2(hbs, HBW_, kt2*2);
                    uint4 bb = wsm4[((w>>1)*32 + kt2)*32 + lane];
                    unsigned be[2] = {bb.x, bb.y}, bo[2] = {bb.z, bb.w};
                    mma_bf16(d, a0, be);
                    mma_bf16(d, a1, bo);
                }
            }
            float* myr = redo + (w*32 + lane)*4;
            myr[0]=d[0]; myr[1]=d[1]; myr[2]=d[2]; myr[3]=d[3];
            __syncthreads();
            if ((w & 1) == 0 && ovalid) {
                float s0 = redo[(w*32+lane)*4+0] + redo[((w+1)*32+lane)*4+0];
                float s1 = redo[(w*32+lane)*4+1] + redo[((w+1)*32+lane)*4+1];
                float s2 = redo[(w*32+lane)*4+2] + redo[((w+1)*32+lane)*4+2];
                float s3 = redo[(w*32+lane)*4+3] + redo[((w+1)*32+lane)*4+3];
                int n0 = grp*8 + tg*2;
                if (n0 + 1 < POSE_) {
                    size_t o0 = ((size_t)b*S_ + t)*POSE_ + n0;
                    size_t o1 = ((size_t)(b+8)*S_ + t)*POSE_ + n0;
                    float2 e0 = *(const float2*)(encp + o0);
                    float2 e1 = *(const float2*)(encp + o1);
                    *(float2*)(outbuf + o0) = make_float2(s0 + e0.x, s1 + e0.y);
                    *(float2*)(outbuf + o1) = make_float2(s2 + e1.x, s3 + e1.y);
                }
            }
            __syncthreads();
            if (tid == 0) st_rel(&g_oflag[ob*8], (unsigned)(t+1));
        }
    }
#undef WAIT_H
#undef A_LOAD2
#undef HBS_COPY
}

extern "C" void kernel_launch(void* const* d_in, const int* in_sizes, int n_in,
                              void* d_out, int out_size)
{
    (void)in_sizes; (void)n_in; (void)out_size;
    const float* src_seq = (const float*)d_in[0];
    const int*   src_pos = (const int*)  d_in[1];
    const float* tgt_seq = (const float*)d_in[2];
    const float* vec_h   = (const float*)d_in[3];
    const float* vec_c   = (const float*)d_in[4];
    const float* dec0    = (const float*)d_in[5];
    const float* emb_W   = (const float*)d_in[6];
    const float* emb_b   = (const float*)d_in[7];
    const float* pos_t   = (const float*)d_in[8];
    const float* Wq      = (const float*)d_in[9];
    const float* Wk      = (const float*)d_in[10];
    const float* Wv      = (const float*)d_in[11];
    const float* Wo      = (const float*)d_in[12];
    const float* ln1g    = (const float*)d_in[13];
    const float* ln1b    = (const float*)d_in[14];
    const float* fW1     = (const float*)d_in[15];
    const float* fb1     = (const float*)d_in[16];
    const float* fW2     = (const float*)d_in[17];
    const float* fb2     = (const float*)d_in[18];
    const float* ln2g    = (const float*)d_in[19];
    const float* ln2b    = (const float*)d_in[20];
    const float* lWx     = (const float*)d_in[21];
    const float* lWh     = (const float*)d_in[22];
    const float* lb      = (const float*)d_in[23];
    const float* outW    = (const float*)d_in[24];
    const float* outb    = (const float*)d_in[25];
    const int*   ep      = (const int*)  d_in[26];
    float* out = (float*)d_out;

    void *px,*pq,*pk,*pv,*po,*pr1,*px2,*ph1,*pt2,*penc,*pxwx,*pencp,*phb,*pwhb,*pwxb,*powb,*pap,*pwp;
    cudaGetSymbolAddress(&px,  g_x);   cudaGetSymbolAddress(&pq,  g_q);
    cudaGetSymbolAddress(&pk,  g_k);   cudaGetSymbolAddress(&pv,  g_v);
    cudaGetSymbolAddress(&po,  g_o);   cudaGetSymbolAddress(&pr1, g_r1);
    cudaGetSymbolAddress(&px2, g_x2);  cudaGetSymbolAddress(&ph1, g_h1);
    cudaGetSymbolAddress(&pt2, g_t2);  cudaGetSymbolAddress(&penc,g_enc);
    cudaGetSymbolAddress(&pxwx,g_xwx); cudaGetSymbolAddress(&pencp,g_encp);
    cudaGetSymbolAddress(&phb, g_hb);  cudaGetSymbolAddress(&pwhb,g_whb);
    cudaGetSymbolAddress(&pwxb,g_wxb); cudaGetSymbolAddress(&powb,g_owb);
    cudaGetSymbolAddress(&pap, g_ap);  cudaGetSymbolAddress(&pwp, g_wp);
    float *X=(float*)px, *Qb=(float*)pq, *Kb=(float*)pk, *Vb=(float*)pv, *Ob=(float*)po;
    float *R1=(float*)pr1, *X2=(float*)px2, *H1=(float*)ph1, *T2=(float*)pt2, *ENC=(float*)penc;
    float *XWX=(float*)pxwx, *ENCP=(float*)pencp;
    unsigned *HB=(unsigned*)phb;
    uint2 *WHB=(uint2*)pwhb, *WXB=(uint2*)pwxb, *OWB=(uint2*)powb;
    uint2 *AP=(uint2*)pap, *WP=(uint2*)pwp;

    const int GSM = 2*GSTAGE_*8;
    cudaFuncSetAttribute(attn_k, cudaFuncAttributeMaxDynamicSharedMemorySize, KSPAN_*KROW_*4);
    cudaFuncSetAttribute(dec_k,  cudaFuncAttributeMaxDynamicSharedMemorySize, DEC_SMEM_);
    cudaFuncSetAttribute(gemmp_k<EPI_NONE>,      cudaFuncAttributeMaxDynamicSharedMemorySize, GSM);
    cudaFuncSetAttribute(gemmp_k<EPI_POS>,       cudaFuncAttributeMaxDynamicSharedMemorySize, GSM);
    cudaFuncSetAttribute(gemmp_k<EPI_ADD>,       cudaFuncAttributeMaxDynamicSharedMemorySize, GSM);
    cudaFuncSetAttribute(gemmp_k<EPI_BIAS_RELU>, cudaFuncAttributeMaxDynamicSharedMemorySize, GSM);
    cudaFuncSetAttribute(gemmp_k<EPI_BIAS_ADD>,  cudaFuncAttributeMaxDynamicSharedMemorySize, GSM);
    cudaFuncSetAttribute(gemmp_k<EPI_BIAS>,      cudaFuncAttributeMaxDynamicSharedMemorySize, GSM);

    dim3 gD((D_+63)/64, M_/128), gF((FFN_+63)/64, M_/128);
    dim3 gG4((G4_+63)/64, M_/128), gP((POSE_+63)/64, M_/128);

#define PACKA(src, KP) packa_k<<<((M_*(KP))+255)/256,256>>>((src), AP, M_*(KP))
#define PACKW(src, KP, N) packw_k<<<(((KP)*(N))+255)/256,256>>>((src), WP, (KP), (N))

    PACKA(src_seq, 219); PACKW(emb_W, 219, D_);
    gemmp_k<EPI_POS><<<gD,256,GSM>>>(AP, 219, WP, X, D_, emb_b, nullptr, pos_t, src_pos);
    PACKA(X, 400);
    PACKW(Wq, 400, D_);
    gemmp_k<EPI_NONE><<<gD,256,GSM>>>(AP, 400, WP, Qb, D_, nullptr, nullptr, nullptr, nullptr);
    PACKW(Wk, 400, D_);
    gemmp_k<EPI_NONE><<<gD,256,GSM>>>(AP, 400, WP, Kb, D_, nullptr, nullptr, nullptr, nullptr);
    PACKW(Wv, 400, D_);
    gemmp_k<EPI_NONE><<<gD,256,GSM>>>(AP, 400, WP, Vb, D_, nullptr, nullptr, nullptr, nullptr);
    attn_k<<<dim3(S_/QT_, H_, B_),128,KSPAN_*KROW_*4>>>(Qb, Kb, Vb, Ob);
    PACKA(Ob, 400); PACKW(Wo, 400, D_);
    gemmp_k<EPI_ADD><<<gD,256,GSM>>>(AP, 400, WP, R1, D_, nullptr, X, nullptr, nullptr);
    ln_k<<<M_,256>>>(R1, X2, ln1g, ln1b);
    PACKA(X2, 400); PACKW(fW1, 400, FFN_);
    gemmp_k<EPI_BIAS_RELU><<<gF,256,GSM>>>(AP, 400, WP, H1, FFN_, fb1, nullptr, nullptr, nullptr);
    PACKA(H1, 512); PACKW(fW2, 512, D_);
    gemmp_k<EPI_BIAS_ADD><<<gD,256,GSM>>>(AP, 512, WP, T2, D_, fb2, X2, nullptr, nullptr);
    ln_k<<<M_,256>>>(T2, ENC, ln2g, ln2b);

    PACKA(tgt_seq, 137); PACKW(lWx, 137, G4_);
    gemmp_k<EPI_NONE><<<gG4,256,GSM>>>(AP, 137, WP, XWX, G4_, nullptr, nullptr, nullptr, nullptr);
    PACKA(ENC, 400); PACKW(outW + (size_t)HID_*POSE_, 400, POSE_);
    gemmp_k<EPI_BIAS><<<gP,256,GSM>>>(AP, 400, WP, ENCP, POSE_, outb, nullptr, nullptr, nullptr);

    pack_whb_k<<<(GATEB_*4*64*32+255)/256,256>>>(lWh, WHB);
    pack_wxb_k<<<(GATEB_*4*18*32+255)/256,256>>>(lWx, WXB);
    pack_owb_k<<<(OGRP_*64*32+255)/256,256>>>(outW, OWB);
    init_dec_k<<<(HBTOT_+255)/256,256>>>(vec_h, HB);

    dec_k<<<NBDEC_,128,DEC_SMEM_>>>(WHB, WXB, OWB, lb, XWX, ENCP, vec_c, dec0, HB, out, ep);
#undef PACKA
#undef PACKW
}

// round 16
// speedup vs baseline: 1.7980x; 1.0758x over previous
#include <cuda_runtime.h>
#include <cuda_bf16.h>
#include <math.h>

#define B_ 16
#define S_ 512
#define FRAME_ 438
#define D_ 800
#define H_ 8
#define DH_ 100
#define FFN_ 1024
#define HID_ 1024
#define POSE_ 274
#define WIN_ 100
#define M_ (B_*S_)
#define G4_ (4*HID_)
#define QT_ 8
#define KSPAN_ (2*WIN_+QT_)
#define KROW_ 101
#define GATEB_ 128
#define OUTB_ 18
#define NBDEC_ (GATEB_+OUTB_)
#define HBW_ 516
#define HBTOT_ (16*HBW_)
#define XBW_ 148
#define OGRP_ 35
#define GSTAGE_ (128*17 + 16*65)
#define WSM_OFF_ 12672
#define DEC_SMEM_ 134656

__device__ float g_x[M_*D_];
__device__ float g_q[M_*D_];
__device__ float g_k[M_*D_];
__device__ float g_v[M_*D_];
__device__ float g_o[M_*D_];
__device__ float g_r1[M_*D_];
__device__ float g_x2[M_*D_];
__device__ float g_h1[M_*FFN_];
__device__ float g_t2[M_*D_];
__device__ float g_enc[M_*D_];
__device__ float g_xwx[(size_t)M_*G4_];
__device__ float g_encp[M_*POSE_];
__device__ __align__(16) unsigned g_hb[4*HBTOT_];
__device__ __align__(16) uint2 g_whb[(size_t)GATEB_*4*64*32];
__device__ __align__(16) uint2 g_wxb[(size_t)GATEB_*4*18*32];
__device__ __align__(16) uint2 g_owb[(size_t)OGRP_*64*32];
__device__ uint2 g_ap[(size_t)M_*512];
__device__ uint2 g_wp[600000];
__device__ unsigned g_hflag[GATEB_*8];
__device__ unsigned g_oflag[OUTB_*8];

enum { EPI_NONE=0, EPI_POS=1, EPI_ADD=2, EPI_BIAS_RELU=3, EPI_BIAS_ADD=4, EPI_BIAS=5 };

__device__ __forceinline__ unsigned packbf(float a, float b) {
    __nv_bfloat162 t = __float22bfloat162_rn(make_float2(a, b));
    return *(unsigned*)&t;
}
__device__ __forceinline__ float bfres(float x, float& hi) {
    __nv_bfloat16 h = __float2bfloat16_rn(x);
    hi = __bfloat162float(h);
    return x - hi;
}
__device__ __forceinline__ void mma_bf16(float* d, const unsigned* a, const unsigned* b) {
    asm volatile("mma.sync.aligned.m16n8k16.row.col.f32.bf16.bf16.f32 "
        "{%0,%1,%2,%3}, {%4,%5,%6,%7}, {%8,%9}, {%0,%1,%2,%3};"
        : "+f"(d[0]), "+f"(d[1]), "+f"(d[2]), "+f"(d[3])
        : "r"(a[0]), "r"(a[1]), "r"(a[2]), "r"(a[3]), "r"(b[0]), "r"(b[1]));
}
__device__ __forceinline__ float tanhap(float x) {
    float y;
    asm("tanh.approx.f32 %0, %1;" : "=f"(y) : "f"(x));
    return y;
}
__device__ __forceinline__ float sigf(float x) { return 0.5f + 0.5f*tanhap(0.5f*x); }

// ---------------- split-bf16 pre-pack kernels ----------------
__global__ void packa_k(const float* __restrict__ A, uint2* __restrict__ out, int npairs)
{
    int i = blockIdx.x*256 + threadIdx.x;
    if (i < npairs) {
        float2 v = ((const float2*)A)[i];
        float h0, h1;
        float l0 = bfres(v.x, h0), l1 = bfres(v.y, h1);
        out[i] = make_uint2(packbf(h0, h1), packbf(l0, l1));
    }
}
__global__ void packw_k(const float* __restrict__ W, uint2* __restrict__ out, int KP, int Nn)
{
    int i = blockIdx.x*256 + threadIdx.x;
    if (i < KP*Nn) {
        int kp = i / Nn, n = i % Nn;
        float w0 = W[(size_t)(2*kp)*Nn + n];
        float w1 = W[(size_t)(2*kp+1)*Nn + n];
        float h0, h1;
        float l0 = bfres(w0, h0), l1 = bfres(w1, h1);
        out[i] = make_uint2(packbf(h0, h1), packbf(l0, l1));
    }
}

// ---------------- packed split-bf16 GEMM, 2-stage cp.async pipeline ----------------
template<int EPI>
__global__ __launch_bounds__(256)
void gemmp_k(const uint2* __restrict__ Ap, int KP,
             const uint2* __restrict__ Wp,
             float* __restrict__ C, int Nn,
             const float* __restrict__ bias, const float* __restrict__ addend,
             const float* __restrict__ pos_table, const int* __restrict__ pos_idx)
{
    extern __shared__ uint2 sm2[];
    int tid = threadIdx.x, lane = tid & 31, w = tid >> 5;
    int wm = w >> 1, wn = w & 1;
    int rowBase = blockIdx.y * 128, colBase = blockIdx.x * 64;
    int tg = lane & 3, qd = lane >> 2;
    int ntiles = (KP + 15) >> 4;

    float d[2][4][4];
#pragma unroll
    for (int mt = 0; mt < 2; mt++)
#pragma unroll
        for (int nt = 0; nt < 4; nt++)
#pragma unroll
            for (int i = 0; i < 4; i++) d[mt][nt][i] = 0.f;

    auto issue = [&](int ti, int s) {
        uint2* As = sm2 + s*GSTAGE_;
        uint2* Ws = As + 128*17;
        int k0p = ti*16;
#pragma unroll
        for (int ii = 0; ii < 8; ii++) {
            int i = ii*256 + tid;
            int row = i >> 4, kw = i & 15, gkp = k0p + kw;
            uint2* dst = &As[row*17 + kw];
            if (gkp < KP) {
                unsigned da = (unsigned)__cvta_generic_to_shared(dst);
                asm volatile("cp.async.ca.shared.global [%0], [%1], 8;"
                             :: "r"(da), "l"(&Ap[(size_t)(rowBase+row)*KP + gkp]));
            } else *dst = make_uint2(0u, 0u);
        }
#pragma unroll
        for (int ii = 0; ii < 4; ii++) {
            int i = ii*256 + tid;
            int n = i & 63, kw = i >> 6;
            int gkp = k0p + kw, gn = colBase + n;
            uint2* dst = &Ws[kw*65 + n];
            if (gkp < KP && gn < Nn) {
                unsigned da = (unsigned)__cvta_generic_to_shared(dst);
                asm volatile("cp.async.ca.shared.global [%0], [%1], 8;"
                             :: "r"(da), "l"(&Wp[(size_t)gkp*Nn + gn]));
            } else *dst = make_uint2(0u, 0u);
        }
        asm volatile("cp.async.commit_group;");
    };

    issue(0, 0);
    for (int ti = 0; ti < ntiles; ti++) {
        if (ti + 1 < ntiles) {
            issue(ti+1, (ti+1) & 1);
            asm volatile("cp.async.wait_group 1;");
        } else {
            asm volatile("cp.async.wait_group 0;");
        }
        __syncthreads();
        uint2* Asm = sm2 + (ti & 1)*GSTAGE_;
        uint2* Wsm = Asm + 128*17;
#pragma unroll
        for (int kt = 0; kt < 2; kt++) {
            unsigned ah[2][4], al[2][4], bh[4][2], bl[4][2];
#pragma unroll
            for (int mt = 0; mt < 2; mt++) {
                int base = (wm*32 + mt*16 + qd)*17 + kt*8 + tg;
                uint2 q0 = Asm[base],     q1 = Asm[base + 8*17];
                uint2 q2 = Asm[base + 4], q3 = Asm[base + 8*17 + 4];
                ah[mt][0]=q0.x; ah[mt][1]=q1.x; ah[mt][2]=q2.x; ah[mt][3]=q3.x;
                al[mt][0]=q0.y; al[mt][1]=q1.y; al[mt][2]=q2.y; al[mt][3]=q3.y;
            }
#pragma unroll
            for (int nt = 0; nt < 4; nt++) {
                int nn = wn*32 + nt*8 + qd;
                int kb = kt*8 + tg;
                uint2 q0 = Wsm[kb*65 + nn], q1 = Wsm[(kb+4)*65 + nn];
                bh[nt][0]=q0.x; bh[nt][1]=q1.x;
                bl[nt][0]=q0.y; bl[nt][1]=q1.y;
            }
#pragma unroll
            for (int mt = 0; mt < 2; mt++)
#pragma unroll
                for (int nt = 0; nt < 4; nt++) {
                    mma_bf16(d[mt][nt], ah[mt], bh[nt]);
                    mma_bf16(d[mt][nt], ah[mt], bl[nt]);
                    mma_bf16(d[mt][nt], al[mt], bh[nt]);
                }
        }
        __syncthreads();
    }

#pragma unroll
    for (int mt = 0; mt < 2; mt++) {
#pragma unroll
        for (int nt = 0; nt < 4; nt++) {
#pragma unroll
            for (int half = 0; half < 2; half++) {
                int row = rowBase + wm*32 + mt*16 + qd + half*8;
                int col = colBase + wn*32 + nt*8 + tg*2;
                if (col < Nn) {
                    float v0 = d[mt][nt][half*2+0];
                    float v1 = d[mt][nt][half*2+1];
                    if (EPI == EPI_POS) {
                        size_t pb = (size_t)pos_idx[row]*Nn + col;
                        v0 += bias[col]   + pos_table[pb];
                        v1 += bias[col+1] + pos_table[pb+1];
                    } else if (EPI == EPI_ADD) {
                        size_t ab = (size_t)row*Nn + col;
                        v0 += addend[ab]; v1 += addend[ab+1];
                    } else if (EPI == EPI_BIAS_RELU) {
                        v0 += bias[col]; v1 += bias[col+1];
                        v0 = v0 > 0.f ? v0 : 0.f; v1 = v1 > 0.f ? v1 : 0.f;
                    } else if (EPI == EPI_BIAS_ADD) {
                        size_t ab = (size_t)row*Nn + col;
                        v0 += bias[col] + addend[ab]; v1 += bias[col+1] + addend[ab+1];
                    } else if (EPI == EPI_BIAS) {
                        v0 += bias[col]; v1 += bias[col+1];
                    }
                    *(float2*)(C + (size_t)row*Nn + col) = make_float2(v0, v1);
                }
            }
        }
    }
}

__global__ __launch_bounds__(256)
void ln_k(const float* __restrict__ in, float* __restrict__ out,
          const float* __restrict__ g, const float* __restrict__ b)
{
    __shared__ float buf[D_];
    __shared__ float red[256];
    int row = blockIdx.x, tid = threadIdx.x;
    float s = 0.f;
    for (int i = tid; i < D_; i += 256) { float v = in[(size_t)row*D_ + i]; buf[i] = v; s += v; }
    red[tid] = s; __syncthreads();
    for (int st = 128; st > 0; st >>= 1) { if (tid < st) red[tid] += red[tid+st]; __syncthreads(); }
    float mean = red[0] / (float)D_;
    __syncthreads();
    float ss = 0.f;
    for (int i = tid; i < D_; i += 256) { float dd = buf[i]-mean; ss += dd*dd; }
    red[tid] = ss; __syncthreads();
    for (int st = 128; st > 0; st >>= 1) { if (tid < st) red[tid] += red[tid+st]; __syncthreads(); }
    float inv = rsqrtf(red[0]/(float)D_ + 1e-6f);
    for (int i = tid; i < D_; i += 256)
        out[(size_t)row*D_ + i] = (buf[i]-mean)*inv*g[i] + b[i];
}

__global__ __launch_bounds__(128)
void attn_k(const float* __restrict__ Q, const float* __restrict__ K,
            const float* __restrict__ V, float* __restrict__ O)
{
    extern __shared__ float ks[];
    __shared__ float qs[QT_*DH_];
    __shared__ float sc[QT_][KSPAN_];
    __shared__ float invs[QT_];
    int tid = threadIdx.x;
    int q0 = blockIdx.x * QT_, h = blockIdx.y, b = blockIdx.z;
    int kl = max(0, q0 - WIN_);
    int kh = min(S_-1, q0 + QT_-1 + WIN_);
    int nk = kh - kl + 1;
    size_t base = ((size_t)b*S_)*D_ + (size_t)h*DH_;

    for (int idx = tid; idx < QT_*DH_; idx += 128) {
        int qi = idx / DH_, dd = idx % DH_;
        qs[idx] = Q[base + (size_t)(q0+qi)*D_ + dd];
    }
    for (int idx = tid; idx < nk*DH_; idx += 128) {
        int kk = idx / DH_, dd = idx % DH_;
        ks[kk*KROW_ + dd] = K[base + (size_t)(kl+kk)*D_ + dd];
    }
    __syncthreads();

    for (int pid = tid; pid < QT_*nk; pid += 128) {
        int kk = pid % nk, qi = pid / nk;
        int qq = q0 + qi, kp = kl + kk;
        float v;
        if (kp >= qq - WIN_ && kp <= qq + WIN_) {
            float dd = 0.f;
            for (int i = 0; i < DH_; i++) dd += qs[qi*DH_ + i]*ks[kk*KROW_ + i];
            v = dd * 0.1f;
        } else v = -1e30f;
        sc[qi][kk] = v;
    }
    __syncthreads();
    {
        int qi = tid >> 4, l = tid & 15;
        float m = -1e30f;
        for (int kk = l; kk < nk; kk += 16) m = fmaxf(m, sc[qi][kk]);
#pragma unroll
        for (int s2 = 8; s2 > 0; s2 >>= 1) m = fmaxf(m, __shfl_xor_sync(0xffffffffu, m, s2, 16));
        float ssum = 0.f;
        for (int kk = l; kk < nk; kk += 16) { float e = __expf(sc[qi][kk]-m); sc[qi][kk] = e; ssum += e; }
#pragma unroll
        for (int s2 = 8; s2 > 0; s2 >>= 1) ssum += __shfl_xor_sync(0xffffffffu, ssum, s2, 16);
        if (l == 0) invs[qi] = 1.f / ssum;
    }
    __syncthreads();
    if (tid < DH_) {
        float acc[QT_];
#pragma unroll
        for (int qi = 0; qi < QT_; qi++) acc[qi] = 0.f;
        for (int kk = 0; kk < nk; kk++) {
            float vv = V[base + (size_t)(kl+kk)*D_ + tid];
#pragma unroll
            for (int qi = 0; qi < QT_; qi++) acc[qi] += sc[qi][kk]*vv;
        }
#pragma unroll
        for (int qi = 0; qi < QT_; qi++)
            O[base + (size_t)(q0+qi)*D_ + tid] = acc[qi]*invs[qi];
    }
}

// ---------------- decoder pack kernels: paired-kt uint4 layout ----------------
__global__ void pack_whb_k(const float* __restrict__ Wh, uint2* __restrict__ out)
{
    size_t idx = (size_t)blockIdx.x*256 + threadIdx.x;
    if (idx >= (size_t)GATEB_*4*64*32) return;
    int lane = idx & 31;
    int kt = (idx >> 5) & 63;
    int q  = (idx >> 11) & 3;
    int g  = idx >> 13;
    int j  = q*1024 + g*8 + (lane >> 2);
    int k0 = kt*16 + (lane & 3)*2;
    float w0 = Wh[(size_t)k0*G4_ + j],     w1 = Wh[(size_t)(k0+1)*G4_ + j];
    float w2 = Wh[(size_t)(k0+8)*G4_ + j], w3 = Wh[(size_t)(k0+9)*G4_ + j];
    size_t o = ((((size_t)g*4 + q)*32 + (kt>>1))*32 + lane)*2 + (kt & 1);
    out[o] = make_uint2(packbf(w0,w1), packbf(w2,w3));
}

__global__ void pack_wxb_k(const float* __restrict__ Wx, uint2* __restrict__ out)
{
    size_t idx = (size_t)blockIdx.x*256 + threadIdx.x;
    if (idx >= (size_t)GATEB_*4*18*32) return;
    int lane = idx & 31;
    size_t r = idx >> 5;
    int kt = r % 18;
    int q  = (r / 18) & 3;
    int g  = r / 72;
    int j  = q*1024 + g*8 + (lane >> 2);
    int k0 = kt*16 + (lane & 3)*2;
    float w0 = (k0   < POSE_) ? Wx[(size_t)k0*G4_ + j]     : 0.f;
    float w1 = (k0+1 < POSE_) ? Wx[(size_t)(k0+1)*G4_ + j] : 0.f;
    float w2 = (k0+8 < POSE_) ? Wx[(size_t)(k0+8)*G4_ + j] : 0.f;
    float w3 = (k0+9 < POSE_) ? Wx[(size_t)(k0+9)*G4_ + j] : 0.f;
    size_t o = ((((size_t)g*4 + q)*9 + (kt>>1))*32 + lane)*2 + (kt & 1);
    out[o] = make_uint2(packbf(w0,w1), packbf(w2,w3));
}

__global__ void pack_owb_k(const float* __restrict__ Wo, uint2* __restrict__ out)
{
    int idx = blockIdx.x*256 + threadIdx.x;
    if (idx >= OGRP_*64*32) return;
    int lane = idx & 31;
    int kt = (idx >> 5) & 63;
    int grp = idx >> 11;
    int n  = grp*8 + (lane >> 2);
    int k0 = kt*16 + (lane & 3)*2;
    float w0=0.f, w1=0.f, w2=0.f, w3=0.f;
    if (n < POSE_) {
        w0 = Wo[(size_t)k0*POSE_ + n];     w1 = Wo[(size_t)(k0+1)*POSE_ + n];
        w2 = Wo[(size_t)(k0+8)*POSE_ + n]; w3 = Wo[(size_t)(k0+9)*POSE_ + n];
    }
    size_t o = (((size_t)grp*32 + (kt>>1))*32 + lane)*2 + (kt & 1);
    out[o] = make_uint2(packbf(w0,w1), packbf(w2,w3));
}

__global__ void init_dec_k(const float* __restrict__ vh, unsigned* __restrict__ hb)
{
    int i = blockIdx.x*256 + threadIdx.x;
    if (i < GATEB_*8) g_hflag[i] = 0;
    if (i < OUTB_*8)  g_oflag[i] = 0;
    if (i < HBTOT_) {
        int b = i / HBW_, kw = i % HBW_;
        int k0 = kw*2;
        float v0 = (k0   < HID_) ? vh[b*HID_ + k0]   : 0.f;
        float v1 = (k0+1 < HID_) ? vh[b*HID_ + k0+1] : 0.f;
        hb[3*HBTOT_ + i] = packbf(v0, v1);
    }
}

__device__ __forceinline__ unsigned ld_acq(const unsigned* p) {
    unsigned v;
    asm volatile("ld.acquire.gpu.global.u32 %0, [%1];" : "=r"(v) : "l"(p) : "memory");
    return v;
}
__device__ __forceinline__ void st_rel(unsigned* p, unsigned v) {
    asm volatile("st.release.gpu.global.u32 [%0], %1;" :: "l"(p), "r"(v) : "memory");
}

// grid = 146 x 128. Gates 0..127 (8 units each); out 128..145.
// Weights cached in SMEM; LSTM pointwise parallel over all 128 threads (hw tanh).
__global__ __launch_bounds__(128)
void dec_k(const uint2* __restrict__ WHB, const uint2* __restrict__ WXB,
           const uint2* __restrict__ OWB, const float* __restrict__ lb,
           const float* __restrict__ xwx, const float* __restrict__ encp,
           const float* __restrict__ vec_c, const float* __restrict__ dec0,
           unsigned* __restrict__ hb, float* __restrict__ outbuf,
           const int* __restrict__ ep)
{
    extern __shared__ unsigned smu[];
    unsigned* hbs = smu;
    unsigned* xbs = smu + HBTOT_;
    float*    red = (float*)(smu + HBTOT_ + 16*XBW_);
    float*    redo = (float*)(smu + HBTOT_);
    uint4*    wsm4 = (uint4*)(smu + WSM_OFF_);

    int tid = threadIdx.x, bx = blockIdx.x;
    int lane = tid & 31, w = tid >> 5;
    int b = lane >> 2, tg = lane & 3;
    bool isGate = bx < GATEB_;
    int p = (int)((double)(*ep) * 0.01);   // double required: fp32 100*0.01 -> 0
    int per = p + 10;
    const uint4* WHB4 = (const uint4*)WHB;
    const uint4* WXB4 = (const uint4*)WXB;
    const uint4* OWB4 = (const uint4*)OWB;

#define HBS_COPY(hrp) { \
        const uint4* srcv = (const uint4*)(hrp); uint4* dstv = (uint4*)hbs; \
        for (int i = tid; i < HBTOT_/4; i += 128) dstv[i] = __ldcg(srcv + i); }

#define A_LOAD2(buf, stride, ktv) { \
        int wA = b*(stride) + (ktv)*8 + tg; \
        a0[0] = (buf)[wA];     a0[1] = (buf)[wA + 8*(stride)]; \
        a0[2] = (buf)[wA + 4]; a0[3] = (buf)[wA + 8*(stride) + 4]; \
        wA += 8; \
        a1[0] = (buf)[wA];     a1[1] = (buf)[wA + 8*(stride)]; \
        a1[2] = (buf)[wA + 4]; a1[3] = (buf)[wA + 8*(stride) + 4]; }

#define WAIT_H(needv) { \
        unsigned _need = (unsigned)(needv); \
        for (;;) { \
            unsigned mn = 0xffffffffu; \
            _Pragma("unroll") \
            for (int ii = 0; ii < 4; ii++) \
                mn = min(mn, ld_acq(&g_hflag[(lane + ii*32)*8])); \
            mn = __reduce_min_sync(0xffffffffu, mn); \
            if (mn >= _need) break; \
        } }

    if (isGate) {
        {
            const uint4* src = WHB4 + (size_t)bx*4096;
            for (int i = tid; i < 4096; i += 128) wsm4[i] = src[i];
            const uint4* srcx = WXB4 + (size_t)bx*1152;
            for (int i = tid; i < 1152; i += 128) wsm4[4096 + i] = srcx[i];
        }
        // per-thread LSTM state: thread tid = u3*16 + b3 handles (unit u3, batch b3)
        int u3 = tid >> 4, b3 = tid & 15;
        int gu = bx*8 + u3;
        int tgp = u3 >> 1;
        int ep2 = ((b3 >> 3) << 1) | (u3 & 1);
        int lanep = (b3 & 7)*4 + tgp;
        float c = vec_c[b3*HID_ + gu];
        float lbv[4];
#pragma unroll
        for (int q = 0; q < 4; q++) lbv[q] = lb[q*1024 + gu];
        __syncthreads();

        for (int t = 0; t < S_; t++) {
            bool sampled = (t % per) < p;
            const unsigned* hr = hb + ((t+3)&3)*(size_t)HBTOT_;
            unsigned*       hw = hb + (t&3)*(size_t)HBTOT_;

            float xwr[4];
            if (!sampled) {
#pragma unroll
                for (int q = 0; q < 4; q++)
                    xwr[q] = __ldcg(xwx + ((size_t)b3*S_ + t)*G4_ + q*1024 + gu);
            }

            if (w == 1 && t > 0) WAIT_H(t);
            if (w == 2) {
                unsigned needO = sampled ? (unsigned)t : (t >= 4 ? (unsigned)(t-3) : 0u);
                if (needO) {
                    for (;;) {
                        unsigned v = (lane < OUTB_) ? ld_acq(&g_oflag[lane*8]) : 0xffffffffu;
                        unsigned mn = __reduce_min_sync(0xffffffffu, v);
                        if (mn >= needO) break;
                    }
                }
            }
            __syncthreads();

            HBS_COPY(hr);
            if (sampled) {
                const float* xsrc0 = (t == 0) ? dec0 : (outbuf + (size_t)(t-1)*POSE_);
                size_t bstride = (t == 0) ? (size_t)POSE_ : (size_t)S_*POSE_;
                for (int i = tid; i < 16*(XBW_-4); i += 128) {
                    int b2 = i / (XBW_-4), kw = i % (XBW_-4);
                    int k0 = kw*2;
                    const float* sp = xsrc0 + (size_t)b2*bstride;
                    float v0 = (k0   < POSE_) ? __ldcg(sp + k0)   : 0.f;
                    float v1 = (k0+1 < POSE_) ? __ldcg(sp + k0+1) : 0.f;
                    xbs[b2*XBW_ + kw] = packbf(v0, v1);
                }
            }
            __syncthreads();

            float d[4][4];
#pragma unroll
            for (int q = 0; q < 4; q++)
#pragma unroll
                for (int i = 0; i < 4; i++) d[q][i] = 0.f;
            unsigned a0[4], a1[4];
#pragma unroll 2
            for (int kt8 = 0; kt8 < 8; kt8++) {
                int kt2 = w*8 + kt8;
                A_LOAD2(hbs, HBW_, kt2*2);
#pragma unroll
                for (int q = 0; q < 4; q++) {
                    uint4 bb = wsm4[(q*32 + kt2)*32 + lane];
                    unsigned be[2] = {bb.x, bb.y}, bo[2] = {bb.z, bb.w};
                    mma_bf16(d[q], a0, be);
                    mma_bf16(d[q], a1, bo);
                }
            }
            if (sampled) {
                int e2 = min(9, w*3 + 3);
                for (int kt2 = w*3; kt2 < e2; kt2++) {
                    A_LOAD2(xbs, XBW_, kt2*2);
#pragma unroll
                    for (int q = 0; q < 4; q++) {
                        uint4 bb = wsm4[4096 + (q*9 + kt2)*32 + lane];
                        unsigned be[2] = {bb.x, bb.y}, bo[2] = {bb.z, bb.w};
                        mma_bf16(d[q], a0, be);
                        mma_bf16(d[q], a1, bo);
                    }
                }
            }
            {
                float* myr = red + (w*32 + lane)*16;
#pragma unroll
                for (int q = 0; q < 4; q++)
#pragma unroll
                    for (int i = 0; i < 4; i++) myr[q*4+i] = d[q][i];
            }
            __syncthreads();

            // parallel pointwise: every thread one (unit, batch) pair
            {
                float gate[4];
#pragma unroll
                for (int q = 0; q < 4; q++) {
                    float s = red[(0*32 + lanep)*16 + q*4 + ep2]
                            + red[(1*32 + lanep)*16 + q*4 + ep2]
                            + red[(2*32 + lanep)*16 + q*4 + ep2]
                            + red[(3*32 + lanep)*16 + q*4 + ep2];
                    s += lbv[q];
                    if (!sampled) s += xwr[q];
                    gate[q] = s;
                }
                float cv = sigf(gate[1])*c + sigf(gate[0])*tanhap(gate[2]);
                float h = sigf(gate[3])*tanhap(cv);
                c = cv;
                float hp = __shfl_xor_sync(0xffffffffu, h, 16);
                if (!(tid & 16))
                    hw[b3*HBW_ + bx*4 + tgp] = packbf(h, hp);
            }
            __syncthreads();
            if (tid == 0) st_rel(&g_hflag[bx*8], (unsigned)(t+1));
        }
    } else {
        int ob = bx - GATEB_;
        int grp = ob*2 + (w >> 1);
        int kh = w & 1;
        bool ovalid = (grp < OGRP_);
        {
            size_t base0 = (size_t)(ob*2)*1024;
            for (int i = tid; i < 2048; i += 128) {
                size_t gi = base0 + i;
                wsm4[i] = (gi < (size_t)OGRP_*1024) ? OWB4[gi] : make_uint4(0u,0u,0u,0u);
            }
        }
        __syncthreads();
        for (int t = 0; t < S_; t++) {
            if (w == 0) WAIT_H(t+1);
            __syncthreads();
            const unsigned* hrp = hb + (t&3)*(size_t)HBTOT_;
            HBS_COPY(hrp);
            __syncthreads();
            float d[4] = {0.f,0.f,0.f,0.f};
            unsigned a0[4], a1[4];
            if (ovalid) {
#pragma unroll 2
                for (int kt16 = 0; kt16 < 16; kt16++) {
                    int kt2 = kh*16 + kt16;
                    A_LOAD2(hbs, HBW_, kt2*2);
                    uint4 bb = wsm4[((w>>1)*32 + kt2)*32 + lane];
                    unsigned be[2] = {bb.x, bb.y}, bo[2] = {bb.z, bb.w};
                    mma_bf16(d, a0, be);
                    mma_bf16(d, a1, bo);
                }
            }
            float* myr = redo + (w*32 + lane)*4;
            myr[0]=d[0]; myr[1]=d[1]; myr[2]=d[2]; myr[3]=d[3];
            __syncthreads();
            if ((w & 1) == 0 && ovalid) {
                float s0 = redo[(w*32+lane)*4+0] + redo[((w+1)*32+lane)*4+0];
                float s1 = redo[(w*32+lane)*4+1] + redo[((w+1)*32+lane)*4+1];
                float s2 = redo[(w*32+lane)*4+2] + redo[((w+1)*32+lane)*4+2];
                float s3 = redo[(w*32+lane)*4+3] + redo[((w+1)*32+lane)*4+3];
                int n0 = grp*8 + tg*2;
                if (n0 + 1 < POSE_) {
                    size_t o0 = ((size_t)b*S_ + t)*POSE_ + n0;
                    size_t o1 = ((size_t)(b+8)*S_ + t)*POSE_ + n0;
                    float2 e0 = *(const float2*)(encp + o0);
                    float2 e1 = *(const float2*)(encp + o1);
                    *(float2*)(outbuf + o0) = make_float2(s0 + e0.x, s1 + e0.y);
                    *(float2*)(outbuf + o1) = make_float2(s2 + e1.x, s3 + e1.y);
                }
            }
            __syncthreads();
            if (tid == 0) st_rel(&g_oflag[ob*8], (unsigned)(t+1));
        }
    }
#undef WAIT_H
#undef A_LOAD2
#undef HBS_COPY
}

extern "C" void kernel_launch(void* const* d_in, const int* in_sizes, int n_in,
                              void* d_out, int out_size)
{
    (void)in_sizes; (void)n_in; (void)out_size;
    const float* src_seq = (const float*)d_in[0];
    const int*   src_pos = (const int*)  d_in[1];
    const float* tgt_seq = (const float*)d_in[2];
    const float* vec_h   = (const float*)d_in[3];
    const float* vec_c   = (const float*)d_in[4];
    const float* dec0    = (const float*)d_in[5];
    const float* emb_W   = (const float*)d_in[6];
    const float* emb_b   = (const float*)d_in[7];
    const float* pos_t   = (const float*)d_in[8];
    const float* Wq      = (const float*)d_in[9];
    const float* Wk      = (const float*)d_in[10];
    const float* Wv      = (const float*)d_in[11];
    const float* Wo      = (const float*)d_in[12];
    const float* ln1g    = (const float*)d_in[13];
    const float* ln1b    = (const float*)d_in[14];
    const float* fW1     = (const float*)d_in[15];
    const float* fb1     = (const float*)d_in[16];
    const float* fW2     = (const float*)d_in[17];
    const float* fb2     = (const float*)d_in[18];
    const float* ln2g    = (const float*)d_in[19];
    const float* ln2b    = (const float*)d_in[20];
    const float* lWx     = (const float*)d_in[21];
    const float* lWh     = (const float*)d_in[22];
    const float* lb      = (const float*)d_in[23];
    const float* outW    = (const float*)d_in[24];
    const float* outb    = (const float*)d_in[25];
    const int*   ep      = (const int*)  d_in[26];
    float* out = (float*)d_out;

    void *px,*pq,*pk,*pv,*po,*pr1,*px2,*ph1,*pt2,*penc,*pxwx,*pencp,*phb,*pwhb,*pwxb,*powb,*pap,*pwp;
    cudaGetSymbolAddress(&px,  g_x);   cudaGetSymbolAddress(&pq,  g_q);
    cudaGetSymbolAddress(&pk,  g_k);   cudaGetSymbolAddress(&pv,  g_v);
    cudaGetSymbolAddress(&po,  g_o);   cudaGetSymbolAddress(&pr1, g_r1);
    cudaGetSymbolAddress(&px2, g_x2);  cudaGetSymbolAddress(&ph1, g_h1);
    cudaGetSymbolAddress(&pt2, g_t2);  cudaGetSymbolAddress(&penc,g_enc);
    cudaGetSymbolAddress(&pxwx,g_xwx); cudaGetSymbolAddress(&pencp,g_encp);
    cudaGetSymbolAddress(&phb, g_hb);  cudaGetSymbolAddress(&pwhb,g_whb);
    cudaGetSymbolAddress(&pwxb,g_wxb); cudaGetSymbolAddress(&powb,g_owb);
    cudaGetSymbolAddress(&pap, g_ap);  cudaGetSymbolAddress(&pwp, g_wp);
    float *X=(float*)px, *Qb=(float*)pq, *Kb=(float*)pk, *Vb=(float*)pv, *Ob=(float*)po;
    float *R1=(float*)pr1, *X2=(float*)px2, *H1=(float*)ph1, *T2=(float*)pt2, *ENC=(float*)penc;
    float *XWX=(float*)pxwx, *ENCP=(float*)pencp;
    unsigned *HB=(unsigned*)phb;
    uint2 *WHB=(uint2*)pwhb, *WXB=(uint2*)pwxb, *OWB=(uint2*)powb;
    uint2 *AP=(uint2*)pap, *WP=(uint2*)pwp;

    const int GSM = 2*GSTAGE_*8;
    cudaFuncSetAttribute(attn_k, cudaFuncAttributeMaxDynamicSharedMemorySize, KSPAN_*KROW_*4);
    cudaFuncSetAttribute(dec_k,  cudaFuncAttributeMaxDynamicSharedMemorySize, DEC_SMEM_);
    cudaFuncSetAttribute(gemmp_k<EPI_NONE>,      cudaFuncAttributeMaxDynamicSharedMemorySize, GSM);
    cudaFuncSetAttribute(gemmp_k<EPI_POS>,       cudaFuncAttributeMaxDynamicSharedMemorySize, GSM);
    cudaFuncSetAttribute(gemmp_k<EPI_ADD>,       cudaFuncAttributeMaxDynamicSharedMemorySize, GSM);
    cudaFuncSetAttribute(gemmp_k<EPI_BIAS_RELU>, cudaFuncAttributeMaxDynamicSharedMemorySize, GSM);
    cudaFuncSetAttribute(gemmp_k<EPI_BIAS_ADD>,  cudaFuncAttributeMaxDynamicSharedMemorySize, GSM);
    cudaFuncSetAttribute(gemmp_k<EPI_BIAS>,      cudaFuncAttributeMaxDynamicSharedMemorySize, GSM);

    dim3 gD((D_+63)/64, M_/128), gF((FFN_+63)/64, M_/128);
    dim3 gG4((G4_+63)/64, M_/128), gP((POSE_+63)/64, M_/128);

#define PACKA(src, KP) packa_k<<<((M_*(KP))+255)/256,256>>>((src), AP, M_*(KP))
#define PACKW(src, KP, N) packw_k<<<(((KP)*(N))+255)/256,256>>>((src), WP, (KP), (N))

    PACKA(src_seq, 219); PACKW(emb_W, 219, D_);
    gemmp_k<EPI_POS><<<gD,256,GSM>>>(AP, 219, WP, X, D_, emb_b, nullptr, pos_t, src_pos);
    PACKA(X, 400);
    PACKW(Wq, 400, D_);
    gemmp_k<EPI_NONE><<<gD,256,GSM>>>(AP, 400, WP, Qb, D_, nullptr, nullptr, nullptr, nullptr);
    PACKW(Wk, 400, D_);
    gemmp_k<EPI_NONE><<<gD,256,GSM>>>(AP, 400, WP, Kb, D_, nullptr, nullptr, nullptr, nullptr);
    PACKW(Wv, 400, D_);
    gemmp_k<EPI_NONE><<<gD,256,GSM>>>(AP, 400, WP, Vb, D_, nullptr, nullptr, nullptr, nullptr);
    attn_k<<<dim3(S_/QT_, H_, B_),128,KSPAN_*KROW_*4>>>(Qb, Kb, Vb, Ob);
    PACKA(Ob, 400); PACKW(Wo, 400, D_);
    gemmp_k<EPI_ADD><<<gD,256,GSM>>>(AP, 400, WP, R1, D_, nullptr, X, nullptr, nullptr);
    ln_k<<<M_,256>>>(R1, X2, ln1g, ln1b);
    PACKA(X2, 400); PACKW(fW1, 400, FFN_);
    gemmp_k<EPI_BIAS_RELU><<<gF,256,GSM>>>(AP, 400, WP, H1, FFN_, fb1, nullptr, nullptr, nullptr);
    PACKA(H1, 512); PACKW(fW2, 512, D_);
    gemmp_k<EPI_BIAS_ADD><<<gD,256,GSM>>>(AP, 512, WP, T2, D_, fb2, X2, nullptr, nullptr);
    ln_k<<<M_,256>>>(T2, ENC, ln2g, ln2b);

    PACKA(tgt_seq, 137); PACKW(lWx, 137, G4_);
    gemmp_k<EPI_NONE><<<gG4,256,GSM>>>(AP, 137, WP, XWX, G4_, nullptr, nullptr, nullptr, nullptr);
    PACKA(ENC, 400); PACKW(outW + (size_t)HID_*POSE_, 400, POSE_);
    gemmp_k<EPI_BIAS><<<gP,256,GSM>>>(AP, 400, WP, ENCP, POSE_, outb, nullptr, nullptr, nullptr);

    pack_whb_k<<<(GATEB_*4*64*32+255)/256,256>>>(lWh, WHB);
    pack_wxb_k<<<(GATEB_*4*18*32+255)/256,256>>>(lWx, WXB);
    pack_owb_k<<<(OGRP_*64*32+255)/256,256>>>(outW, OWB);
    init_dec_k<<<(HBTOT_+255)/256,256>>>(vec_h, HB);

    dec_k<<<NBDEC_,128,DEC_SMEM_>>>(WHB, WXB, OWB, lb, XWX, ENCP, vec_c, dec0, HB, out, ep);
#undef PACKA
#undef PACKW
}